// round 1
// baseline (speedup 1.0000x reference)
#include <cuda_runtime.h>

#define D_MODEL 1024
#define SEQ     2048
#define BATCH   2
#define NHEAD   16
#define DHEAD   64
#define MTOT    (BATCH * SEQ)   // 4096 rows total

// Scratch (allocation-free rule: __device__ globals)
__device__ float g_Q [MTOT * D_MODEL];
__device__ float g_K [MTOT * D_MODEL];
__device__ float g_V [MTOT * D_MODEL];
__device__ float g_Ao[MTOT * D_MODEL];

// ---------------------------------------------------------------------------
// C[M,N] = A[M,K] @ W[N,K]^T + bias[N]
// Both A and W are K-major (row-major over K) -> TN SGEMM.
// 128x128 tile, BK=8, 256 threads, 8x8 register blocking.
// ---------------------------------------------------------------------------
__global__ void __launch_bounds__(256) gemm_tn_bias(
    const float* __restrict__ A, const float* __restrict__ W,
    const float* __restrict__ bias, float* __restrict__ C,
    int M, int N, int K)
{
    __shared__ float As[8][128];
    __shared__ float Ws[8][128];

    const int bm = blockIdx.y * 128;
    const int bn = blockIdx.x * 128;
    const int tid = threadIdx.x;
    const int tx = tid & 15;        // 0..15 -> N sub-tile
    const int ty = tid >> 4;        // 0..15 -> M sub-tile
    const int lm = tid & 127;       // loader row in tile
    const int lk = (tid >> 7) * 4;  // loader k offset (0 or 4)

    const float* Ap = A + (size_t)(bm + lm) * K + lk;
    const float* Wp = W + (size_t)(bn + lm) * K + lk;

    float acc[8][8];
    #pragma unroll
    for (int i = 0; i < 8; i++)
        #pragma unroll
        for (int j = 0; j < 8; j++) acc[i][j] = 0.f;

    for (int kt = 0; kt < K; kt += 8) {
        float4 av = *(const float4*)(Ap + kt);
        float4 wv = *(const float4*)(Wp + kt);
        __syncthreads();   // previous iteration's reads done
        As[lk + 0][lm] = av.x; As[lk + 1][lm] = av.y;
        As[lk + 2][lm] = av.z; As[lk + 3][lm] = av.w;
        Ws[lk + 0][lm] = wv.x; Ws[lk + 1][lm] = wv.y;
        Ws[lk + 2][lm] = wv.z; Ws[lk + 3][lm] = wv.w;
        __syncthreads();

        #pragma unroll
        for (int kk = 0; kk < 8; kk++) {
            float a[8], w[8];
            *(float4*)(a)     = *(const float4*)&As[kk][ty * 8];
            *(float4*)(a + 4) = *(const float4*)&As[kk][ty * 8 + 4];
            *(float4*)(w)     = *(const float4*)&Ws[kk][tx * 8];
            *(float4*)(w + 4) = *(const float4*)&Ws[kk][tx * 8 + 4];
            #pragma unroll
            for (int i = 0; i < 8; i++)
                #pragma unroll
                for (int j = 0; j < 8; j++)
                    acc[i][j] += a[i] * w[j];
        }
    }

    // epilogue: add bias, vectorized stores
    float bsv[8];
    #pragma unroll
    for (int j = 0; j < 8; j++) bsv[j] = bias[bn + tx * 8 + j];

    #pragma unroll
    for (int i = 0; i < 8; i++) {
        const int row = bm + ty * 8 + i;
        float4 o0, o1;
        o0.x = acc[i][0] + bsv[0]; o0.y = acc[i][1] + bsv[1];
        o0.z = acc[i][2] + bsv[2]; o0.w = acc[i][3] + bsv[3];
        o1.x = acc[i][4] + bsv[4]; o1.y = acc[i][5] + bsv[5];
        o1.z = acc[i][6] + bsv[6]; o1.w = acc[i][7] + bsv[7];
        float* cp = C + (size_t)row * N + bn + tx * 8;
        *(float4*)(cp)     = o0;
        *(float4*)(cp + 4) = o1;
    }
}

// ---------------------------------------------------------------------------
// Causal flash attention, fp32. One thread per query row, 128 rows per block.
// KV tiles of 32 keys staged in smem, online softmax in chunks of 8 keys
// (chunk max keeps the 64-wide accumulator rescale to 8 mul/key).
// Q/K/V laid out [B,S,D_MODEL] with head h at columns [h*64, h*64+64).
// ---------------------------------------------------------------------------
__global__ void __launch_bounds__(128) attn_kernel(
    const float* __restrict__ Q, const float* __restrict__ K,
    const float* __restrict__ V, float* __restrict__ O)
{
    const int b  = blockIdx.z;
    const int h  = blockIdx.y;
    const int qb = blockIdx.x;
    const int t  = threadIdx.x;
    const int row = qb * 128 + t;

    const size_t base = (size_t)b * SEQ * D_MODEL + (size_t)h * DHEAD;
    const float* qp = Q + base + (size_t)row * D_MODEL;

    float q[64];
    #pragma unroll
    for (int c = 0; c < 16; c++) {
        float4 v4 = *(const float4*)(qp + c * 4);
        q[c*4+0] = v4.x * 0.125f; q[c*4+1] = v4.y * 0.125f;  // 1/sqrt(64)
        q[c*4+2] = v4.z * 0.125f; q[c*4+3] = v4.w * 0.125f;
    }

    float acc[64];
    #pragma unroll
    for (int d = 0; d < 64; d++) acc[d] = 0.f;
    float m = -1e30f, l = 0.f;

    __shared__ float4 Ks[32][16];
    __shared__ float4 Vs[32][16];

    const int kend = qb * 128 + 128;  // keys [0, kend) cover this block's rows
    for (int k0 = 0; k0 < kend; k0 += 32) {
        __syncthreads();
        #pragma unroll
        for (int i = 0; i < 4; i++) {
            int idx = t + i * 128;            // 0..511
            int kr = idx >> 4, kc = idx & 15;
            size_t g = base + (size_t)(k0 + kr) * D_MODEL + kc * 4;
            Ks[kr][kc] = *(const float4*)(K + g);
            Vs[kr][kc] = *(const float4*)(V + g);
        }
        __syncthreads();

        #pragma unroll 1
        for (int j0 = 0; j0 < 32; j0 += 8) {
            // --- scores for 8 keys (fully unrolled; s[] stays in registers) ---
            float s[8];
            #pragma unroll
            for (int jj = 0; jj < 8; jj++) {
                float sj = 0.f;
                #pragma unroll
                for (int c = 0; c < 16; c++) {
                    float4 kv = Ks[j0 + jj][c];
                    sj += q[c*4+0] * kv.x; sj += q[c*4+1] * kv.y;
                    sj += q[c*4+2] * kv.z; sj += q[c*4+3] * kv.w;
                }
                // causal mask: key index k0+j0+jj must be <= row
                s[jj] = (k0 + j0 + jj <= row) ? sj : -1e30f;
            }

            float cmax = s[0];
            #pragma unroll
            for (int jj = 1; jj < 8; jj++) cmax = fmaxf(cmax, s[jj]);
            const float mnew = fmaxf(m, cmax);
            const float corr = __expf(m - mnew);

            float p[8];
            float psum = 0.f;
            #pragma unroll
            for (int jj = 0; jj < 8; jj++) {
                p[jj] = __expf(s[jj] - mnew);   // masked -> exp(-huge) = 0
                psum += p[jj];
            }
            l = l * corr + psum;
            m = mnew;

            // --- accumulate p @ V ---
            #pragma unroll
            for (int c = 0; c < 16; c++) {
                float4 v0 = Vs[j0+0][c], v1 = Vs[j0+1][c];
                float4 v2 = Vs[j0+2][c], v3 = Vs[j0+3][c];
                float4 v4 = Vs[j0+4][c], v5 = Vs[j0+5][c];
                float4 v6 = Vs[j0+6][c], v7 = Vs[j0+7][c];

                float ax = acc[c*4+0] * corr;
                float ay = acc[c*4+1] * corr;
                float az = acc[c*4+2] * corr;
                float aw = acc[c*4+3] * corr;

                ax += p[0]*v0.x; ay += p[0]*v0.y; az += p[0]*v0.z; aw += p[0]*v0.w;
                ax += p[1]*v1.x; ay += p[1]*v1.y; az += p[1]*v1.z; aw += p[1]*v1.w;
                ax += p[2]*v2.x; ay += p[2]*v2.y; az += p[2]*v2.z; aw += p[2]*v2.w;
                ax += p[3]*v3.x; ay += p[3]*v3.y; az += p[3]*v3.z; aw += p[3]*v3.w;
                ax += p[4]*v4.x; ay += p[4]*v4.y; az += p[4]*v4.z; aw += p[4]*v4.w;
                ax += p[5]*v5.x; ay += p[5]*v5.y; az += p[5]*v5.z; aw += p[5]*v5.w;
                ax += p[6]*v6.x; ay += p[6]*v6.y; az += p[6]*v6.z; aw += p[6]*v6.w;
                ax += p[7]*v7.x; ay += p[7]*v7.y; az += p[7]*v7.z; aw += p[7]*v7.w;

                acc[c*4+0] = ax; acc[c*4+1] = ay;
                acc[c*4+2] = az; acc[c*4+3] = aw;
            }
        }
    }

    const float inv = 1.f / l;
    float* op = O + base + (size_t)row * D_MODEL;
    #pragma unroll
    for (int c = 0; c < 16; c++) {
        float4 o;
        o.x = acc[c*4+0] * inv; o.y = acc[c*4+1] * inv;
        o.z = acc[c*4+2] * inv; o.w = acc[c*4+3] * inv;
        *(float4*)(op + c * 4) = o;
    }
}

// ---------------------------------------------------------------------------
extern "C" void kernel_launch(void* const* d_in, const int* in_sizes, int n_in,
                              void* d_out, int out_size)
{
    const float* x  = (const float*)d_in[0];
    const float* Wq = (const float*)d_in[1];
    const float* bq = (const float*)d_in[2];
    const float* Wk = (const float*)d_in[3];
    const float* bk = (const float*)d_in[4];
    const float* Wv = (const float*)d_in[5];
    const float* bv = (const float*)d_in[6];
    const float* Wo = (const float*)d_in[7];
    const float* bo = (const float*)d_in[8];
    float* out = (float*)d_out;

    float *Qb, *Kb, *Vb, *Ab;
    cudaGetSymbolAddress((void**)&Qb, g_Q);
    cudaGetSymbolAddress((void**)&Kb, g_K);
    cudaGetSymbolAddress((void**)&Vb, g_V);
    cudaGetSymbolAddress((void**)&Ab, g_Ao);

    dim3 ggrid(D_MODEL / 128, MTOT / 128);  // (8, 32)
    gemm_tn_bias<<<ggrid, 256>>>(x, Wq, bq, Qb, MTOT, D_MODEL, D_MODEL);
    gemm_tn_bias<<<ggrid, 256>>>(x, Wk, bk, Kb, MTOT, D_MODEL, D_MODEL);
    gemm_tn_bias<<<ggrid, 256>>>(x, Wv, bv, Vb, MTOT, D_MODEL, D_MODEL);

    dim3 agrid(SEQ / 128, NHEAD, BATCH);    // (16, 16, 2)
    attn_kernel<<<agrid, 128>>>(Qb, Kb, Vb, Ab);

    gemm_tn_bias<<<ggrid, 256>>>(Ab, Wo, bo, out, MTOT, D_MODEL, D_MODEL);
}

// round 3
// speedup vs baseline: 1.5013x; 1.5013x over previous
#include <cuda_runtime.h>
#include <cuda_bf16.h>
#include <cstdint>

#define D_MODEL 1024
#define SEQ     2048
#define BATCH   2
#define NHEAD   16
#define DHEAD   64
#define MTOT    (BATCH * SEQ)   // 4096

// ---------------- scratch (__device__ globals; no allocation allowed) ------
__device__ float g_Q [MTOT * D_MODEL];
__device__ float g_K [MTOT * D_MODEL];
__device__ float g_V [MTOT * D_MODEL];
__device__ float g_Ao[MTOT * D_MODEL];

__device__ __nv_bfloat16 g_xhi [MTOT * D_MODEL];
__device__ __nv_bfloat16 g_xlo [MTOT * D_MODEL];
__device__ __nv_bfloat16 g_Whi [4][D_MODEL * D_MODEL];
__device__ __nv_bfloat16 g_Wlo [4][D_MODEL * D_MODEL];
__device__ __nv_bfloat16 g_aohi[MTOT * D_MODEL];
__device__ __nv_bfloat16 g_aolo[MTOT * D_MODEL];

// ---------------------------------------------------------------------------
__device__ __forceinline__ uint32_t smem_u32(const void* p) {
    uint32_t a;
    asm("{ .reg .u64 t; cvta.to.shared.u64 t, %1; cvt.u32.u64 %0, t; }"
        : "=r"(a) : "l"(p));
    return a;
}

#define MMA_BF16(acc, a, b) \
    asm volatile("mma.sync.aligned.m16n8k16.row.col.f32.bf16.bf16.f32 " \
        "{%0,%1,%2,%3}, {%4,%5,%6,%7}, {%8,%9}, {%0,%1,%2,%3};" \
        : "+f"((acc)[0]), "+f"((acc)[1]), "+f"((acc)[2]), "+f"((acc)[3]) \
        : "r"((a)[0]), "r"((a)[1]), "r"((a)[2]), "r"((a)[3]), \
          "r"((b)[0]), "r"((b)[1]))

#define LDMATRIX_X4(r, addr) \
    asm volatile("ldmatrix.sync.aligned.m8n8.x4.shared.b16 {%0,%1,%2,%3}, [%4];" \
        : "=r"((r)[0]), "=r"((r)[1]), "=r"((r)[2]), "=r"((r)[3]) : "r"(addr))

#define CP_ASYNC16(d, g) \
    asm volatile("cp.async.cg.shared.global [%0], [%1], 16;" :: "r"(d), "l"(g))
#define CP_COMMIT()  asm volatile("cp.async.commit_group;" ::: "memory")
#define CP_WAIT(n)   asm volatile("cp.async.wait_group %0;" :: "n"(n) : "memory")

// ---------------------------------------------------------------------------
// fp32 -> (hi, lo) bf16 split.
// ---------------------------------------------------------------------------
__global__ void __launch_bounds__(256) split_bf16(
    const float* __restrict__ in, __nv_bfloat16* __restrict__ hi,
    __nv_bfloat16* __restrict__ lo, int n4)
{
    int i = blockIdx.x * 256 + threadIdx.x;
    if (i >= n4) return;
    float4 v = ((const float4*)in)[i];
    __nv_bfloat16 hx = __float2bfloat16(v.x);
    __nv_bfloat16 hy = __float2bfloat16(v.y);
    __nv_bfloat16 hz = __float2bfloat16(v.z);
    __nv_bfloat16 hw = __float2bfloat16(v.w);
    __nv_bfloat16 lx = __float2bfloat16(v.x - __bfloat162float(hx));
    __nv_bfloat16 ly = __float2bfloat16(v.y - __bfloat162float(hy));
    __nv_bfloat16 lz = __float2bfloat16(v.z - __bfloat162float(hz));
    __nv_bfloat16 lw = __float2bfloat16(v.w - __bfloat162float(hw));
    union { __nv_bfloat162 b[2]; uint2 u; } H, L;
    H.b[0] = __nv_bfloat162(hx, hy); H.b[1] = __nv_bfloat162(hz, hw);
    L.b[0] = __nv_bfloat162(lx, ly); L.b[1] = __nv_bfloat162(lz, lw);
    *(uint2*)(hi + 4 * (size_t)i) = H.u;
    *(uint2*)(lo + 4 * (size_t)i) = L.u;
}

// ---------------------------------------------------------------------------
// C[M,N] = A[M,K] @ B[N,K]^T + bias, error-compensated split-bf16 via
// mma.sync.m16n8k16 (HMMA path; tcgen05 not available on this PTX target).
//   C += Ahi*Bhi^T + Ahi*Blo^T + Alo*Bhi^T
// 128x128 CTA tile, BK=32, 256 threads, warp grid 2(m) x 4(n), warp tile
// 64x32. Double-buffered cp.async, 80B-padded smem rows (conflict-free).
// ---------------------------------------------------------------------------
#define TROW   80                 // padded row stride bytes (64B data + 16B pad)
#define TILE_B (128 * TROW)       // 10240 B per tile
#define STAGE_B (4 * TILE_B)      // Ahi,Alo,Bhi,Blo
#define GEMM_SMEM (2 * STAGE_B)   // 81920 B

__global__ void __launch_bounds__(256, 1) gemm_bf16_mma(
    const __nv_bfloat16* __restrict__ Ahi, const __nv_bfloat16* __restrict__ Alo,
    const __nv_bfloat16* __restrict__ Bhi, const __nv_bfloat16* __restrict__ Blo,
    const float* __restrict__ bias, float* __restrict__ C)
{
    extern __shared__ char smem[];
    constexpr int K = D_MODEL;
    const int tid  = threadIdx.x;
    const int lane = tid & 31;
    const int wid  = tid >> 5;
    const int bm = blockIdx.y * 128;
    const int bn = blockIdx.x * 128;
    const int m0w = (wid & 1) * 64;     // warp m offset in tile
    const int n0w = (wid >> 1) * 32;    // warp n offset in tile
    const int gid = lane >> 2;          // 0..7
    const int tg  = lane & 3;           // 0..3

    const uint32_t sb = smem_u32(smem);

    const __nv_bfloat16* src[4] = {
        Ahi + (size_t)bm * K, Alo + (size_t)bm * K,
        Bhi + (size_t)bn * K, Blo + (size_t)bn * K };

    // copy one BK=32 chunk (4 tiles of 128 rows x 32 bf16) into stage buf
    auto copy_chunk = [&](int c) {
        const int buf = c & 1;
        const int kc  = c * 32;
        #pragma unroll
        for (int t = 0; t < 4; t++) {
            #pragma unroll
            for (int i = 0; i < 2; i++) {
                int v = tid + i * 256;            // 0..511
                int row = v >> 2, seg = v & 3;    // 4 x 16B per row
                const __nv_bfloat16* g = src[t] + (size_t)row * K + kc + seg * 8;
                uint32_t d = sb + buf * STAGE_B + t * TILE_B + row * TROW + seg * 16;
                CP_ASYNC16(d, g);
            }
        }
    };

    float acc[4][4][4];
    #pragma unroll
    for (int mt = 0; mt < 4; mt++)
        #pragma unroll
        for (int nt = 0; nt < 4; nt++)
            #pragma unroll
            for (int j = 0; j < 4; j++) acc[mt][nt][j] = 0.f;

    const int NCH = K / 32;   // 32 chunks
    copy_chunk(0);
    CP_COMMIT();

    for (int c = 0; c < NCH; c++) {
        if (c + 1 < NCH) {
            copy_chunk(c + 1);
            CP_COMMIT();
            CP_WAIT(1);
        } else {
            CP_WAIT(0);
        }
        __syncthreads();

        const uint32_t stage = sb + (c & 1) * STAGE_B;

        #pragma unroll
        for (int ks = 0; ks < 2; ks++) {   // two k16 steps per chunk
            uint32_t ahi[4][4], alo[4][4];
            const uint32_t aoff = (uint32_t)(m0w + (lane & 15)) * TROW
                                  + ks * 32 + (lane >> 4) * 16;
            #pragma unroll
            for (int mt = 0; mt < 4; mt++) {
                uint32_t ad = stage + aoff + mt * (16 * TROW);
                LDMATRIX_X4(ahi[mt], ad);
                LDMATRIX_X4(alo[mt], ad + TILE_B);
            }

            uint32_t bhi[4][2], blo[4][2];
            const uint32_t boff = (uint32_t)(n0w + gid) * TROW + ks * 32 + tg * 4;
            #pragma unroll
            for (int nt = 0; nt < 4; nt++) {
                uint32_t bd = stage + 2 * TILE_B + boff + nt * (8 * TROW);
                asm volatile("ld.shared.b32 %0, [%1];" : "=r"(bhi[nt][0]) : "r"(bd));
                asm volatile("ld.shared.b32 %0, [%1];" : "=r"(bhi[nt][1]) : "r"(bd + 16));
                asm volatile("ld.shared.b32 %0, [%1];" : "=r"(blo[nt][0]) : "r"(bd + TILE_B));
                asm volatile("ld.shared.b32 %0, [%1];" : "=r"(blo[nt][1]) : "r"(bd + TILE_B + 16));
            }

            // term-outer ordering: 16 independent accumulation chains each
            #pragma unroll
            for (int mt = 0; mt < 4; mt++)
                #pragma unroll
                for (int nt = 0; nt < 4; nt++)
                    MMA_BF16(acc[mt][nt], ahi[mt], bhi[nt]);
            #pragma unroll
            for (int mt = 0; mt < 4; mt++)
                #pragma unroll
                for (int nt = 0; nt < 4; nt++)
                    MMA_BF16(acc[mt][nt], ahi[mt], blo[nt]);
            #pragma unroll
            for (int mt = 0; mt < 4; mt++)
                #pragma unroll
                for (int nt = 0; nt < 4; nt++)
                    MMA_BF16(acc[mt][nt], alo[mt], bhi[nt]);
        }
        __syncthreads();
    }

    // epilogue: bias + store
    #pragma unroll
    for (int nt = 0; nt < 4; nt++) {
        const int col = bn + n0w + nt * 8 + 2 * tg;
        const float b0 = bias[col], b1 = bias[col + 1];
        #pragma unroll
        for (int mt = 0; mt < 4; mt++) {
            const int r0 = bm + m0w + mt * 16 + gid;
            float2 v0, v1;
            v0.x = acc[mt][nt][0] + b0; v0.y = acc[mt][nt][1] + b1;
            v1.x = acc[mt][nt][2] + b0; v1.y = acc[mt][nt][3] + b1;
            *(float2*)(C + (size_t)r0 * D_MODEL + col)       = v0;
            *(float2*)(C + (size_t)(r0 + 8) * D_MODEL + col) = v1;
        }
    }
}

// ---------------------------------------------------------------------------
// Causal flash attention, fp32 (unchanged from R1).
// ---------------------------------------------------------------------------
__global__ void __launch_bounds__(128) attn_kernel(
    const float* __restrict__ Q, const float* __restrict__ K,
    const float* __restrict__ V, float* __restrict__ O)
{
    const int b  = blockIdx.z;
    const int h  = blockIdx.y;
    const int qb = blockIdx.x;
    const int t  = threadIdx.x;
    const int row = qb * 128 + t;

    const size_t base = (size_t)b * SEQ * D_MODEL + (size_t)h * DHEAD;
    const float* qp = Q + base + (size_t)row * D_MODEL;

    float q[64];
    #pragma unroll
    for (int c = 0; c < 16; c++) {
        float4 v4 = *(const float4*)(qp + c * 4);
        q[c*4+0] = v4.x * 0.125f; q[c*4+1] = v4.y * 0.125f;
        q[c*4+2] = v4.z * 0.125f; q[c*4+3] = v4.w * 0.125f;
    }

    float acc[64];
    #pragma unroll
    for (int d = 0; d < 64; d++) acc[d] = 0.f;
    float m = -1e30f, l = 0.f;

    __shared__ float4 Ks[32][16];
    __shared__ float4 Vs[32][16];

    const int kend = qb * 128 + 128;
    for (int k0 = 0; k0 < kend; k0 += 32) {
        __syncthreads();
        #pragma unroll
        for (int i = 0; i < 4; i++) {
            int idx = t + i * 128;
            int kr = idx >> 4, kc = idx & 15;
            size_t g = base + (size_t)(k0 + kr) * D_MODEL + kc * 4;
            Ks[kr][kc] = *(const float4*)(K + g);
            Vs[kr][kc] = *(const float4*)(V + g);
        }
        __syncthreads();

        #pragma unroll 1
        for (int j0 = 0; j0 < 32; j0 += 8) {
            float s[8];
            #pragma unroll
            for (int jj = 0; jj < 8; jj++) {
                float sj = 0.f;
                #pragma unroll
                for (int c = 0; c < 16; c++) {
                    float4 kv = Ks[j0 + jj][c];
                    sj += q[c*4+0] * kv.x; sj += q[c*4+1] * kv.y;
                    sj += q[c*4+2] * kv.z; sj += q[c*4+3] * kv.w;
                }
                s[jj] = (k0 + j0 + jj <= row) ? sj : -1e30f;
            }

            float cmax = s[0];
            #pragma unroll
            for (int jj = 1; jj < 8; jj++) cmax = fmaxf(cmax, s[jj]);
            const float mnew = fmaxf(m, cmax);
            const float corr = __expf(m - mnew);

            float p[8];
            float psum = 0.f;
            #pragma unroll
            for (int jj = 0; jj < 8; jj++) {
                p[jj] = __expf(s[jj] - mnew);
                psum += p[jj];
            }
            l = l * corr + psum;
            m = mnew;

            #pragma unroll
            for (int c = 0; c < 16; c++) {
                float4 v0 = Vs[j0+0][c], v1 = Vs[j0+1][c];
                float4 v2 = Vs[j0+2][c], v3 = Vs[j0+3][c];
                float4 v4 = Vs[j0+4][c], v5 = Vs[j0+5][c];
                float4 v6 = Vs[j0+6][c], v7 = Vs[j0+7][c];

                float ax = acc[c*4+0] * corr;
                float ay = acc[c*4+1] * corr;
                float az = acc[c*4+2] * corr;
                float aw = acc[c*4+3] * corr;

                ax += p[0]*v0.x; ay += p[0]*v0.y; az += p[0]*v0.z; aw += p[0]*v0.w;
                ax += p[1]*v1.x; ay += p[1]*v1.y; az += p[1]*v1.z; aw += p[1]*v1.w;
                ax += p[2]*v2.x; ay += p[2]*v2.y; az += p[2]*v2.z; aw += p[2]*v2.w;
                ax += p[3]*v3.x; ay += p[3]*v3.y; az += p[3]*v3.z; aw += p[3]*v3.w;
                ax += p[4]*v4.x; ay += p[4]*v4.y; az += p[4]*v4.z; aw += p[4]*v4.w;
                ax += p[5]*v5.x; ay += p[5]*v5.y; az += p[5]*v5.z; aw += p[5]*v5.w;
                ax += p[6]*v6.x; ay += p[6]*v6.y; az += p[6]*v6.z; aw += p[6]*v6.w;
                ax += p[7]*v7.x; ay += p[7]*v7.y; az += p[7]*v7.z; aw += p[7]*v7.w;

                acc[c*4+0] = ax; acc[c*4+1] = ay;
                acc[c*4+2] = az; acc[c*4+3] = aw;
            }
        }
    }

    const float inv = 1.f / l;
    float* op = O + base + (size_t)row * D_MODEL;
    #pragma unroll
    for (int c = 0; c < 16; c++) {
        float4 o;
        o.x = acc[c*4+0] * inv; o.y = acc[c*4+1] * inv;
        o.z = acc[c*4+2] * inv; o.w = acc[c*4+3] * inv;
        *(float4*)(op + c * 4) = o;
    }
}

// ---------------------------------------------------------------------------
extern "C" void kernel_launch(void* const* d_in, const int* in_sizes, int n_in,
                              void* d_out, int out_size)
{
    const float* x  = (const float*)d_in[0];
    const float* Wq = (const float*)d_in[1];
    const float* bq = (const float*)d_in[2];
    const float* Wk = (const float*)d_in[3];
    const float* bk = (const float*)d_in[4];
    const float* Wv = (const float*)d_in[5];
    const float* bv = (const float*)d_in[6];
    const float* Wo = (const float*)d_in[7];
    const float* bo = (const float*)d_in[8];
    float* out = (float*)d_out;

    float *Qb, *Kb, *Vb, *Ab;
    cudaGetSymbolAddress((void**)&Qb, g_Q);
    cudaGetSymbolAddress((void**)&Kb, g_K);
    cudaGetSymbolAddress((void**)&Vb, g_V);
    cudaGetSymbolAddress((void**)&Ab, g_Ao);

    __nv_bfloat16 *xhi, *xlo, *Whi, *Wlo, *aohi, *aolo;
    cudaGetSymbolAddress((void**)&xhi, g_xhi);
    cudaGetSymbolAddress((void**)&xlo, g_xlo);
    cudaGetSymbolAddress((void**)&Whi, g_Whi);
    cudaGetSymbolAddress((void**)&Wlo, g_Wlo);
    cudaGetSymbolAddress((void**)&aohi, g_aohi);
    cudaGetSymbolAddress((void**)&aolo, g_aolo);

    cudaFuncSetAttribute(gemm_bf16_mma,
                         cudaFuncAttributeMaxDynamicSharedMemorySize, GEMM_SMEM);

    const int NX4 = MTOT * D_MODEL / 4;
    const int NW4 = D_MODEL * D_MODEL / 4;
    const int WSZ = D_MODEL * D_MODEL;

    split_bf16<<<(NX4 + 255) / 256, 256>>>(x, xhi, xlo, NX4);
    split_bf16<<<(NW4 + 255) / 256, 256>>>(Wq, Whi + 0 * WSZ, Wlo + 0 * WSZ, NW4);
    split_bf16<<<(NW4 + 255) / 256, 256>>>(Wk, Whi + 1 * WSZ, Wlo + 1 * WSZ, NW4);
    split_bf16<<<(NW4 + 255) / 256, 256>>>(Wv, Whi + 2 * WSZ, Wlo + 2 * WSZ, NW4);
    split_bf16<<<(NW4 + 255) / 256, 256>>>(Wo, Whi + 3 * WSZ, Wlo + 3 * WSZ, NW4);

    dim3 ggrid(D_MODEL / 128, MTOT / 128);   // (8, 32)
    gemm_bf16_mma<<<ggrid, 256, GEMM_SMEM>>>(xhi, xlo, Whi + 0 * WSZ, Wlo + 0 * WSZ, bq, Qb);
    gemm_bf16_mma<<<ggrid, 256, GEMM_SMEM>>>(xhi, xlo, Whi + 1 * WSZ, Wlo + 1 * WSZ, bk, Kb);
    gemm_bf16_mma<<<ggrid, 256, GEMM_SMEM>>>(xhi, xlo, Whi + 2 * WSZ, Wlo + 2 * WSZ, bv, Vb);

    dim3 agrid(SEQ / 128, NHEAD, BATCH);     // (16, 16, 2)
    attn_kernel<<<agrid, 128>>>(Qb, Kb, Vb, Ab);

    split_bf16<<<(NX4 + 255) / 256, 256>>>(Ab, aohi, aolo, NX4);
    gemm_bf16_mma<<<ggrid, 256, GEMM_SMEM>>>(aohi, aolo, Whi + 3 * WSZ, Wlo + 3 * WSZ, bo, out);
}

// round 5
// speedup vs baseline: 1.6477x; 1.0975x over previous
#include <cuda_runtime.h>
#include <cuda_bf16.h>
#include <cstdint>

#define D_MODEL 1024
#define SEQ     2048
#define BATCH   2
#define NHEAD   16
#define DHEAD   64
#define MTOT    (BATCH * SEQ)   // 4096

// ---------------- scratch (__device__ globals) ------------------------------
__device__ __nv_bfloat16 g_xhi [MTOT * D_MODEL];
__device__ __nv_bfloat16 g_xlo [MTOT * D_MODEL];
__device__ __nv_bfloat16 g_Whi [4][D_MODEL * D_MODEL];
__device__ __nv_bfloat16 g_Wlo [4][D_MODEL * D_MODEL];
__device__ __nv_bfloat16 g_qhi [MTOT * D_MODEL];
__device__ __nv_bfloat16 g_qlo [MTOT * D_MODEL];
__device__ __nv_bfloat16 g_khi [MTOT * D_MODEL];
__device__ __nv_bfloat16 g_klo [MTOT * D_MODEL];
__device__ __nv_bfloat16 g_vhi [MTOT * D_MODEL];
__device__ __nv_bfloat16 g_vlo [MTOT * D_MODEL];
__device__ __nv_bfloat16 g_aohi[MTOT * D_MODEL];
__device__ __nv_bfloat16 g_aolo[MTOT * D_MODEL];

// ---------------------------------------------------------------------------
__device__ __forceinline__ uint32_t smem_u32(const void* p) {
    uint32_t a;
    asm("{ .reg .u64 t; cvta.to.shared.u64 t, %1; cvt.u32.u64 %0, t; }"
        : "=r"(a) : "l"(p));
    return a;
}

#define MMA_BF16(acc, a, b) \
    asm volatile("mma.sync.aligned.m16n8k16.row.col.f32.bf16.bf16.f32 " \
        "{%0,%1,%2,%3}, {%4,%5,%6,%7}, {%8,%9}, {%0,%1,%2,%3};" \
        : "+f"((acc)[0]), "+f"((acc)[1]), "+f"((acc)[2]), "+f"((acc)[3]) \
        : "r"((a)[0]), "r"((a)[1]), "r"((a)[2]), "r"((a)[3]), \
          "r"((b)[0]), "r"((b)[1]))

#define LDMATRIX_X4(r, addr) \
    asm volatile("ldmatrix.sync.aligned.m8n8.x4.shared.b16 {%0,%1,%2,%3}, [%4];" \
        : "=r"((r)[0]), "=r"((r)[1]), "=r"((r)[2]), "=r"((r)[3]) : "r"(addr))

#define LDS32(r, addr) \
    asm volatile("ld.shared.b32 %0, [%1];" : "=r"(r) : "r"(addr))

#define CP_ASYNC16(d, g) \
    asm volatile("cp.async.cg.shared.global [%0], [%1], 16;" :: "r"(d), "l"(g))
#define CP_COMMIT()  asm volatile("cp.async.commit_group;" ::: "memory")
#define CP_WAIT(n)   asm volatile("cp.async.wait_group %0;" :: "n"(n) : "memory")

__device__ __forceinline__ uint32_t pack_bf16(float lo, float hi) {
    __nv_bfloat162 t = __floats2bfloat162_rn(lo, hi);  // x=lo, y=hi
    return *(uint32_t*)&t;
}

// fast exp2 for x <= 0 (fma/alu pipe only, rel err ~2e-6)
__device__ __forceinline__ float exp2f_fast(float x) {
    x = fmaxf(x, -100.f);
    float r = x + 12582912.f;             // round-to-nearest int (magic)
    int  ir = __float_as_int(r);
    float n = r - 12582912.f;
    float f = x - n;                      // [-0.5, 0.5]
    float p = 1.33335581e-3f;
    p = fmaf(p, f, 9.61817249e-3f);
    p = fmaf(p, f, 5.55041086e-2f);
    p = fmaf(p, f, 2.40226507e-1f);
    p = fmaf(p, f, 6.93147182e-1f);
    p = fmaf(p, f, 1.0f);
    return __int_as_float(__float_as_int(p) + ((ir - 0x4B400000) << 23));
}

// ---------------------------------------------------------------------------
// fp32 -> (hi, lo) bf16 split (inputs x and weights only).
// ---------------------------------------------------------------------------
__global__ void __launch_bounds__(256) split_bf16(
    const float* __restrict__ in, __nv_bfloat16* __restrict__ hi,
    __nv_bfloat16* __restrict__ lo, int n4)
{
    int i = blockIdx.x * 256 + threadIdx.x;
    if (i >= n4) return;
    float4 v = ((const float4*)in)[i];
    __nv_bfloat16 hx = __float2bfloat16(v.x);
    __nv_bfloat16 hy = __float2bfloat16(v.y);
    __nv_bfloat16 hz = __float2bfloat16(v.z);
    __nv_bfloat16 hw = __float2bfloat16(v.w);
    __nv_bfloat16 lx = __float2bfloat16(v.x - __bfloat162float(hx));
    __nv_bfloat16 ly = __float2bfloat16(v.y - __bfloat162float(hy));
    __nv_bfloat16 lz = __float2bfloat16(v.z - __bfloat162float(hz));
    __nv_bfloat16 lw = __float2bfloat16(v.w - __bfloat162float(hw));
    union { __nv_bfloat162 b[2]; uint2 u; } H, L;
    H.b[0] = __nv_bfloat162(hx, hy); H.b[1] = __nv_bfloat162(hz, hw);
    L.b[0] = __nv_bfloat162(lx, ly); L.b[1] = __nv_bfloat162(lz, lw);
    *(uint2*)(hi + 4 * (size_t)i) = H.u;
    *(uint2*)(lo + 4 * (size_t)i) = L.u;
}

// ---------------------------------------------------------------------------
// Split-bf16 GEMM (validated R3). Epilogue: if Chi != null, writes
// (acc+bias)*scale split to bf16 hi/lo; else fp32 acc+bias to Cf.
// ---------------------------------------------------------------------------
#define TROW   80
#define TILE_B (128 * TROW)
#define STAGE_B (4 * TILE_B)
#define GEMM_SMEM (2 * STAGE_B)   // 81920 B

__global__ void __launch_bounds__(256, 1) gemm_bf16_mma(
    const __nv_bfloat16* __restrict__ Ahi, const __nv_bfloat16* __restrict__ Alo,
    const __nv_bfloat16* __restrict__ Bhi, const __nv_bfloat16* __restrict__ Blo,
    const float* __restrict__ bias, float* __restrict__ Cf,
    __nv_bfloat16* __restrict__ Chi, __nv_bfloat16* __restrict__ Clo,
    float scale)
{
    extern __shared__ char smem[];
    constexpr int K = D_MODEL;
    const int tid  = threadIdx.x;
    const int lane = tid & 31;
    const int wid  = tid >> 5;
    const int bm = blockIdx.y * 128;
    const int bn = blockIdx.x * 128;
    const int m0w = (wid & 1) * 64;
    const int n0w = (wid >> 1) * 32;
    const int gid = lane >> 2;
    const int tg  = lane & 3;

    const uint32_t sb = smem_u32(smem);

    const __nv_bfloat16* src[4] = {
        Ahi + (size_t)bm * K, Alo + (size_t)bm * K,
        Bhi + (size_t)bn * K, Blo + (size_t)bn * K };

    auto copy_chunk = [&](int c) {
        const int buf = c & 1;
        const int kc  = c * 32;
        #pragma unroll
        for (int t = 0; t < 4; t++) {
            #pragma unroll
            for (int i = 0; i < 2; i++) {
                int v = tid + i * 256;
                int row = v >> 2, seg = v & 3;
                const __nv_bfloat16* g = src[t] + (size_t)row * K + kc + seg * 8;
                uint32_t d = sb + buf * STAGE_B + t * TILE_B + row * TROW + seg * 16;
                CP_ASYNC16(d, g);
            }
        }
    };

    float acc[4][4][4];
    #pragma unroll
    for (int mt = 0; mt < 4; mt++)
        #pragma unroll
        for (int nt = 0; nt < 4; nt++)
            #pragma unroll
            for (int j = 0; j < 4; j++) acc[mt][nt][j] = 0.f;

    const int NCH = K / 32;
    copy_chunk(0);
    CP_COMMIT();

    for (int c = 0; c < NCH; c++) {
        if (c + 1 < NCH) { copy_chunk(c + 1); CP_COMMIT(); CP_WAIT(1); }
        else             { CP_WAIT(0); }
        __syncthreads();

        const uint32_t stage = sb + (c & 1) * STAGE_B;

        #pragma unroll
        for (int ks = 0; ks < 2; ks++) {
            uint32_t ahi[4][4], alo[4][4];
            const uint32_t aoff = (uint32_t)(m0w + (lane & 15)) * TROW
                                  + ks * 32 + (lane >> 4) * 16;
            #pragma unroll
            for (int mt = 0; mt < 4; mt++) {
                uint32_t ad = stage + aoff + mt * (16 * TROW);
                LDMATRIX_X4(ahi[mt], ad);
                LDMATRIX_X4(alo[mt], ad + TILE_B);
            }

            uint32_t bhi[4][2], blo[4][2];
            const uint32_t boff = (uint32_t)(n0w + gid) * TROW + ks * 32 + tg * 4;
            #pragma unroll
            for (int nt = 0; nt < 4; nt++) {
                uint32_t bd = stage + 2 * TILE_B + boff + nt * (8 * TROW);
                LDS32(bhi[nt][0], bd);
                LDS32(bhi[nt][1], bd + 16);
                LDS32(blo[nt][0], bd + TILE_B);
                LDS32(blo[nt][1], bd + TILE_B + 16);
            }

            #pragma unroll
            for (int mt = 0; mt < 4; mt++)
                #pragma unroll
                for (int nt = 0; nt < 4; nt++)
                    MMA_BF16(acc[mt][nt], ahi[mt], bhi[nt]);
            #pragma unroll
            for (int mt = 0; mt < 4; mt++)
                #pragma unroll
                for (int nt = 0; nt < 4; nt++)
                    MMA_BF16(acc[mt][nt], ahi[mt], blo[nt]);
            #pragma unroll
            for (int mt = 0; mt < 4; mt++)
                #pragma unroll
                for (int nt = 0; nt < 4; nt++)
                    MMA_BF16(acc[mt][nt], alo[mt], bhi[nt]);
        }
        __syncthreads();
    }

    if (Chi) {
        #pragma unroll
        for (int nt = 0; nt < 4; nt++) {
            const int col = bn + n0w + nt * 8 + 2 * tg;
            const float b0 = bias[col], b1 = bias[col + 1];
            #pragma unroll
            for (int mt = 0; mt < 4; mt++) {
                const int r0 = bm + m0w + mt * 16 + gid;
                #pragma unroll
                for (int s = 0; s < 2; s++) {
                    float v0 = (acc[mt][nt][2*s+0] + b0) * scale;
                    float v1 = (acc[mt][nt][2*s+1] + b1) * scale;
                    __nv_bfloat16 h0 = __float2bfloat16(v0);
                    __nv_bfloat16 h1 = __float2bfloat16(v1);
                    float l0 = v0 - __bfloat162float(h0);
                    float l1 = v1 - __bfloat162float(h1);
                    size_t off = (size_t)(r0 + 8 * s) * D_MODEL + col;
                    __nv_bfloat162 H(h0, h1);
                    *(uint32_t*)(Chi + off) = *(uint32_t*)&H;
                    *(uint32_t*)(Clo + off) = pack_bf16(l0, l1);
                }
            }
        }
    } else {
        #pragma unroll
        for (int nt = 0; nt < 4; nt++) {
            const int col = bn + n0w + nt * 8 + 2 * tg;
            const float b0 = bias[col], b1 = bias[col + 1];
            #pragma unroll
            for (int mt = 0; mt < 4; mt++) {
                const int r0 = bm + m0w + mt * 16 + gid;
                float2 v0, v1;
                v0.x = acc[mt][nt][0] + b0; v0.y = acc[mt][nt][1] + b1;
                v1.x = acc[mt][nt][2] + b0; v1.y = acc[mt][nt][3] + b1;
                *(float2*)(Cf + (size_t)r0 * D_MODEL + col)       = v0;
                *(float2*)(Cf + (size_t)(r0 + 8) * D_MODEL + col) = v1;
            }
        }
    }
}

// ---------------------------------------------------------------------------
// MMA flash attention. CTA = 128 query rows of one (b,h); 4 warps x 32 rows.
// Key tiles of 64. Split-bf16 QK^T and PV (3 terms each). exp2 polynomial
// softmax (scores pre-scaled by 0.125*log2e in Q projection epilogue).
// V transposed into smem so all B-fragments are plain 32-bit LDS.
// ---------------------------------------------------------------------------
#define ATROW 144
#define SM_QHI 0
#define SM_QLO (128 * ATROW)
#define SM_KHI (2 * 128 * ATROW)
#define SM_KLO (SM_KHI + 64 * ATROW)
#define SM_VHI (SM_KLO + 64 * ATROW)
#define SM_VLO (SM_VHI + 64 * ATROW)
#define ATTN_SMEM (SM_VLO + 64 * ATROW)  // 73728

__global__ void __launch_bounds__(128, 2) attn_mma(
    const __nv_bfloat16* __restrict__ Qhi, const __nv_bfloat16* __restrict__ Qlo,
    const __nv_bfloat16* __restrict__ Khi, const __nv_bfloat16* __restrict__ Klo,
    const __nv_bfloat16* __restrict__ Vhi, const __nv_bfloat16* __restrict__ Vlo,
    __nv_bfloat16* __restrict__ Ohi, __nv_bfloat16* __restrict__ Olo)
{
    extern __shared__ char smem[];
    const uint32_t sb = smem_u32(smem);
    const int b  = blockIdx.z;
    const int h  = blockIdx.y;
    const int qb = gridDim.x - 1 - blockIdx.x;   // heavy CTAs first
    const int tid  = threadIdx.x;
    const int lane = tid & 31;
    const int wid  = tid >> 5;
    const int gid  = lane >> 2;
    const int tg   = lane & 3;
    const int q0   = qb * 128;
    const int m0w  = wid * 32;                   // warp rows q0+m0w..+31
    const size_t rowbase = (size_t)b * SEQ;
    const int colh = h * DHEAD;

    // stage Q (hi+lo) via cp.async
    #pragma unroll
    for (int i = 0; i < 8; i++) {
        int v = tid + i * 128;            // 0..1023
        int r = v >> 3, seg = v & 7;
        size_t g = (rowbase + q0 + r) * D_MODEL + colh + seg * 8;
        CP_ASYNC16(sb + SM_QHI + r * ATROW + seg * 16, Qhi + g);
        CP_ASYNC16(sb + SM_QLO + r * ATROW + seg * 16, Qlo + g);
    }
    CP_COMMIT();

    float oacc[2][8][4];
    #pragma unroll
    for (int mf = 0; mf < 2; mf++)
        #pragma unroll
        for (int nf = 0; nf < 8; nf++)
            #pragma unroll
            for (int e = 0; e < 4; e++) oacc[mf][nf][e] = 0.f;
    float mrow[2][2] = {{-1e30f, -1e30f}, {-1e30f, -1e30f}};
    float lrow[2][2] = {{0.f, 0.f}, {0.f, 0.f}};

    for (int kt0 = 0; kt0 < q0 + 128; kt0 += 64) {
        __syncthreads();   // prior tile compute done before overwrite
        // stage K (cp.async) + transposed V (SIMT)
        #pragma unroll
        for (int i = 0; i < 4; i++) {
            int v = tid + i * 128;        // 0..511
            int r = v >> 3, seg = v & 7;
            size_t g = (rowbase + kt0 + r) * D_MODEL + colh + seg * 8;
            CP_ASYNC16(sb + SM_KHI + r * ATROW + seg * 16, Khi + g);
            CP_ASYNC16(sb + SM_KLO + r * ATROW + seg * 16, Klo + g);
        }
        CP_COMMIT();
        #pragma unroll
        for (int i = 0; i < 16; i++) {
            int v = tid + i * 128;        // 0..2047
            int k = v >> 5, dp = v & 31;  // key, dh-pair
            size_t g = (rowbase + kt0 + k) * D_MODEL + colh + dp * 2;
            uint32_t uh = *(const uint32_t*)(Vhi + g);
            uint32_t ul = *(const uint32_t*)(Vlo + g);
            uint32_t a0 = sb + SM_VHI + (2 * dp) * ATROW + k * 2;
            uint32_t a1 = sb + SM_VLO + (2 * dp) * ATROW + k * 2;
            asm volatile("st.shared.b16 [%0], %1;" :: "r"(a0), "h"((unsigned short)(uh & 0xFFFF)));
            asm volatile("st.shared.b16 [%0], %1;" :: "r"(a0 + ATROW), "h"((unsigned short)(uh >> 16)));
            asm volatile("st.shared.b16 [%0], %1;" :: "r"(a1), "h"((unsigned short)(ul & 0xFFFF)));
            asm volatile("st.shared.b16 [%0], %1;" :: "r"(a1 + ATROW), "h"((unsigned short)(ul >> 16)));
        }
        CP_WAIT(0);
        __syncthreads();

        // per-warp early-out: tile entirely above this warp's diagonal
        if (kt0 > q0 + m0w + 31) continue;

        // ---- S = Q K^T (3 terms) ----
        float sacc[2][8][4];
        #pragma unroll
        for (int mf = 0; mf < 2; mf++)
            #pragma unroll
            for (int nf = 0; nf < 8; nf++)
                #pragma unroll
                for (int e = 0; e < 4; e++) sacc[mf][nf][e] = 0.f;

        #pragma unroll
        for (int ks = 0; ks < 4; ks++) {
            uint32_t ahi[2][4], alo[2][4];
            const uint32_t aoff = (uint32_t)(m0w + (lane & 15)) * ATROW
                                  + ks * 32 + (lane >> 4) * 16;
            #pragma unroll
            for (int mf = 0; mf < 2; mf++) {
                uint32_t ad = sb + SM_QHI + aoff + mf * (16 * ATROW);
                LDMATRIX_X4(ahi[mf], ad);
                LDMATRIX_X4(alo[mf], ad + (SM_QLO - SM_QHI));
            }
            #pragma unroll
            for (int nf = 0; nf < 8; nf++) {
                uint32_t bh[2], bl[2];
                uint32_t bd = sb + SM_KHI + (uint32_t)(nf * 8 + gid) * ATROW + ks * 32 + tg * 4;
                LDS32(bh[0], bd); LDS32(bh[1], bd + 16);
                LDS32(bl[0], bd + (SM_KLO - SM_KHI));
                LDS32(bl[1], bd + (SM_KLO - SM_KHI) + 16);
                #pragma unroll
                for (int mf = 0; mf < 2; mf++) {
                    MMA_BF16(sacc[mf][nf], ahi[mf], bh);
                    MMA_BF16(sacc[mf][nf], ahi[mf], bl);
                    MMA_BF16(sacc[mf][nf], alo[mf], bh);
                }
            }
        }

        // ---- causal mask (diagonal tiles only) ----
        if (kt0 + 63 > q0 + m0w) {
            #pragma unroll
            for (int mf = 0; mf < 2; mf++)
                #pragma unroll
                for (int nf = 0; nf < 8; nf++)
                    #pragma unroll
                    for (int e = 0; e < 4; e++) {
                        int col = kt0 + nf * 8 + 2 * tg + (e & 1);
                        int row = q0 + m0w + mf * 16 + gid + ((e >> 1) ? 8 : 0);
                        if (col > row) sacc[mf][nf][e] = -1e30f;
                    }
        }

        // ---- online softmax ----
        float corr[2][2];
        #pragma unroll
        for (int mf = 0; mf < 2; mf++) {
            #pragma unroll
            for (int s = 0; s < 2; s++) {
                float vmax = -1e30f;
                #pragma unroll
                for (int nf = 0; nf < 8; nf++) {
                    vmax = fmaxf(vmax, sacc[mf][nf][2*s]);
                    vmax = fmaxf(vmax, sacc[mf][nf][2*s+1]);
                }
                vmax = fmaxf(vmax, __shfl_xor_sync(0xFFFFFFFF, vmax, 1));
                vmax = fmaxf(vmax, __shfl_xor_sync(0xFFFFFFFF, vmax, 2));
                float mo = mrow[mf][s];
                float mn = fmaxf(mo, vmax);
                float cr = exp2f_fast(mo - mn);
                corr[mf][s] = cr;
                mrow[mf][s] = mn;
                float rs = 0.f;
                #pragma unroll
                for (int nf = 0; nf < 8; nf++) {
                    float p0 = exp2f_fast(sacc[mf][nf][2*s]   - mn);
                    float p1 = exp2f_fast(sacc[mf][nf][2*s+1] - mn);
                    sacc[mf][nf][2*s]   = p0;
                    sacc[mf][nf][2*s+1] = p1;
                    rs += p0 + p1;
                }
                rs += __shfl_xor_sync(0xFFFFFFFF, rs, 1);
                rs += __shfl_xor_sync(0xFFFFFFFF, rs, 2);
                lrow[mf][s] = lrow[mf][s] * cr + rs;
            }
        }
        #pragma unroll
        for (int mf = 0; mf < 2; mf++)
            #pragma unroll
            for (int nf = 0; nf < 8; nf++)
                #pragma unroll
                for (int e = 0; e < 4; e++)
                    oacc[mf][nf][e] *= corr[mf][e >> 1];

        // ---- O += P V (3 terms, P split hi/lo) ----
        #pragma unroll
        for (int kf = 0; kf < 4; kf++) {
            uint32_t phi[2][4], plo[2][4];
            #pragma unroll
            for (int mf = 0; mf < 2; mf++) {
                #pragma unroll
                for (int half = 0; half < 2; half++) {   // nf = 2kf, 2kf+1
                    const float* c = sacc[mf][2 * kf + half];
                    #pragma unroll
                    for (int s = 0; s < 2; s++) {        // reg pairs (0,1),(2,3)
                        float v0 = c[2*s], v1 = c[2*s+1];
                        __nv_bfloat16 h0 = __float2bfloat16(v0);
                        __nv_bfloat16 h1 = __float2bfloat16(v1);
                        float l0 = v0 - __bfloat162float(h0);
                        float l1 = v1 - __bfloat162float(h1);
                        __nv_bfloat162 H(h0, h1);
                        phi[mf][half * 2 + s] = *(uint32_t*)&H;
                        plo[mf][half * 2 + s] = pack_bf16(l0, l1);
                    }
                }
                // reorder to A-frag: a0=(lo half,s0) a1=(lo half,s1) a2=(hi half,s0) a3=(hi half,s1)
                // built order: [half*2+s] = {h0s0,h0s1,h1s0,h1s1} == {a0,a1,a2,a3}  ✓
            }
            #pragma unroll
            for (int nf = 0; nf < 8; nf++) {
                uint32_t bh[2], bl[2];
                uint32_t bd = sb + SM_VHI + (uint32_t)(nf * 8 + gid) * ATROW
                              + (uint32_t)(kf * 16 + 2 * tg) * 2;
                LDS32(bh[0], bd); LDS32(bh[1], bd + 16);
                LDS32(bl[0], bd + (SM_VLO - SM_VHI));
                LDS32(bl[1], bd + (SM_VLO - SM_VHI) + 16);
                #pragma unroll
                for (int mf = 0; mf < 2; mf++) {
                    MMA_BF16(oacc[mf][nf], phi[mf], bh);
                    MMA_BF16(oacc[mf][nf], phi[mf], bl);
                    MMA_BF16(oacc[mf][nf], plo[mf], bh);
                }
            }
        }
    }

    // ---- epilogue: normalize, split to bf16, store ----
    float inv[2][2];
    #pragma unroll
    for (int mf = 0; mf < 2; mf++) {
        inv[mf][0] = 1.f / lrow[mf][0];
        inv[mf][1] = 1.f / lrow[mf][1];
    }
    #pragma unroll
    for (int mf = 0; mf < 2; mf++) {
        #pragma unroll
        for (int s = 0; s < 2; s++) {
            int r = q0 + m0w + mf * 16 + gid + 8 * s;
            #pragma unroll
            for (int nf = 0; nf < 8; nf++) {
                float v0 = oacc[mf][nf][2*s]   * inv[mf][s];
                float v1 = oacc[mf][nf][2*s+1] * inv[mf][s];
                __nv_bfloat16 h0 = __float2bfloat16(v0);
                __nv_bfloat16 h1 = __float2bfloat16(v1);
                float l0 = v0 - __bfloat162float(h0);
                float l1 = v1 - __bfloat162float(h1);
                size_t off = (rowbase + r) * D_MODEL + colh + nf * 8 + 2 * tg;
                __nv_bfloat162 H(h0, h1);
                *(uint32_t*)(Ohi + off) = *(uint32_t*)&H;
                *(uint32_t*)(Olo + off) = pack_bf16(l0, l1);
            }
        }
    }
}

// ---------------------------------------------------------------------------
extern "C" void kernel_launch(void* const* d_in, const int* in_sizes, int n_in,
                              void* d_out, int out_size)
{
    const float* x  = (const float*)d_in[0];
    const float* Wq = (const float*)d_in[1];
    const float* bq = (const float*)d_in[2];
    const float* Wk = (const float*)d_in[3];
    const float* bk = (const float*)d_in[4];
    const float* Wv = (const float*)d_in[5];
    const float* bv = (const float*)d_in[6];
    const float* Wo = (const float*)d_in[7];
    const float* bo = (const float*)d_in[8];
    float* out = (float*)d_out;

    __nv_bfloat16 *xhi, *xlo, *Whi, *Wlo;
    __nv_bfloat16 *qhi, *qlo, *khi, *klo, *vhi, *vlo, *aohi, *aolo;
    cudaGetSymbolAddress((void**)&xhi, g_xhi);
    cudaGetSymbolAddress((void**)&xlo, g_xlo);
    cudaGetSymbolAddress((void**)&Whi, g_Whi);
    cudaGetSymbolAddress((void**)&Wlo, g_Wlo);
    cudaGetSymbolAddress((void**)&qhi, g_qhi);
    cudaGetSymbolAddress((void**)&qlo, g_qlo);
    cudaGetSymbolAddress((void**)&khi, g_khi);
    cudaGetSymbolAddress((void**)&klo, g_klo);
    cudaGetSymbolAddress((void**)&vhi, g_vhi);
    cudaGetSymbolAddress((void**)&vlo, g_vlo);
    cudaGetSymbolAddress((void**)&aohi, g_aohi);
    cudaGetSymbolAddress((void**)&aolo, g_aolo);

    cudaFuncSetAttribute(gemm_bf16_mma,
                         cudaFuncAttributeMaxDynamicSharedMemorySize, GEMM_SMEM);
    cudaFuncSetAttribute(attn_mma,
                         cudaFuncAttributeMaxDynamicSharedMemorySize, ATTN_SMEM);

    const int NX4 = MTOT * D_MODEL / 4;
    const int NW4 = D_MODEL * D_MODEL / 4;
    const int WSZ = D_MODEL * D_MODEL;
    const float SCALE_Q = 0.125f * 1.44269504f;   // 1/sqrt(64) * log2(e)

    split_bf16<<<(NX4 + 255) / 256, 256>>>(x, xhi, xlo, NX4);
    split_bf16<<<(NW4 + 255) / 256, 256>>>(Wq, Whi + 0 * WSZ, Wlo + 0 * WSZ, NW4);
    split_bf16<<<(NW4 + 255) / 256, 256>>>(Wk, Whi + 1 * WSZ, Wlo + 1 * WSZ, NW4);
    split_bf16<<<(NW4 + 255) / 256, 256>>>(Wv, Whi + 2 * WSZ, Wlo + 2 * WSZ, NW4);
    split_bf16<<<(NW4 + 255) / 256, 256>>>(Wo, Whi + 3 * WSZ, Wlo + 3 * WSZ, NW4);

    dim3 ggrid(D_MODEL / 128, MTOT / 128);   // (8, 32)
    gemm_bf16_mma<<<ggrid, 256, GEMM_SMEM>>>(xhi, xlo, Whi + 0 * WSZ, Wlo + 0 * WSZ,
                                             bq, nullptr, qhi, qlo, SCALE_Q);
    gemm_bf16_mma<<<ggrid, 256, GEMM_SMEM>>>(xhi, xlo, Whi + 1 * WSZ, Wlo + 1 * WSZ,
                                             bk, nullptr, khi, klo, 1.0f);
    gemm_bf16_mma<<<ggrid, 256, GEMM_SMEM>>>(xhi, xlo, Whi + 2 * WSZ, Wlo + 2 * WSZ,
                                             bv, nullptr, vhi, vlo, 1.0f);

    dim3 agrid(SEQ / 128, NHEAD, BATCH);     // (16, 16, 2)
    attn_mma<<<agrid, 128, ATTN_SMEM>>>(qhi, qlo, khi, klo, vhi, vlo, aohi, aolo);

    gemm_bf16_mma<<<ggrid, 256, GEMM_SMEM>>>(aohi, aolo, Whi + 3 * WSZ, Wlo + 3 * WSZ,
                                             bo, out, nullptr, nullptr, 1.0f);
}

// round 7
// speedup vs baseline: 2.7839x; 1.6895x over previous
#include <cuda_runtime.h>
#include <cuda_bf16.h>
#include <cstdint>

#define D_MODEL 1024
#define SEQ     2048
#define BATCH   2
#define NHEAD   16
#define DHEAD   64
#define MTOT    (BATCH * SEQ)   // 4096

// ---------------- scratch (__device__ globals) ------------------------------
__device__ __nv_bfloat16 g_xhi [MTOT * D_MODEL];
__device__ __nv_bfloat16 g_xlo [MTOT * D_MODEL];
__device__ __nv_bfloat16 g_Whi [4][D_MODEL * D_MODEL];
__device__ __nv_bfloat16 g_Wlo [4][D_MODEL * D_MODEL];
__device__ __nv_bfloat16 g_qhi [MTOT * D_MODEL];
__device__ __nv_bfloat16 g_qlo [MTOT * D_MODEL];
__device__ __nv_bfloat16 g_khi [MTOT * D_MODEL];
__device__ __nv_bfloat16 g_klo [MTOT * D_MODEL];
__device__ __nv_bfloat16 g_vhi [MTOT * D_MODEL];
__device__ __nv_bfloat16 g_vlo [MTOT * D_MODEL];
__device__ __nv_bfloat16 g_aohi[MTOT * D_MODEL];
__device__ __nv_bfloat16 g_aolo[MTOT * D_MODEL];

// ---------------------------------------------------------------------------
__device__ __forceinline__ uint32_t smem_u32(const void* p) {
    uint32_t a;
    asm("{ .reg .u64 t; cvta.to.shared.u64 t, %1; cvt.u32.u64 %0, t; }"
        : "=r"(a) : "l"(p));
    return a;
}

#define MMA_BF16(acc, a, b) \
    asm volatile("mma.sync.aligned.m16n8k16.row.col.f32.bf16.bf16.f32 " \
        "{%0,%1,%2,%3}, {%4,%5,%6,%7}, {%8,%9}, {%0,%1,%2,%3};" \
        : "+f"((acc)[0]), "+f"((acc)[1]), "+f"((acc)[2]), "+f"((acc)[3]) \
        : "r"((a)[0]), "r"((a)[1]), "r"((a)[2]), "r"((a)[3]), \
          "r"((b)[0]), "r"((b)[1]))

#define LDMATRIX_X4(r, addr) \
    asm volatile("ldmatrix.sync.aligned.m8n8.x4.shared.b16 {%0,%1,%2,%3}, [%4];" \
        : "=r"((r)[0]), "=r"((r)[1]), "=r"((r)[2]), "=r"((r)[3]) : "r"(addr))

#define LDMATRIX_X4_T(r, addr) \
    asm volatile("ldmatrix.sync.aligned.m8n8.x4.trans.shared.b16 {%0,%1,%2,%3}, [%4];" \
        : "=r"((r)[0]), "=r"((r)[1]), "=r"((r)[2]), "=r"((r)[3]) : "r"(addr))

#define LDS32(r, addr) \
    asm volatile("ld.shared.b32 %0, [%1];" : "=r"(r) : "r"(addr))

#define CP_ASYNC16(d, g) \
    asm volatile("cp.async.cg.shared.global [%0], [%1], 16;" :: "r"(d), "l"(g))
#define CP_COMMIT()  asm volatile("cp.async.commit_group;" ::: "memory")
#define CP_WAIT(n)   asm volatile("cp.async.wait_group %0;" :: "n"(n) : "memory")

__device__ __forceinline__ uint32_t pack_bf16(float lo, float hi) {
    __nv_bfloat162 t = __floats2bfloat162_rn(lo, hi);  // x=lo, y=hi
    return *(uint32_t*)&t;
}

// fast exp2 for x <= 0 (fma/alu pipe only, rel err ~2e-6)
__device__ __forceinline__ float exp2f_fast(float x) {
    x = fmaxf(x, -100.f);
    float r = x + 12582912.f;
    int  ir = __float_as_int(r);
    float n = r - 12582912.f;
    float f = x - n;
    float p = 1.33335581e-3f;
    p = fmaf(p, f, 9.61817249e-3f);
    p = fmaf(p, f, 5.55041086e-2f);
    p = fmaf(p, f, 2.40226507e-1f);
    p = fmaf(p, f, 6.93147182e-1f);
    p = fmaf(p, f, 1.0f);
    return __int_as_float(__float_as_int(p) + ((ir - 0x4B400000) << 23));
}

// ---------------------------------------------------------------------------
// fp32 -> (hi, lo) bf16 split.
// ---------------------------------------------------------------------------
__global__ void __launch_bounds__(256) split_bf16(
    const float* __restrict__ in, __nv_bfloat16* __restrict__ hi,
    __nv_bfloat16* __restrict__ lo, int n4)
{
    int i = blockIdx.x * 256 + threadIdx.x;
    if (i >= n4) return;
    float4 v = ((const float4*)in)[i];
    __nv_bfloat16 hx = __float2bfloat16(v.x);
    __nv_bfloat16 hy = __float2bfloat16(v.y);
    __nv_bfloat16 hz = __float2bfloat16(v.z);
    __nv_bfloat16 hw = __float2bfloat16(v.w);
    __nv_bfloat16 lx = __float2bfloat16(v.x - __bfloat162float(hx));
    __nv_bfloat16 ly = __float2bfloat16(v.y - __bfloat162float(hy));
    __nv_bfloat16 lz = __float2bfloat16(v.z - __bfloat162float(hz));
    __nv_bfloat16 lw = __float2bfloat16(v.w - __bfloat162float(hw));
    union { __nv_bfloat162 b[2]; uint2 u; } H, L;
    H.b[0] = __nv_bfloat162(hx, hy); H.b[1] = __nv_bfloat162(hz, hw);
    L.b[0] = __nv_bfloat162(lx, ly); L.b[1] = __nv_bfloat162(lz, lw);
    *(uint2*)(hi + 4 * (size_t)i) = H.u;
    *(uint2*)(lo + 4 * (size_t)i) = L.u;
}

// ---------------------------------------------------------------------------
// Split-bf16 GEMM (validated R3/R5).
// ---------------------------------------------------------------------------
#define TROW   80
#define TILE_B (128 * TROW)
#define STAGE_B (4 * TILE_B)
#define GEMM_SMEM (2 * STAGE_B)   // 81920 B

__global__ void __launch_bounds__(256, 1) gemm_bf16_mma(
    const __nv_bfloat16* __restrict__ Ahi, const __nv_bfloat16* __restrict__ Alo,
    const __nv_bfloat16* __restrict__ Bhi, const __nv_bfloat16* __restrict__ Blo,
    const float* __restrict__ bias, float* __restrict__ Cf,
    __nv_bfloat16* __restrict__ Chi, __nv_bfloat16* __restrict__ Clo,
    float scale)
{
    extern __shared__ char smem[];
    constexpr int K = D_MODEL;
    const int tid  = threadIdx.x;
    const int lane = tid & 31;
    const int wid  = tid >> 5;
    const int bm = blockIdx.y * 128;
    const int bn = blockIdx.x * 128;
    const int m0w = (wid & 1) * 64;
    const int n0w = (wid >> 1) * 32;
    const int gid = lane >> 2;
    const int tg  = lane & 3;

    const uint32_t sb = smem_u32(smem);

    const __nv_bfloat16* src[4] = {
        Ahi + (size_t)bm * K, Alo + (size_t)bm * K,
        Bhi + (size_t)bn * K, Blo + (size_t)bn * K };

    auto copy_chunk = [&](int c) {
        const int buf = c & 1;
        const int kc  = c * 32;
        #pragma unroll
        for (int t = 0; t < 4; t++) {
            #pragma unroll
            for (int i = 0; i < 2; i++) {
                int v = tid + i * 256;
                int row = v >> 2, seg = v & 3;
                const __nv_bfloat16* g = src[t] + (size_t)row * K + kc + seg * 8;
                uint32_t d = sb + buf * STAGE_B + t * TILE_B + row * TROW + seg * 16;
                CP_ASYNC16(d, g);
            }
        }
    };

    float acc[4][4][4];
    #pragma unroll
    for (int mt = 0; mt < 4; mt++)
        #pragma unroll
        for (int nt = 0; nt < 4; nt++)
            #pragma unroll
            for (int j = 0; j < 4; j++) acc[mt][nt][j] = 0.f;

    const int NCH = K / 32;
    copy_chunk(0);
    CP_COMMIT();

    for (int c = 0; c < NCH; c++) {
        if (c + 1 < NCH) { copy_chunk(c + 1); CP_COMMIT(); CP_WAIT(1); }
        else             { CP_WAIT(0); }
        __syncthreads();

        const uint32_t stage = sb + (c & 1) * STAGE_B;

        #pragma unroll
        for (int ks = 0; ks < 2; ks++) {
            uint32_t ahi[4][4], alo[4][4];
            const uint32_t aoff = (uint32_t)(m0w + (lane & 15)) * TROW
                                  + ks * 32 + (lane >> 4) * 16;
            #pragma unroll
            for (int mt = 0; mt < 4; mt++) {
                uint32_t ad = stage + aoff + mt * (16 * TROW);
                LDMATRIX_X4(ahi[mt], ad);
                LDMATRIX_X4(alo[mt], ad + TILE_B);
            }

            uint32_t bhi[4][2], blo[4][2];
            const uint32_t boff = (uint32_t)(n0w + gid) * TROW + ks * 32 + tg * 4;
            #pragma unroll
            for (int nt = 0; nt < 4; nt++) {
                uint32_t bd = stage + 2 * TILE_B + boff + nt * (8 * TROW);
                LDS32(bhi[nt][0], bd);
                LDS32(bhi[nt][1], bd + 16);
                LDS32(blo[nt][0], bd + TILE_B);
                LDS32(blo[nt][1], bd + TILE_B + 16);
            }

            #pragma unroll
            for (int mt = 0; mt < 4; mt++)
                #pragma unroll
                for (int nt = 0; nt < 4; nt++)
                    MMA_BF16(acc[mt][nt], ahi[mt], bhi[nt]);
            #pragma unroll
            for (int mt = 0; mt < 4; mt++)
                #pragma unroll
                for (int nt = 0; nt < 4; nt++)
                    MMA_BF16(acc[mt][nt], ahi[mt], blo[nt]);
            #pragma unroll
            for (int mt = 0; mt < 4; mt++)
                #pragma unroll
                for (int nt = 0; nt < 4; nt++)
                    MMA_BF16(acc[mt][nt], alo[mt], bhi[nt]);
        }
        __syncthreads();
    }

    if (Chi) {
        #pragma unroll
        for (int nt = 0; nt < 4; nt++) {
            const int col = bn + n0w + nt * 8 + 2 * tg;
            const float b0 = bias[col], b1 = bias[col + 1];
            #pragma unroll
            for (int mt = 0; mt < 4; mt++) {
                const int r0 = bm + m0w + mt * 16 + gid;
                #pragma unroll
                for (int s = 0; s < 2; s++) {
                    float v0 = (acc[mt][nt][2*s+0] + b0) * scale;
                    float v1 = (acc[mt][nt][2*s+1] + b1) * scale;
                    __nv_bfloat16 h0 = __float2bfloat16(v0);
                    __nv_bfloat16 h1 = __float2bfloat16(v1);
                    float l0 = v0 - __bfloat162float(h0);
                    float l1 = v1 - __bfloat162float(h1);
                    size_t off = (size_t)(r0 + 8 * s) * D_MODEL + col;
                    __nv_bfloat162 H(h0, h1);
                    *(uint32_t*)(Chi + off) = *(uint32_t*)&H;
                    *(uint32_t*)(Clo + off) = pack_bf16(l0, l1);
                }
            }
        }
    } else {
        #pragma unroll
        for (int nt = 0; nt < 4; nt++) {
            const int col = bn + n0w + nt * 8 + 2 * tg;
            const float b0 = bias[col], b1 = bias[col + 1];
            #pragma unroll
            for (int mt = 0; mt < 4; mt++) {
                const int r0 = bm + m0w + mt * 16 + gid;
                float2 v0, v1;
                v0.x = acc[mt][nt][0] + b0; v0.y = acc[mt][nt][1] + b1;
                v1.x = acc[mt][nt][2] + b0; v1.y = acc[mt][nt][3] + b1;
                *(float2*)(Cf + (size_t)r0 * D_MODEL + col)       = v0;
                *(float2*)(Cf + (size_t)(r0 + 8) * D_MODEL + col) = v1;
            }
        }
    }
}

// ---------------------------------------------------------------------------
// MMA flash attention v2 (fixed). CTA = 128 query rows; 8 warps x 16 rows.
// Q fragments preloaded to registers; K/V double-buffered via cp.async;
// V B-fragments via ldmatrix.x4.trans. 3-term split-bf16 QK^T and PV;
// exp2 polynomial softmax (scores pre-scaled by 0.125*log2e).
// ---------------------------------------------------------------------------
#define ATROW 144
#define ARR_B (64 * ATROW)          // 9216 per K/V array
#define ASTG  (4 * ARR_B)           // 36864 per stage (Khi,Klo,Vhi,Vlo)
#define A_KHI 0
#define A_KLO ARR_B
#define A_VHI (2 * ARR_B)
#define A_VLO (3 * ARR_B)
#define AQ_HI 0                     // Q staged in stage-0 area
#define AQ_LO (128 * ATROW)         // 18432
#define ATTN_SMEM (2 * ASTG)        // 73728

__global__ void __launch_bounds__(256, 2) attn_mma(
    const __nv_bfloat16* __restrict__ Qhi, const __nv_bfloat16* __restrict__ Qlo,
    const __nv_bfloat16* __restrict__ Khi, const __nv_bfloat16* __restrict__ Klo,
    const __nv_bfloat16* __restrict__ Vhi, const __nv_bfloat16* __restrict__ Vlo,
    __nv_bfloat16* __restrict__ Ohi, __nv_bfloat16* __restrict__ Olo)
{
    extern __shared__ char smem[];
    const uint32_t sb = smem_u32(smem);
    const int b  = blockIdx.z;
    const int h  = blockIdx.y;
    const int qb = gridDim.x - 1 - blockIdx.x;   // heavy CTAs first
    const int tid  = threadIdx.x;
    const int lane = tid & 31;
    const int wid  = tid >> 5;                   // 0..7
    const int gid  = lane >> 2;
    const int tg   = lane & 3;
    const int q0   = qb * 128;
    const int r0w  = q0 + wid * 16;              // this warp's 16 rows
    const size_t rowbase = (size_t)b * SEQ;
    const int colh = h * DHEAD;

    // ---- stage Q (FIX: 8 iters cover both arrays x 128 rows x 8 segs) ----
    #pragma unroll
    for (int i = 0; i < 8; i++) {
        int v = tid + i * 256;            // 0..2047
        int arr = v >> 10;                // 0:hi 1:lo
        int rem = v & 1023;
        int r = rem >> 3, seg = rem & 7;
        size_t g = (rowbase + q0 + r) * D_MODEL + colh + seg * 8;
        const __nv_bfloat16* s = arr ? Qlo : Qhi;
        CP_ASYNC16(sb + (arr ? AQ_LO : AQ_HI) + r * ATROW + seg * 16, s + g);
    }
    CP_COMMIT();
    CP_WAIT(0);
    __syncthreads();

    uint32_t qh[4][4], ql[4][4];
    {
        const uint32_t aoff = (uint32_t)(wid * 16 + (lane & 15)) * ATROW
                              + (lane >> 4) * 16;
        #pragma unroll
        for (int ks = 0; ks < 4; ks++) {
            LDMATRIX_X4(qh[ks], sb + AQ_HI + aoff + ks * 32);
            LDMATRIX_X4(ql[ks], sb + AQ_LO + aoff + ks * 32);
        }
    }
    __syncthreads();   // Q smem consumed; safe to overwrite with K/V stages

    float oacc[8][4];
    #pragma unroll
    for (int nf = 0; nf < 8; nf++)
        #pragma unroll
        for (int e = 0; e < 4; e++) oacc[nf][e] = 0.f;
    float mrow[2] = {-1e30f, -1e30f};
    float lrow[2] = {0.f, 0.f};

    const __nv_bfloat16* kvsrc[4] = { Khi, Klo, Vhi, Vlo };

    auto stage_tile = [&](int c) {
        const uint32_t base = sb + (uint32_t)(c & 1) * ASTG;
        const int kt = c * 64;
        #pragma unroll
        for (int i = 0; i < 8; i++) {
            int v = tid + i * 256;        // 0..2047
            int arr = v >> 9;             // 0..3
            int rem = v & 511;
            int r = rem >> 3, seg = rem & 7;
            size_t g = (rowbase + kt + r) * D_MODEL + colh + seg * 8;
            CP_ASYNC16(base + arr * ARR_B + r * ATROW + seg * 16, kvsrc[arr] + g);
        }
    };

    const int NT = (q0 + 128) / 64;       // tiles of 64 keys
    stage_tile(0);
    CP_COMMIT();

    for (int c = 0; c < NT; c++) {
        if (c + 1 < NT) { stage_tile(c + 1); CP_COMMIT(); CP_WAIT(1); }
        else            { CP_WAIT(0); }
        __syncthreads();

        const int kt0 = c * 64;
        const uint32_t stg = sb + (uint32_t)(c & 1) * ASTG;

        if (kt0 <= r0w + 15) {            // warp not fully masked
            // ---- S = Q K^T (3 terms) ----
            float sacc[8][4];
            #pragma unroll
            for (int nf = 0; nf < 8; nf++)
                #pragma unroll
                for (int e = 0; e < 4; e++) sacc[nf][e] = 0.f;

            #pragma unroll
            for (int ks = 0; ks < 4; ks++) {
                #pragma unroll
                for (int nf = 0; nf < 8; nf++) {
                    uint32_t bh[2], bl[2];
                    uint32_t bd = stg + A_KHI + (uint32_t)(nf * 8 + gid) * ATROW
                                  + ks * 32 + tg * 4;
                    LDS32(bh[0], bd); LDS32(bh[1], bd + 16);
                    LDS32(bl[0], bd + ARR_B);
                    LDS32(bl[1], bd + ARR_B + 16);
                    MMA_BF16(sacc[nf], qh[ks], bh);
                    MMA_BF16(sacc[nf], qh[ks], bl);
                    MMA_BF16(sacc[nf], ql[ks], bh);
                }
            }

            // ---- causal mask (diagonal tiles only) ----
            if (kt0 + 63 > r0w) {
                #pragma unroll
                for (int nf = 0; nf < 8; nf++)
                    #pragma unroll
                    for (int e = 0; e < 4; e++) {
                        int col = kt0 + nf * 8 + 2 * tg + (e & 1);
                        int row = r0w + gid + ((e >> 1) ? 8 : 0);
                        if (col > row) sacc[nf][e] = -1e30f;
                    }
            }

            // ---- online softmax ----
            float corr[2];
            #pragma unroll
            for (int s = 0; s < 2; s++) {
                float vmax = -1e30f;
                #pragma unroll
                for (int nf = 0; nf < 8; nf++) {
                    vmax = fmaxf(vmax, sacc[nf][2*s]);
                    vmax = fmaxf(vmax, sacc[nf][2*s+1]);
                }
                vmax = fmaxf(vmax, __shfl_xor_sync(0xFFFFFFFF, vmax, 1));
                vmax = fmaxf(vmax, __shfl_xor_sync(0xFFFFFFFF, vmax, 2));
                float mo = mrow[s];
                float mn = fmaxf(mo, vmax);
                float cr = exp2f_fast(mo - mn);
                corr[s] = cr;
                mrow[s] = mn;
                float rs = 0.f;
                #pragma unroll
                for (int nf = 0; nf < 8; nf++) {
                    float p0 = exp2f_fast(sacc[nf][2*s]   - mn);
                    float p1 = exp2f_fast(sacc[nf][2*s+1] - mn);
                    sacc[nf][2*s]   = p0;
                    sacc[nf][2*s+1] = p1;
                    rs += p0 + p1;
                }
                rs += __shfl_xor_sync(0xFFFFFFFF, rs, 1);
                rs += __shfl_xor_sync(0xFFFFFFFF, rs, 2);
                lrow[s] = lrow[s] * cr + rs;
            }
            #pragma unroll
            for (int nf = 0; nf < 8; nf++)
                #pragma unroll
                for (int e = 0; e < 4; e++)
                    oacc[nf][e] *= corr[e >> 1];

            // ---- O += P V (3 terms) ----
            #pragma unroll
            for (int kf = 0; kf < 4; kf++) {
                // pack P fragment (A-frag for keys kf*16..+15)
                uint32_t phi[4], plo[4];
                #pragma unroll
                for (int half = 0; half < 2; half++) {
                    const float* c2 = sacc[2 * kf + half];
                    #pragma unroll
                    for (int s = 0; s < 2; s++) {
                        float v0 = c2[2*s], v1 = c2[2*s+1];
                        __nv_bfloat16 h0 = __float2bfloat16(v0);
                        __nv_bfloat16 h1 = __float2bfloat16(v1);
                        float l0 = v0 - __bfloat162float(h0);
                        float l1 = v1 - __bfloat162float(h1);
                        __nv_bfloat162 H(h0, h1);
                        phi[half * 2 + s] = *(uint32_t*)&H;
                        plo[half * 2 + s] = pack_bf16(l0, l1);
                    }
                }
                // V B-frags via ldmatrix.trans; FIX: 32 B (16 dh) per nf2 step
                #pragma unroll
                for (int nf2 = 0; nf2 < 4; nf2++) {
                    uint32_t row = kf * 16 + ((lane >> 3) & 1) * 8 + (lane & 7);
                    uint32_t cb  = nf2 * 32 + (lane >> 4) * 16;
                    uint32_t ad  = stg + A_VHI + row * ATROW + cb;
                    uint32_t rh[4], rl[4];
                    LDMATRIX_X4_T(rh, ad);
                    LDMATRIX_X4_T(rl, ad + ARR_B);
                    uint32_t bh0[2] = { rh[0], rh[1] }, bh1[2] = { rh[2], rh[3] };
                    uint32_t bl0[2] = { rl[0], rl[1] }, bl1[2] = { rl[2], rl[3] };
                    MMA_BF16(oacc[2*nf2],   phi, bh0);
                    MMA_BF16(oacc[2*nf2],   phi, bl0);
                    MMA_BF16(oacc[2*nf2],   plo, bh0);
                    MMA_BF16(oacc[2*nf2+1], phi, bh1);
                    MMA_BF16(oacc[2*nf2+1], phi, bl1);
                    MMA_BF16(oacc[2*nf2+1], plo, bh1);
                }
            }
        }
        __syncthreads();   // all warps done with this stage before reuse
    }

    // ---- epilogue: normalize, split to bf16, store ----
    float inv[2] = { 1.f / lrow[0], 1.f / lrow[1] };
    #pragma unroll
    for (int s = 0; s < 2; s++) {
        int r = r0w + gid + 8 * s;
        #pragma unroll
        for (int nf = 0; nf < 8; nf++) {
            float v0 = oacc[nf][2*s]   * inv[s];
            float v1 = oacc[nf][2*s+1] * inv[s];
            __nv_bfloat16 h0 = __float2bfloat16(v0);
            __nv_bfloat16 h1 = __float2bfloat16(v1);
            float l0 = v0 - __bfloat162float(h0);
            float l1 = v1 - __bfloat162float(h1);
            size_t off = (rowbase + r) * D_MODEL + colh + nf * 8 + 2 * tg;
            __nv_bfloat162 H(h0, h1);
            *(uint32_t*)(Ohi + off) = *(uint32_t*)&H;
            *(uint32_t*)(Olo + off) = pack_bf16(l0, l1);
        }
    }
}

// ---------------------------------------------------------------------------
extern "C" void kernel_launch(void* const* d_in, const int* in_sizes, int n_in,
                              void* d_out, int out_size)
{
    const float* x  = (const float*)d_in[0];
    const float* Wq = (const float*)d_in[1];
    const float* bq = (const float*)d_in[2];
    const float* Wk = (const float*)d_in[3];
    const float* bk = (const float*)d_in[4];
    const float* Wv = (const float*)d_in[5];
    const float* bv = (const float*)d_in[6];
    const float* Wo = (const float*)d_in[7];
    const float* bo = (const float*)d_in[8];
    float* out = (float*)d_out;

    __nv_bfloat16 *xhi, *xlo, *Whi, *Wlo;
    __nv_bfloat16 *qhi, *qlo, *khi, *klo, *vhi, *vlo, *aohi, *aolo;
    cudaGetSymbolAddress((void**)&xhi, g_xhi);
    cudaGetSymbolAddress((void**)&xlo, g_xlo);
    cudaGetSymbolAddress((void**)&Whi, g_Whi);
    cudaGetSymbolAddress((void**)&Wlo, g_Wlo);
    cudaGetSymbolAddress((void**)&qhi, g_qhi);
    cudaGetSymbolAddress((void**)&qlo, g_qlo);
    cudaGetSymbolAddress((void**)&khi, g_khi);
    cudaGetSymbolAddress((void**)&klo, g_klo);
    cudaGetSymbolAddress((void**)&vhi, g_vhi);
    cudaGetSymbolAddress((void**)&vlo, g_vlo);
    cudaGetSymbolAddress((void**)&aohi, g_aohi);
    cudaGetSymbolAddress((void**)&aolo, g_aolo);

    cudaFuncSetAttribute(gemm_bf16_mma,
                         cudaFuncAttributeMaxDynamicSharedMemorySize, GEMM_SMEM);
    cudaFuncSetAttribute(attn_mma,
                         cudaFuncAttributeMaxDynamicSharedMemorySize, ATTN_SMEM);

    const int NX4 = MTOT * D_MODEL / 4;
    const int NW4 = D_MODEL * D_MODEL / 4;
    const int WSZ = D_MODEL * D_MODEL;
    const float SCALE_Q = 0.125f * 1.44269504f;   // 1/sqrt(64) * log2(e)

    split_bf16<<<(NX4 + 255) / 256, 256>>>(x, xhi, xlo, NX4);
    split_bf16<<<(NW4 + 255) / 256, 256>>>(Wq, Whi + 0 * WSZ, Wlo + 0 * WSZ, NW4);
    split_bf16<<<(NW4 + 255) / 256, 256>>>(Wk, Whi + 1 * WSZ, Wlo + 1 * WSZ, NW4);
    split_bf16<<<(NW4 + 255) / 256, 256>>>(Wv, Whi + 2 * WSZ, Wlo + 2 * WSZ, NW4);
    split_bf16<<<(NW4 + 255) / 256, 256>>>(Wo, Whi + 3 * WSZ, Wlo + 3 * WSZ, NW4);

    dim3 ggrid(D_MODEL / 128, MTOT / 128);   // (8, 32)
    gemm_bf16_mma<<<ggrid, 256, GEMM_SMEM>>>(xhi, xlo, Whi + 0 * WSZ, Wlo + 0 * WSZ,
                                             bq, nullptr, qhi, qlo, SCALE_Q);
    gemm_bf16_mma<<<ggrid, 256, GEMM_SMEM>>>(xhi, xlo, Whi + 1 * WSZ, Wlo + 1 * WSZ,
                                             bk, nullptr, khi, klo, 1.0f);
    gemm_bf16_mma<<<ggrid, 256, GEMM_SMEM>>>(xhi, xlo, Whi + 2 * WSZ, Wlo + 2 * WSZ,
                                             bv, nullptr, vhi, vlo, 1.0f);

    dim3 agrid(SEQ / 128, NHEAD, BATCH);     // (16, 16, 2)
    attn_mma<<<agrid, 256, ATTN_SMEM>>>(qhi, qlo, khi, klo, vhi, vlo, aohi, aolo);

    gemm_bf16_mma<<<ggrid, 256, GEMM_SMEM>>>(aohi, aolo, Whi + 3 * WSZ, Wlo + 3 * WSZ,
                                             bo, out, nullptr, nullptr, 1.0f);
}

// round 8
// speedup vs baseline: 3.1214x; 1.1212x over previous
#include <cuda_runtime.h>
#include <cuda_bf16.h>
#include <cstdint>

#define D_MODEL 1024
#define SEQ     2048
#define BATCH   2
#define NHEAD   16
#define DHEAD   64
#define MTOT    (BATCH * SEQ)   // 4096
#define NELEM   (MTOT * D_MODEL)

// ---------------- scratch (__device__ globals) ------------------------------
__device__ __nv_bfloat16 g_xhi [NELEM];
__device__ __nv_bfloat16 g_xlo [NELEM];
__device__ __nv_bfloat16 g_Whi [4][D_MODEL * D_MODEL];
__device__ __nv_bfloat16 g_Wlo [4][D_MODEL * D_MODEL];
__device__ __nv_bfloat16 g_prjhi[3][NELEM];   // Q, K, V
__device__ __nv_bfloat16 g_prjlo[3][NELEM];
__device__ __nv_bfloat16 g_aohi[NELEM];
__device__ __nv_bfloat16 g_aolo[NELEM];

// ---------------------------------------------------------------------------
__device__ __forceinline__ uint32_t smem_u32(const void* p) {
    uint32_t a;
    asm("{ .reg .u64 t; cvta.to.shared.u64 t, %1; cvt.u32.u64 %0, t; }"
        : "=r"(a) : "l"(p));
    return a;
}

#define MMA_BF16(acc, a, b) \
    asm volatile("mma.sync.aligned.m16n8k16.row.col.f32.bf16.bf16.f32 " \
        "{%0,%1,%2,%3}, {%4,%5,%6,%7}, {%8,%9}, {%0,%1,%2,%3};" \
        : "+f"((acc)[0]), "+f"((acc)[1]), "+f"((acc)[2]), "+f"((acc)[3]) \
        : "r"((a)[0]), "r"((a)[1]), "r"((a)[2]), "r"((a)[3]), \
          "r"((b)[0]), "r"((b)[1]))

#define LDMATRIX_X4(r, addr) \
    asm volatile("ldmatrix.sync.aligned.m8n8.x4.shared.b16 {%0,%1,%2,%3}, [%4];" \
        : "=r"((r)[0]), "=r"((r)[1]), "=r"((r)[2]), "=r"((r)[3]) : "r"(addr))

#define LDMATRIX_X4_T(r, addr) \
    asm volatile("ldmatrix.sync.aligned.m8n8.x4.trans.shared.b16 {%0,%1,%2,%3}, [%4];" \
        : "=r"((r)[0]), "=r"((r)[1]), "=r"((r)[2]), "=r"((r)[3]) : "r"(addr))

#define LDS32(r, addr) \
    asm volatile("ld.shared.b32 %0, [%1];" : "=r"(r) : "r"(addr))

#define CP_ASYNC16(d, g) \
    asm volatile("cp.async.cg.shared.global [%0], [%1], 16;" :: "r"(d), "l"(g))
#define CP_COMMIT()  asm volatile("cp.async.commit_group;" ::: "memory")
#define CP_WAIT(n)   asm volatile("cp.async.wait_group %0;" :: "n"(n) : "memory")

__device__ __forceinline__ uint32_t pack_bf16(float lo, float hi) {
    __nv_bfloat162 t = __floats2bfloat162_rn(lo, hi);
    return *(uint32_t*)&t;
}

// fast exp2 for x <= 0 (fma/alu pipe only, rel err ~2e-6)
__device__ __forceinline__ float exp2f_fast(float x) {
    x = fmaxf(x, -100.f);
    float r = x + 12582912.f;
    int  ir = __float_as_int(r);
    float n = r - 12582912.f;
    float f = x - n;
    float p = 1.33335581e-3f;
    p = fmaf(p, f, 9.61817249e-3f);
    p = fmaf(p, f, 5.55041086e-2f);
    p = fmaf(p, f, 2.40226507e-1f);
    p = fmaf(p, f, 6.93147182e-1f);
    p = fmaf(p, f, 1.0f);
    return __int_as_float(__float_as_int(p) + ((ir - 0x4B400000) << 23));
}

// ---------------------------------------------------------------------------
// fp32 -> (hi, lo) bf16 splits
// ---------------------------------------------------------------------------
__device__ __forceinline__ void split4(const float* __restrict__ in,
                                       __nv_bfloat16* __restrict__ hi,
                                       __nv_bfloat16* __restrict__ lo, int i) {
    float4 v = ((const float4*)in)[i];
    __nv_bfloat16 hx = __float2bfloat16(v.x);
    __nv_bfloat16 hy = __float2bfloat16(v.y);
    __nv_bfloat16 hz = __float2bfloat16(v.z);
    __nv_bfloat16 hw = __float2bfloat16(v.w);
    __nv_bfloat16 lx = __float2bfloat16(v.x - __bfloat162float(hx));
    __nv_bfloat16 ly = __float2bfloat16(v.y - __bfloat162float(hy));
    __nv_bfloat16 lz = __float2bfloat16(v.z - __bfloat162float(hz));
    __nv_bfloat16 lw = __float2bfloat16(v.w - __bfloat162float(hw));
    union { __nv_bfloat162 b[2]; uint2 u; } H, L;
    H.b[0] = __nv_bfloat162(hx, hy); H.b[1] = __nv_bfloat162(hz, hw);
    L.b[0] = __nv_bfloat162(lx, ly); L.b[1] = __nv_bfloat162(lz, lw);
    *(uint2*)(hi + 4 * (size_t)i) = H.u;
    *(uint2*)(lo + 4 * (size_t)i) = L.u;
}

__global__ void __launch_bounds__(256) split_x(const float* __restrict__ in, int n4) {
    int i = blockIdx.x * 256 + threadIdx.x;
    if (i < n4) split4(in, g_xhi, g_xlo, i);
}

__global__ void __launch_bounds__(256) split_w4(
    const float* __restrict__ W0, const float* __restrict__ W1,
    const float* __restrict__ W2, const float* __restrict__ W3, int n4) {
    int y = blockIdx.y;
    const float* in = (y == 0) ? W0 : (y == 1) ? W1 : (y == 2) ? W2 : W3;
    int i = blockIdx.x * 256 + threadIdx.x;
    if (i < n4) split4(in, g_Whi[y], g_Wlo[y], i);
}

// ---------------------------------------------------------------------------
// GEMM mainloop (shared by QKV + O kernels). 128x128 tile, BK=32, 256 thr,
// warp grid 2x4, nt-outer MMA ordering to keep live regs ~115 (occ 2).
// ---------------------------------------------------------------------------
#define TROW   80
#define TILE_B (128 * TROW)
#define STAGE_B (4 * TILE_B)
#define GEMM_SMEM (2 * STAGE_B)   // 81920 B

__device__ __forceinline__ void gemm_mainloop(
    const __nv_bfloat16* __restrict__ Ahi, const __nv_bfloat16* __restrict__ Alo,
    const __nv_bfloat16* __restrict__ Bhi, const __nv_bfloat16* __restrict__ Blo,
    uint32_t sb, int tid, float acc[4][4][4])
{
    constexpr int K = D_MODEL;
    const int lane = tid & 31;
    const int wid  = tid >> 5;
    const int m0w = (wid & 1) * 64;
    const int n0w = (wid >> 1) * 32;
    const int gid = lane >> 2;
    const int tg  = lane & 3;

    const __nv_bfloat16* src[4] = { Ahi, Alo, Bhi, Blo };

    auto copy_chunk = [&](int c) {
        const int buf = c & 1;
        const int kc  = c * 32;
        #pragma unroll
        for (int t = 0; t < 4; t++) {
            #pragma unroll
            for (int i = 0; i < 2; i++) {
                int v = tid + i * 256;
                int row = v >> 2, seg = v & 3;
                const __nv_bfloat16* g = src[t] + (size_t)row * K + kc + seg * 8;
                uint32_t d = sb + buf * STAGE_B + t * TILE_B + row * TROW + seg * 16;
                CP_ASYNC16(d, g);
            }
        }
    };

    const int NCH = K / 32;
    copy_chunk(0);
    CP_COMMIT();

    for (int c = 0; c < NCH; c++) {
        if (c + 1 < NCH) { copy_chunk(c + 1); CP_COMMIT(); CP_WAIT(1); }
        else             { CP_WAIT(0); }
        __syncthreads();

        const uint32_t stage = sb + (c & 1) * STAGE_B;

        #pragma unroll
        for (int ks = 0; ks < 2; ks++) {
            uint32_t ahi[4][4], alo[4][4];
            const uint32_t aoff = (uint32_t)(m0w + (lane & 15)) * TROW
                                  + ks * 32 + (lane >> 4) * 16;
            #pragma unroll
            for (int mt = 0; mt < 4; mt++) {
                uint32_t ad = stage + aoff + mt * (16 * TROW);
                LDMATRIX_X4(ahi[mt], ad);
                LDMATRIX_X4(alo[mt], ad + TILE_B);
            }

            const uint32_t boff = (uint32_t)(n0w + gid) * TROW + ks * 32 + tg * 4;
            #pragma unroll
            for (int nt = 0; nt < 4; nt++) {
                uint32_t bh[2], bl[2];
                uint32_t bd = stage + 2 * TILE_B + boff + nt * (8 * TROW);
                LDS32(bh[0], bd);
                LDS32(bh[1], bd + 16);
                LDS32(bl[0], bd + TILE_B);
                LDS32(bl[1], bd + TILE_B + 16);
                #pragma unroll
                for (int mt = 0; mt < 4; mt++)
                    MMA_BF16(acc[mt][nt], ahi[mt], bh);
                #pragma unroll
                for (int mt = 0; mt < 4; mt++)
                    MMA_BF16(acc[mt][nt], ahi[mt], bl);
                #pragma unroll
                for (int mt = 0; mt < 4; mt++)
                    MMA_BF16(acc[mt][nt], alo[mt], bh);
            }
        }
        __syncthreads();
    }
}

// ---- fused Q/K/V projection: grid (8, 32, 3) ----
__global__ void __launch_bounds__(256, 2) gemm_qkv(
    const float* __restrict__ bq, const float* __restrict__ bk,
    const float* __restrict__ bv)
{
    extern __shared__ char smem[];
    const uint32_t sb = smem_u32(smem);
    const int tid = threadIdx.x;
    const int z = blockIdx.z;
    const int bm = blockIdx.y * 128;
    const int bn = blockIdx.x * 128;

    float acc[4][4][4];
    #pragma unroll
    for (int mt = 0; mt < 4; mt++)
        #pragma unroll
        for (int nt = 0; nt < 4; nt++)
            #pragma unroll
            for (int j = 0; j < 4; j++) acc[mt][nt][j] = 0.f;

    gemm_mainloop(g_xhi + (size_t)bm * D_MODEL, g_xlo + (size_t)bm * D_MODEL,
                  g_Whi[z] + (size_t)bn * D_MODEL, g_Wlo[z] + (size_t)bn * D_MODEL,
                  sb, tid, acc);

    const float* bias = (z == 0) ? bq : (z == 1) ? bk : bv;
    const float scale = (z == 0) ? 0.125f * 1.44269504f : 1.f;
    __nv_bfloat16* Chi = g_prjhi[z];
    __nv_bfloat16* Clo = g_prjlo[z];

    const int lane = tid & 31, wid = tid >> 5;
    const int m0w = (wid & 1) * 64, n0w = (wid >> 1) * 32;
    const int gid = lane >> 2, tg = lane & 3;

    #pragma unroll
    for (int nt = 0; nt < 4; nt++) {
        const int col = bn + n0w + nt * 8 + 2 * tg;
        const float b0 = bias[col], b1 = bias[col + 1];
        #pragma unroll
        for (int mt = 0; mt < 4; mt++) {
            const int r0 = bm + m0w + mt * 16 + gid;
            #pragma unroll
            for (int s = 0; s < 2; s++) {
                float v0 = (acc[mt][nt][2*s+0] + b0) * scale;
                float v1 = (acc[mt][nt][2*s+1] + b1) * scale;
                __nv_bfloat16 h0 = __float2bfloat16(v0);
                __nv_bfloat16 h1 = __float2bfloat16(v1);
                float l0 = v0 - __bfloat162float(h0);
                float l1 = v1 - __bfloat162float(h1);
                size_t off = (size_t)(r0 + 8 * s) * D_MODEL + col;
                __nv_bfloat162 H(h0, h1);
                *(uint32_t*)(Chi + off) = *(uint32_t*)&H;
                *(uint32_t*)(Clo + off) = pack_bf16(l0, l1);
            }
        }
    }
}

// ---- output projection: grid (8, 32), fp32 epilogue ----
__global__ void __launch_bounds__(256, 2) gemm_o(
    const float* __restrict__ bo, float* __restrict__ out)
{
    extern __shared__ char smem[];
    const uint32_t sb = smem_u32(smem);
    const int tid = threadIdx.x;
    const int bm = blockIdx.y * 128;
    const int bn = blockIdx.x * 128;

    float acc[4][4][4];
    #pragma unroll
    for (int mt = 0; mt < 4; mt++)
        #pragma unroll
        for (int nt = 0; nt < 4; nt++)
            #pragma unroll
            for (int j = 0; j < 4; j++) acc[mt][nt][j] = 0.f;

    gemm_mainloop(g_aohi + (size_t)bm * D_MODEL, g_aolo + (size_t)bm * D_MODEL,
                  g_Whi[3] + (size_t)bn * D_MODEL, g_Wlo[3] + (size_t)bn * D_MODEL,
                  sb, tid, acc);

    const int lane = tid & 31, wid = tid >> 5;
    const int m0w = (wid & 1) * 64, n0w = (wid >> 1) * 32;
    const int gid = lane >> 2, tg = lane & 3;

    #pragma unroll
    for (int nt = 0; nt < 4; nt++) {
        const int col = bn + n0w + nt * 8 + 2 * tg;
        const float b0 = bo[col], b1 = bo[col + 1];
        #pragma unroll
        for (int mt = 0; mt < 4; mt++) {
            const int r0 = bm + m0w + mt * 16 + gid;
            float2 v0, v1;
            v0.x = acc[mt][nt][0] + b0; v0.y = acc[mt][nt][1] + b1;
            v1.x = acc[mt][nt][2] + b0; v1.y = acc[mt][nt][3] + b1;
            *(float2*)(out + (size_t)r0 * D_MODEL + col)       = v0;
            *(float2*)(out + (size_t)(r0 + 8) * D_MODEL + col) = v1;
        }
    }
}

// ---------------------------------------------------------------------------
// MMA flash attention (validated R7). CTA = 128 query rows; 8 warps x 16 rows.
// ---------------------------------------------------------------------------
#define ATROW 144
#define ARR_B (64 * ATROW)
#define ASTG  (4 * ARR_B)
#define A_KHI 0
#define A_KLO ARR_B
#define A_VHI (2 * ARR_B)
#define A_VLO (3 * ARR_B)
#define AQ_HI 0
#define AQ_LO (128 * ATROW)
#define ATTN_SMEM (2 * ASTG)        // 73728

__global__ void __launch_bounds__(256, 2) attn_mma(
    const __nv_bfloat16* __restrict__ Qhi, const __nv_bfloat16* __restrict__ Qlo,
    const __nv_bfloat16* __restrict__ Khi, const __nv_bfloat16* __restrict__ Klo,
    const __nv_bfloat16* __restrict__ Vhi, const __nv_bfloat16* __restrict__ Vlo,
    __nv_bfloat16* __restrict__ Ohi, __nv_bfloat16* __restrict__ Olo)
{
    extern __shared__ char smem[];
    const uint32_t sb = smem_u32(smem);
    const int b  = blockIdx.z;
    const int h  = blockIdx.y;
    const int qb = gridDim.x - 1 - blockIdx.x;
    const int tid  = threadIdx.x;
    const int lane = tid & 31;
    const int wid  = tid >> 5;
    const int gid  = lane >> 2;
    const int tg   = lane & 3;
    const int q0   = qb * 128;
    const int r0w  = q0 + wid * 16;
    const size_t rowbase = (size_t)b * SEQ;
    const int colh = h * DHEAD;

    #pragma unroll
    for (int i = 0; i < 8; i++) {
        int v = tid + i * 256;
        int arr = v >> 10;
        int rem = v & 1023;
        int r = rem >> 3, seg = rem & 7;
        size_t g = (rowbase + q0 + r) * D_MODEL + colh + seg * 8;
        const __nv_bfloat16* s = arr ? Qlo : Qhi;
        CP_ASYNC16(sb + (arr ? AQ_LO : AQ_HI) + r * ATROW + seg * 16, s + g);
    }
    CP_COMMIT();
    CP_WAIT(0);
    __syncthreads();

    uint32_t qh[4][4], ql[4][4];
    {
        const uint32_t aoff = (uint32_t)(wid * 16 + (lane & 15)) * ATROW
                              + (lane >> 4) * 16;
        #pragma unroll
        for (int ks = 0; ks < 4; ks++) {
            LDMATRIX_X4(qh[ks], sb + AQ_HI + aoff + ks * 32);
            LDMATRIX_X4(ql[ks], sb + AQ_LO + aoff + ks * 32);
        }
    }
    __syncthreads();

    float oacc[8][4];
    #pragma unroll
    for (int nf = 0; nf < 8; nf++)
        #pragma unroll
        for (int e = 0; e < 4; e++) oacc[nf][e] = 0.f;
    float mrow[2] = {-1e30f, -1e30f};
    float lrow[2] = {0.f, 0.f};

    const __nv_bfloat16* kvsrc[4] = { Khi, Klo, Vhi, Vlo };

    auto stage_tile = [&](int c) {
        const uint32_t base = sb + (uint32_t)(c & 1) * ASTG;
        const int kt = c * 64;
        #pragma unroll
        for (int i = 0; i < 8; i++) {
            int v = tid + i * 256;
            int arr = v >> 9;
            int rem = v & 511;
            int r = rem >> 3, seg = rem & 7;
            size_t g = (rowbase + kt + r) * D_MODEL + colh + seg * 8;
            CP_ASYNC16(base + arr * ARR_B + r * ATROW + seg * 16, kvsrc[arr] + g);
        }
    };

    const int NT = (q0 + 128) / 64;
    stage_tile(0);
    CP_COMMIT();

    for (int c = 0; c < NT; c++) {
        if (c + 1 < NT) { stage_tile(c + 1); CP_COMMIT(); CP_WAIT(1); }
        else            { CP_WAIT(0); }
        __syncthreads();

        const int kt0 = c * 64;
        const uint32_t stg = sb + (uint32_t)(c & 1) * ASTG;

        if (kt0 <= r0w + 15) {
            float sacc[8][4];
            #pragma unroll
            for (int nf = 0; nf < 8; nf++)
                #pragma unroll
                for (int e = 0; e < 4; e++) sacc[nf][e] = 0.f;

            #pragma unroll
            for (int ks = 0; ks < 4; ks++) {
                #pragma unroll
                for (int nf = 0; nf < 8; nf++) {
                    uint32_t bh[2], bl[2];
                    uint32_t bd = stg + A_KHI + (uint32_t)(nf * 8 + gid) * ATROW
                                  + ks * 32 + tg * 4;
                    LDS32(bh[0], bd); LDS32(bh[1], bd + 16);
                    LDS32(bl[0], bd + ARR_B);
                    LDS32(bl[1], bd + ARR_B + 16);
                    MMA_BF16(sacc[nf], qh[ks], bh);
                    MMA_BF16(sacc[nf], qh[ks], bl);
                    MMA_BF16(sacc[nf], ql[ks], bh);
                }
            }

            if (kt0 + 63 > r0w) {
                #pragma unroll
                for (int nf = 0; nf < 8; nf++)
                    #pragma unroll
                    for (int e = 0; e < 4; e++) {
                        int col = kt0 + nf * 8 + 2 * tg + (e & 1);
                        int row = r0w + gid + ((e >> 1) ? 8 : 0);
                        if (col > row) sacc[nf][e] = -1e30f;
                    }
            }

            float corr[2];
            #pragma unroll
            for (int s = 0; s < 2; s++) {
                float vmax = -1e30f;
                #pragma unroll
                for (int nf = 0; nf < 8; nf++) {
                    vmax = fmaxf(vmax, sacc[nf][2*s]);
                    vmax = fmaxf(vmax, sacc[nf][2*s+1]);
                }
                vmax = fmaxf(vmax, __shfl_xor_sync(0xFFFFFFFF, vmax, 1));
                vmax = fmaxf(vmax, __shfl_xor_sync(0xFFFFFFFF, vmax, 2));
                float mo = mrow[s];
                float mn = fmaxf(mo, vmax);
                float cr = exp2f_fast(mo - mn);
                corr[s] = cr;
                mrow[s] = mn;
                float rs = 0.f;
                #pragma unroll
                for (int nf = 0; nf < 8; nf++) {
                    float p0 = exp2f_fast(sacc[nf][2*s]   - mn);
                    float p1 = exp2f_fast(sacc[nf][2*s+1] - mn);
                    sacc[nf][2*s]   = p0;
                    sacc[nf][2*s+1] = p1;
                    rs += p0 + p1;
                }
                rs += __shfl_xor_sync(0xFFFFFFFF, rs, 1);
                rs += __shfl_xor_sync(0xFFFFFFFF, rs, 2);
                lrow[s] = lrow[s] * cr + rs;
            }
            #pragma unroll
            for (int nf = 0; nf < 8; nf++)
                #pragma unroll
                for (int e = 0; e < 4; e++)
                    oacc[nf][e] *= corr[e >> 1];

            #pragma unroll
            for (int kf = 0; kf < 4; kf++) {
                uint32_t phi[4], plo[4];
                #pragma unroll
                for (int half = 0; half < 2; half++) {
                    const float* c2 = sacc[2 * kf + half];
                    #pragma unroll
                    for (int s = 0; s < 2; s++) {
                        float v0 = c2[2*s], v1 = c2[2*s+1];
                        __nv_bfloat16 h0 = __float2bfloat16(v0);
                        __nv_bfloat16 h1 = __float2bfloat16(v1);
                        float l0 = v0 - __bfloat162float(h0);
                        float l1 = v1 - __bfloat162float(h1);
                        __nv_bfloat162 H(h0, h1);
                        phi[half * 2 + s] = *(uint32_t*)&H;
                        plo[half * 2 + s] = pack_bf16(l0, l1);
                    }
                }
                #pragma unroll
                for (int nf2 = 0; nf2 < 4; nf2++) {
                    uint32_t row = kf * 16 + ((lane >> 3) & 1) * 8 + (lane & 7);
                    uint32_t cb  = nf2 * 32 + (lane >> 4) * 16;
                    uint32_t ad  = stg + A_VHI + row * ATROW + cb;
                    uint32_t rh[4], rl[4];
                    LDMATRIX_X4_T(rh, ad);
                    LDMATRIX_X4_T(rl, ad + ARR_B);
                    uint32_t bh0[2] = { rh[0], rh[1] }, bh1[2] = { rh[2], rh[3] };
                    uint32_t bl0[2] = { rl[0], rl[1] }, bl1[2] = { rl[2], rl[3] };
                    MMA_BF16(oacc[2*nf2],   phi, bh0);
                    MMA_BF16(oacc[2*nf2],   phi, bl0);
                    MMA_BF16(oacc[2*nf2],   plo, bh0);
                    MMA_BF16(oacc[2*nf2+1], phi, bh1);
                    MMA_BF16(oacc[2*nf2+1], phi, bl1);
                    MMA_BF16(oacc[2*nf2+1], plo, bh1);
                }
            }
        }
        __syncthreads();
    }

    float inv[2] = { 1.f / lrow[0], 1.f / lrow[1] };
    #pragma unroll
    for (int s = 0; s < 2; s++) {
        int r = r0w + gid + 8 * s;
        #pragma unroll
        for (int nf = 0; nf < 8; nf++) {
            float v0 = oacc[nf][2*s]   * inv[s];
            float v1 = oacc[nf][2*s+1] * inv[s];
            __nv_bfloat16 h0 = __float2bfloat16(v0);
            __nv_bfloat16 h1 = __float2bfloat16(v1);
            float l0 = v0 - __bfloat162float(h0);
            float l1 = v1 - __bfloat162float(h1);
            size_t off = (rowbase + r) * D_MODEL + colh + nf * 8 + 2 * tg;
            __nv_bfloat162 H(h0, h1);
            *(uint32_t*)(Ohi + off) = *(uint32_t*)&H;
            *(uint32_t*)(Olo + off) = pack_bf16(l0, l1);
        }
    }
}

// ---------------------------------------------------------------------------
extern "C" void kernel_launch(void* const* d_in, const int* in_sizes, int n_in,
                              void* d_out, int out_size)
{
    const float* x  = (const float*)d_in[0];
    const float* Wq = (const float*)d_in[1];
    const float* bq = (const float*)d_in[2];
    const float* Wk = (const float*)d_in[3];
    const float* bk = (const float*)d_in[4];
    const float* Wv = (const float*)d_in[5];
    const float* bv = (const float*)d_in[6];
    const float* Wo = (const float*)d_in[7];
    const float* bo = (const float*)d_in[8];
    float* out = (float*)d_out;

    __nv_bfloat16 *prjhi, *prjlo, *aohi, *aolo;
    cudaGetSymbolAddress((void**)&prjhi, g_prjhi);
    cudaGetSymbolAddress((void**)&prjlo, g_prjlo);
    cudaGetSymbolAddress((void**)&aohi, g_aohi);
    cudaGetSymbolAddress((void**)&aolo, g_aolo);

    cudaFuncSetAttribute(gemm_qkv,
                         cudaFuncAttributeMaxDynamicSharedMemorySize, GEMM_SMEM);
    cudaFuncSetAttribute(gemm_o,
                         cudaFuncAttributeMaxDynamicSharedMemorySize, GEMM_SMEM);
    cudaFuncSetAttribute(attn_mma,
                         cudaFuncAttributeMaxDynamicSharedMemorySize, ATTN_SMEM);

    const int NX4 = NELEM / 4;
    const int NW4 = D_MODEL * D_MODEL / 4;

    split_x<<<(NX4 + 255) / 256, 256>>>(x, NX4);
    {
        dim3 wgrid((NW4 + 255) / 256, 4);
        split_w4<<<wgrid, 256>>>(Wq, Wk, Wv, Wo, NW4);
    }

    {
        dim3 ggrid(D_MODEL / 128, MTOT / 128, 3);   // (8, 32, 3)
        gemm_qkv<<<ggrid, 256, GEMM_SMEM>>>(bq, bk, bv);
    }

    dim3 agrid(SEQ / 128, NHEAD, BATCH);            // (16, 16, 2)
    attn_mma<<<agrid, 256, ATTN_SMEM>>>(
        prjhi + 0 * (size_t)NELEM, prjlo + 0 * (size_t)NELEM,
        prjhi + 1 * (size_t)NELEM, prjlo + 1 * (size_t)NELEM,
        prjhi + 2 * (size_t)NELEM, prjlo + 2 * (size_t)NELEM,
        aohi, aolo);

    {
        dim3 ggrid(D_MODEL / 128, MTOT / 128);      // (8, 32)
        gemm_o<<<ggrid, 256, GEMM_SMEM>>>(bo, out);
    }
}

// round 12
// speedup vs baseline: 3.6457x; 1.1680x over previous
#include <cuda_runtime.h>
#include <cuda_bf16.h>
#include <cstdint>

#define D_MODEL 1024
#define SEQ     2048
#define BATCH   2
#define NHEAD   16
#define DHEAD   64
#define MTOT    (BATCH * SEQ)   // 4096
#define NELEM   (MTOT * D_MODEL)

// ---------------- scratch (__device__ globals) ------------------------------
__device__ __nv_bfloat16 g_xhi [NELEM];
__device__ __nv_bfloat16 g_xlo [NELEM];
__device__ __nv_bfloat16 g_Whi [4][D_MODEL * D_MODEL];
__device__ __nv_bfloat16 g_Wlo [4][D_MODEL * D_MODEL];
__device__ __nv_bfloat16 g_prjhi[3][NELEM];   // Q, K, V
__device__ __nv_bfloat16 g_prjlo[3][NELEM];
__device__ __nv_bfloat16 g_aohi[NELEM];
__device__ __nv_bfloat16 g_aolo[NELEM];

// ---------------------------------------------------------------------------
__device__ __forceinline__ uint32_t smem_u32(const void* p) {
    uint32_t a;
    asm("{ .reg .u64 t; cvta.to.shared.u64 t, %1; cvt.u32.u64 %0, t; }"
        : "=r"(a) : "l"(p));
    return a;
}

#define MMA_BF16(acc, a, b) \
    asm volatile("mma.sync.aligned.m16n8k16.row.col.f32.bf16.bf16.f32 " \
        "{%0,%1,%2,%3}, {%4,%5,%6,%7}, {%8,%9}, {%0,%1,%2,%3};" \
        : "+f"((acc)[0]), "+f"((acc)[1]), "+f"((acc)[2]), "+f"((acc)[3]) \
        : "r"((a)[0]), "r"((a)[1]), "r"((a)[2]), "r"((a)[3]), \
          "r"((b)[0]), "r"((b)[1]))

#define LDMATRIX_X4(r, addr) \
    asm volatile("ldmatrix.sync.aligned.m8n8.x4.shared.b16 {%0,%1,%2,%3}, [%4];" \
        : "=r"((r)[0]), "=r"((r)[1]), "=r"((r)[2]), "=r"((r)[3]) : "r"(addr))

#define LDMATRIX_X4_T(r, addr) \
    asm volatile("ldmatrix.sync.aligned.m8n8.x4.trans.shared.b16 {%0,%1,%2,%3}, [%4];" \
        : "=r"((r)[0]), "=r"((r)[1]), "=r"((r)[2]), "=r"((r)[3]) : "r"(addr))

#define CP_ASYNC16(d, g) \
    asm volatile("cp.async.cg.shared.global [%0], [%1], 16;" :: "r"(d), "l"(g))
#define CP_COMMIT()  asm volatile("cp.async.commit_group;" ::: "memory")
#define CP_WAIT(n)   asm volatile("cp.async.wait_group %0;" :: "n"(n) : "memory")

__device__ __forceinline__ uint32_t pack_bf16(float lo, float hi) {
    __nv_bfloat162 t = __floats2bfloat162_rn(lo, hi);
    return *(uint32_t*)&t;
}

// fast exp2 for x <= 0 (fma/alu pipe only, rel err ~2e-6)
__device__ __forceinline__ float exp2f_fast(float x) {
    x = fmaxf(x, -100.f);
    float r = x + 12582912.f;
    int  ir = __float_as_int(r);
    float n = r - 12582912.f;
    float f = x - n;
    float p = 1.33335581e-3f;
    p = fmaf(p, f, 9.61817249e-3f);
    p = fmaf(p, f, 5.55041086e-2f);
    p = fmaf(p, f, 2.40226507e-1f);
    p = fmaf(p, f, 6.93147182e-1f);
    p = fmaf(p, f, 1.0f);
    return __int_as_float(__float_as_int(p) + ((ir - 0x4B400000) << 23));
}

// ---------------------------------------------------------------------------
// fp32 -> (hi, lo) bf16 splits
// ---------------------------------------------------------------------------
__device__ __forceinline__ void split4(const float* __restrict__ in,
                                       __nv_bfloat16* __restrict__ hi,
                                       __nv_bfloat16* __restrict__ lo, int i) {
    float4 v = ((const float4*)in)[i];
    __nv_bfloat16 hx = __float2bfloat16(v.x);
    __nv_bfloat16 hy = __float2bfloat16(v.y);
    __nv_bfloat16 hz = __float2bfloat16(v.z);
    __nv_bfloat16 hw = __float2bfloat16(v.w);
    __nv_bfloat16 lx = __float2bfloat16(v.x - __bfloat162float(hx));
    __nv_bfloat16 ly = __float2bfloat16(v.y - __bfloat162float(hy));
    __nv_bfloat16 lz = __float2bfloat16(v.z - __bfloat162float(hz));
    __nv_bfloat16 lw = __float2bfloat16(v.w - __bfloat162float(hw));
    union { __nv_bfloat162 b[2]; uint2 u; } H, L;
    H.b[0] = __nv_bfloat162(hx, hy); H.b[1] = __nv_bfloat162(hz, hw);
    L.b[0] = __nv_bfloat162(lx, ly); L.b[1] = __nv_bfloat162(lz, lw);
    *(uint2*)(hi + 4 * (size_t)i) = H.u;
    *(uint2*)(lo + 4 * (size_t)i) = L.u;
}

__global__ void __launch_bounds__(256) split_x(const float* __restrict__ in, int n4) {
    int i = blockIdx.x * 256 + threadIdx.x;
    if (i < n4) split4(in, g_xhi, g_xlo, i);
}

__global__ void __launch_bounds__(256) split_w4(
    const float* __restrict__ W0, const float* __restrict__ W1,
    const float* __restrict__ W2, const float* __restrict__ W3, int n4) {
    int y = blockIdx.y;
    const float* in = (y == 0) ? W0 : (y == 1) ? W1 : (y == 2) ? W2 : W3;
    int i = blockIdx.x * 256 + threadIdx.x;
    if (i < n4) split4(in, g_Whi[y], g_Wlo[y], i);
}

// ---------------------------------------------------------------------------
// GEMM mainloop. 128x128 tile, BK=32, 256 thr, warp grid 2x4, B-fragments
// via ldmatrix.x4 (2 n8-blocks per instruction), nt-pair-outer ordering.
// ---------------------------------------------------------------------------
#define TROW   80
#define TILE_B (128 * TROW)
#define STAGE_B (4 * TILE_B)
#define GEMM_SMEM (2 * STAGE_B)   // 81920 B

__device__ __forceinline__ void gemm_mainloop(
    const __nv_bfloat16* __restrict__ Ahi, const __nv_bfloat16* __restrict__ Alo,
    const __nv_bfloat16* __restrict__ Bhi, const __nv_bfloat16* __restrict__ Blo,
    uint32_t sb, int tid, float acc[4][4][4])
{
    constexpr int K = D_MODEL;
    const int lane = tid & 31;
    const int wid  = tid >> 5;
    const int m0w = (wid & 1) * 64;
    const int n0w = (wid >> 1) * 32;

    const __nv_bfloat16* src[4] = { Ahi, Alo, Bhi, Blo };

    auto copy_chunk = [&](int c) {
        const int buf = c & 1;
        const int kc  = c * 32;
        #pragma unroll
        for (int t = 0; t < 4; t++) {
            #pragma unroll
            for (int i = 0; i < 2; i++) {
                int v = tid + i * 256;
                int row = v >> 2, seg = v & 3;
                const __nv_bfloat16* g = src[t] + (size_t)row * K + kc + seg * 8;
                uint32_t d = sb + buf * STAGE_B + t * TILE_B + row * TROW + seg * 16;
                CP_ASYNC16(d, g);
            }
        }
    };

    const int NCH = K / 32;
    copy_chunk(0);
    CP_COMMIT();

    for (int c = 0; c < NCH; c++) {
        if (c + 1 < NCH) { copy_chunk(c + 1); CP_COMMIT(); CP_WAIT(1); }
        else             { CP_WAIT(0); }
        __syncthreads();

        const uint32_t stage = sb + (c & 1) * STAGE_B;

        #pragma unroll
        for (int ks = 0; ks < 2; ks++) {
            uint32_t ahi[4][4], alo[4][4];
            const uint32_t aoff = (uint32_t)(m0w + (lane & 15)) * TROW
                                  + ks * 32 + (lane >> 4) * 16;
            #pragma unroll
            for (int mt = 0; mt < 4; mt++) {
                uint32_t ad = stage + aoff + mt * (16 * TROW);
                LDMATRIX_X4(ahi[mt], ad);
                LDMATRIX_X4(alo[mt], ad + TILE_B);
            }

            // B-frags: one ldmatrix.x4 covers 2 n8 blocks x k16
            const uint32_t brow = (uint32_t)(n0w + ((lane & 16) >> 1) + (lane & 7));
            const uint32_t bcol = (uint32_t)(ks * 32 + (lane & 8) * 2);
            #pragma unroll
            for (int ntp = 0; ntp < 2; ntp++) {
                uint32_t bh[4], bl[4];
                uint32_t bd = stage + 2 * TILE_B + (brow + ntp * 16) * TROW + bcol;
                LDMATRIX_X4(bh, bd);
                LDMATRIX_X4(bl, bd + TILE_B);
                uint32_t bh0[2] = { bh[0], bh[1] }, bh1[2] = { bh[2], bh[3] };
                uint32_t bl0[2] = { bl[0], bl[1] }, bl1[2] = { bl[2], bl[3] };
                #pragma unroll
                for (int mt = 0; mt < 4; mt++)
                    MMA_BF16(acc[mt][2*ntp], ahi[mt], bh0);
                #pragma unroll
                for (int mt = 0; mt < 4; mt++)
                    MMA_BF16(acc[mt][2*ntp], ahi[mt], bl0);
                #pragma unroll
                for (int mt = 0; mt < 4; mt++)
                    MMA_BF16(acc[mt][2*ntp], alo[mt], bh0);
                #pragma unroll
                for (int mt = 0; mt < 4; mt++)
                    MMA_BF16(acc[mt][2*ntp+1], ahi[mt], bh1);
                #pragma unroll
                for (int mt = 0; mt < 4; mt++)
                    MMA_BF16(acc[mt][2*ntp+1], ahi[mt], bl1);
                #pragma unroll
                for (int mt = 0; mt < 4; mt++)
                    MMA_BF16(acc[mt][2*ntp+1], alo[mt], bh1);
            }
        }
        __syncthreads();
    }
}

// ---- fused Q/K/V projection: grid (24, 32); z = bx % 3 for A-tile L2 reuse
__global__ void __launch_bounds__(256, 2) gemm_qkv(
    const float* __restrict__ bq, const float* __restrict__ bk,
    const float* __restrict__ bv)
{
    extern __shared__ char smem[];
    const uint32_t sb = smem_u32(smem);
    const int tid = threadIdx.x;
    const int z  = blockIdx.x % 3;
    const int bn = (blockIdx.x / 3) * 128;
    const int bm = blockIdx.y * 128;

    float acc[4][4][4];
    #pragma unroll
    for (int mt = 0; mt < 4; mt++)
        #pragma unroll
        for (int nt = 0; nt < 4; nt++)
            #pragma unroll
            for (int j = 0; j < 4; j++) acc[mt][nt][j] = 0.f;

    gemm_mainloop(g_xhi + (size_t)bm * D_MODEL, g_xlo + (size_t)bm * D_MODEL,
                  g_Whi[z] + (size_t)bn * D_MODEL, g_Wlo[z] + (size_t)bn * D_MODEL,
                  sb, tid, acc);

    const float* bias = (z == 0) ? bq : (z == 1) ? bk : bv;
    const float scale = (z == 0) ? 0.125f * 1.44269504f : 1.f;
    __nv_bfloat16* Chi = g_prjhi[z];
    __nv_bfloat16* Clo = g_prjlo[z];

    const int lane = tid & 31, wid = tid >> 5;
    const int m0w = (wid & 1) * 64, n0w = (wid >> 1) * 32;
    const int gid = lane >> 2, tg = lane & 3;

    #pragma unroll
    for (int nt = 0; nt < 4; nt++) {
        const int col = bn + n0w + nt * 8 + 2 * tg;
        const float b0 = bias[col], b1 = bias[col + 1];
        #pragma unroll
        for (int mt = 0; mt < 4; mt++) {
            const int r0 = bm + m0w + mt * 16 + gid;
            #pragma unroll
            for (int s = 0; s < 2; s++) {
                float v0 = (acc[mt][nt][2*s+0] + b0) * scale;
                float v1 = (acc[mt][nt][2*s+1] + b1) * scale;
                __nv_bfloat16 h0 = __float2bfloat16(v0);
                __nv_bfloat16 h1 = __float2bfloat16(v1);
                float l0 = v0 - __bfloat162float(h0);
                float l1 = v1 - __bfloat162float(h1);
                size_t off = (size_t)(r0 + 8 * s) * D_MODEL + col;
                __nv_bfloat162 H(h0, h1);
                *(uint32_t*)(Chi + off) = *(uint32_t*)&H;
                *(uint32_t*)(Clo + off) = pack_bf16(l0, l1);
            }
        }
    }
}

// ---- output projection: grid (8, 32), fp32 epilogue ----
__global__ void __launch_bounds__(256, 2) gemm_o(
    const float* __restrict__ bo, float* __restrict__ out)
{
    extern __shared__ char smem[];
    const uint32_t sb = smem_u32(smem);
    const int tid = threadIdx.x;
    const int bm = blockIdx.y * 128;
    const int bn = blockIdx.x * 128;

    float acc[4][4][4];
    #pragma unroll
    for (int mt = 0; mt < 4; mt++)
        #pragma unroll
        for (int nt = 0; nt < 4; nt++)
            #pragma unroll
            for (int j = 0; j < 4; j++) acc[mt][nt][j] = 0.f;

    gemm_mainloop(g_aohi + (size_t)bm * D_MODEL, g_aolo + (size_t)bm * D_MODEL,
                  g_Whi[3] + (size_t)bn * D_MODEL, g_Wlo[3] + (size_t)bn * D_MODEL,
                  sb, tid, acc);

    const int lane = tid & 31, wid = tid >> 5;
    const int m0w = (wid & 1) * 64, n0w = (wid >> 1) * 32;
    const int gid = lane >> 2, tg = lane & 3;

    #pragma unroll
    for (int nt = 0; nt < 4; nt++) {
        const int col = bn + n0w + nt * 8 + 2 * tg;
        const float b0 = bo[col], b1 = bo[col + 1];
        #pragma unroll
        for (int mt = 0; mt < 4; mt++) {
            const int r0 = bm + m0w + mt * 16 + gid;
            float2 v0, v1;
            v0.x = acc[mt][nt][0] + b0; v0.y = acc[mt][nt][1] + b1;
            v1.x = acc[mt][nt][2] + b0; v1.y = acc[mt][nt][3] + b1;
            *(float2*)(out + (size_t)r0 * D_MODEL + col)       = v0;
            *(float2*)(out + (size_t)(r0 + 8) * D_MODEL + col) = v1;
        }
    }
}

// ---------------------------------------------------------------------------
// MMA flash attention. Flat grid 512 with LPT ordering (task sizes strictly
// descending). 8 warps x 16 rows; K B-frags via ldmatrix.x4; V via trans.
// ---------------------------------------------------------------------------
#define ATROW 144
#define ARR_B (64 * ATROW)
#define ASTG  (4 * ARR_B)
#define A_KHI 0
#define A_KLO ARR_B
#define A_VHI (2 * ARR_B)
#define A_VLO (3 * ARR_B)
#define AQ_HI 0
#define AQ_LO (128 * ATROW)
#define ATTN_SMEM (2 * ASTG)        // 73728

__global__ void __launch_bounds__(256, 2) attn_mma(
    const __nv_bfloat16* __restrict__ Qhi, const __nv_bfloat16* __restrict__ Qlo,
    const __nv_bfloat16* __restrict__ Khi, const __nv_bfloat16* __restrict__ Klo,
    const __nv_bfloat16* __restrict__ Vhi, const __nv_bfloat16* __restrict__ Vlo,
    __nv_bfloat16* __restrict__ Ohi, __nv_bfloat16* __restrict__ Olo)
{
    extern __shared__ char smem[];
    const uint32_t sb = smem_u32(smem);
    const int fid = blockIdx.x;
    const int qb  = 15 - (fid >> 5);          // LPT: heavy tasks first
    const int h   = (fid & 31) >> 1;
    const int b   = fid & 1;
    const int tid  = threadIdx.x;
    const int lane = tid & 31;
    const int wid  = tid >> 5;
    const int gid  = lane >> 2;
    const int tg   = lane & 3;
    const int q0   = qb * 128;
    const int r0w  = q0 + wid * 16;
    const size_t rowbase = (size_t)b * SEQ;
    const int colh = h * DHEAD;

    #pragma unroll
    for (int i = 0; i < 8; i++) {
        int v = tid + i * 256;
        int arr = v >> 10;
        int rem = v & 1023;
        int r = rem >> 3, seg = rem & 7;
        size_t g = (rowbase + q0 + r) * D_MODEL + colh + seg * 8;
        const __nv_bfloat16* s = arr ? Qlo : Qhi;
        CP_ASYNC16(sb + (arr ? AQ_LO : AQ_HI) + r * ATROW + seg * 16, s + g);
    }
    CP_COMMIT();
    CP_WAIT(0);
    __syncthreads();

    uint32_t qh[4][4], ql[4][4];
    {
        const uint32_t aoff = (uint32_t)(wid * 16 + (lane & 15)) * ATROW
                              + (lane >> 4) * 16;
        #pragma unroll
        for (int ks = 0; ks < 4; ks++) {
            LDMATRIX_X4(qh[ks], sb + AQ_HI + aoff + ks * 32);
            LDMATRIX_X4(ql[ks], sb + AQ_LO + aoff + ks * 32);
        }
    }
    __syncthreads();

    float oacc[8][4];
    #pragma unroll
    for (int nf = 0; nf < 8; nf++)
        #pragma unroll
        for (int e = 0; e < 4; e++) oacc[nf][e] = 0.f;
    float mrow[2] = {-1e30f, -1e30f};
    float lrow[2] = {0.f, 0.f};

    const __nv_bfloat16* kvsrc[4] = { Khi, Klo, Vhi, Vlo };

    auto stage_tile = [&](int c) {
        const uint32_t base = sb + (uint32_t)(c & 1) * ASTG;
        const int kt = c * 64;
        #pragma unroll
        for (int i = 0; i < 8; i++) {
            int v = tid + i * 256;
            int arr = v >> 9;
            int rem = v & 511;
            int r = rem >> 3, seg = rem & 7;
            size_t g = (rowbase + kt + r) * D_MODEL + colh + seg * 8;
            CP_ASYNC16(base + arr * ARR_B + r * ATROW + seg * 16, kvsrc[arr] + g);
        }
    };

    const int NT = (q0 + 128) / 64;
    stage_tile(0);
    CP_COMMIT();

    for (int c = 0; c < NT; c++) {
        if (c + 1 < NT) { stage_tile(c + 1); CP_COMMIT(); CP_WAIT(1); }
        else            { CP_WAIT(0); }
        __syncthreads();

        const int kt0 = c * 64;
        const uint32_t stg = sb + (uint32_t)(c & 1) * ASTG;

        if (kt0 <= r0w + 15) {
            float sacc[8][4];
            #pragma unroll
            for (int nf = 0; nf < 8; nf++)
                #pragma unroll
                for (int e = 0; e < 4; e++) sacc[nf][e] = 0.f;

            // ---- S = Q K^T: K B-frags via ldmatrix.x4 (2 n8 blocks/instr) ----
            const uint32_t krow = ((lane & 16) >> 1) + (lane & 7);
            #pragma unroll
            for (int ks = 0; ks < 4; ks++) {
                const uint32_t kcol = (uint32_t)(ks * 32 + (lane & 8) * 2);
                #pragma unroll
                for (int nfp = 0; nfp < 4; nfp++) {
                    uint32_t bh[4], bl[4];
                    uint32_t bd = stg + A_KHI + (krow + nfp * 16) * ATROW + kcol;
                    LDMATRIX_X4(bh, bd);
                    LDMATRIX_X4(bl, bd + ARR_B);
                    uint32_t bh0[2] = { bh[0], bh[1] }, bh1[2] = { bh[2], bh[3] };
                    uint32_t bl0[2] = { bl[0], bl[1] }, bl1[2] = { bl[2], bl[3] };
                    MMA_BF16(sacc[2*nfp],   qh[ks], bh0);
                    MMA_BF16(sacc[2*nfp],   qh[ks], bl0);
                    MMA_BF16(sacc[2*nfp],   ql[ks], bh0);
                    MMA_BF16(sacc[2*nfp+1], qh[ks], bh1);
                    MMA_BF16(sacc[2*nfp+1], qh[ks], bl1);
                    MMA_BF16(sacc[2*nfp+1], ql[ks], bh1);
                }
            }

            if (kt0 + 63 > r0w) {
                #pragma unroll
                for (int nf = 0; nf < 8; nf++)
                    #pragma unroll
                    for (int e = 0; e < 4; e++) {
                        int col = kt0 + nf * 8 + 2 * tg + (e & 1);
                        int row = r0w + gid + ((e >> 1) ? 8 : 0);
                        if (col > row) sacc[nf][e] = -1e30f;
                    }
            }

            float corr[2];
            #pragma unroll
            for (int s = 0; s < 2; s++) {
                float vmax = -1e30f;
                #pragma unroll
                for (int nf = 0; nf < 8; nf++) {
                    vmax = fmaxf(vmax, sacc[nf][2*s]);
                    vmax = fmaxf(vmax, sacc[nf][2*s+1]);
                }
                vmax = fmaxf(vmax, __shfl_xor_sync(0xFFFFFFFF, vmax, 1));
                vmax = fmaxf(vmax, __shfl_xor_sync(0xFFFFFFFF, vmax, 2));
                float mo = mrow[s];
                float mn = fmaxf(mo, vmax);
                float cr = exp2f_fast(mo - mn);
                corr[s] = cr;
                mrow[s] = mn;
                float rs = 0.f;
                #pragma unroll
                for (int nf = 0; nf < 8; nf++) {
                    float p0 = exp2f_fast(sacc[nf][2*s]   - mn);
                    float p1 = exp2f_fast(sacc[nf][2*s+1] - mn);
                    sacc[nf][2*s]   = p0;
                    sacc[nf][2*s+1] = p1;
                    rs += p0 + p1;
                }
                rs += __shfl_xor_sync(0xFFFFFFFF, rs, 1);
                rs += __shfl_xor_sync(0xFFFFFFFF, rs, 2);
                lrow[s] = lrow[s] * cr + rs;
            }
            #pragma unroll
            for (int nf = 0; nf < 8; nf++)
                #pragma unroll
                for (int e = 0; e < 4; e++)
                    oacc[nf][e] *= corr[e >> 1];

            #pragma unroll
            for (int kf = 0; kf < 4; kf++) {
                uint32_t phi[4], plo[4];
                #pragma unroll
                for (int half = 0; half < 2; half++) {
                    const float* c2 = sacc[2 * kf + half];
                    #pragma unroll
                    for (int s = 0; s < 2; s++) {
                        float v0 = c2[2*s], v1 = c2[2*s+1];
                        __nv_bfloat16 h0 = __float2bfloat16(v0);
                        __nv_bfloat16 h1 = __float2bfloat16(v1);
                        float l0 = v0 - __bfloat162float(h0);
                        float l1 = v1 - __bfloat162float(h1);
                        __nv_bfloat162 H(h0, h1);
                        phi[half * 2 + s] = *(uint32_t*)&H;
                        plo[half * 2 + s] = pack_bf16(l0, l1);
                    }
                }
                #pragma unroll
                for (int nf2 = 0; nf2 < 4; nf2++) {
                    uint32_t row = kf * 16 + ((lane >> 3) & 1) * 8 + (lane & 7);
                    uint32_t cb  = nf2 * 32 + (lane >> 4) * 16;
                    uint32_t ad  = stg + A_VHI + row * ATROW + cb;
                    uint32_t rh[4], rl[4];
                    LDMATRIX_X4_T(rh, ad);
                    LDMATRIX_X4_T(rl, ad + ARR_B);
                    uint32_t bh0[2] = { rh[0], rh[1] }, bh1[2] = { rh[2], rh[3] };
                    uint32_t bl0[2] = { rl[0], rl[1] }, bl1[2] = { rl[2], rl[3] };
                    MMA_BF16(oacc[2*nf2],   phi, bh0);
                    MMA_BF16(oacc[2*nf2],   phi, bl0);
                    MMA_BF16(oacc[2*nf2],   plo, bh0);
                    MMA_BF16(oacc[2*nf2+1], phi, bh1);
                    MMA_BF16(oacc[2*nf2+1], phi, bl1);
                    MMA_BF16(oacc[2*nf2+1], plo, bh1);
                }
            }
        }
        __syncthreads();
    }

    float inv[2] = { 1.f / lrow[0], 1.f / lrow[1] };
    #pragma unroll
    for (int s = 0; s < 2; s++) {
        int r = r0w + gid + 8 * s;
        #pragma unroll
        for (int nf = 0; nf < 8; nf++) {
            float v0 = oacc[nf][2*s]   * inv[s];
            float v1 = oacc[nf][2*s+1] * inv[s];
            __nv_bfloat16 h0 = __float2bfloat16(v0);
            __nv_bfloat16 h1 = __float2bfloat16(v1);
            float l0 = v0 - __bfloat162float(h0);
            float l1 = v1 - __bfloat162float(h1);
            size_t off = (rowbase + r) * D_MODEL + colh + nf * 8 + 2 * tg;
            __nv_bfloat162 H(h0, h1);
            *(uint32_t*)(Ohi + off) = *(uint32_t*)&H;
            *(uint32_t*)(Olo + off) = pack_bf16(l0, l1);
        }
    }
}

// ---------------------------------------------------------------------------
extern "C" void kernel_launch(void* const* d_in, const int* in_sizes, int n_in,
                              void* d_out, int out_size)
{
    const float* x  = (const float*)d_in[0];
    const float* Wq = (const float*)d_in[1];
    const float* bq = (const float*)d_in[2];
    const float* Wk = (const float*)d_in[3];
    const float* bk = (const float*)d_in[4];
    const float* Wv = (const float*)d_in[5];
    const float* bv = (const float*)d_in[6];
    const float* Wo = (const float*)d_in[7];
    const float* bo = (const float*)d_in[8];
    float* out = (float*)d_out;

    __nv_bfloat16 *prjhi, *prjlo, *aohi, *aolo;
    cudaGetSymbolAddress((void**)&prjhi, g_prjhi);
    cudaGetSymbolAddress((void**)&prjlo, g_prjlo);
    cudaGetSymbolAddress((void**)&aohi, g_aohi);
    cudaGetSymbolAddress((void**)&aolo, g_aolo);

    cudaFuncSetAttribute(gemm_qkv,
                         cudaFuncAttributeMaxDynamicSharedMemorySize, GEMM_SMEM);
    cudaFuncSetAttribute(gemm_o,
                         cudaFuncAttributeMaxDynamicSharedMemorySize, GEMM_SMEM);
    cudaFuncSetAttribute(attn_mma,
                         cudaFuncAttributeMaxDynamicSharedMemorySize, ATTN_SMEM);

    const int NX4 = NELEM / 4;
    const int NW4 = D_MODEL * D_MODEL / 4;

    split_x<<<(NX4 + 255) / 256, 256>>>(x, NX4);
    {
        dim3 wgrid((NW4 + 255) / 256, 4);
        split_w4<<<wgrid, 256>>>(Wq, Wk, Wv, Wo, NW4);
    }

    {
        dim3 ggrid(24, MTOT / 128);                 // (24, 32): z = bx % 3
        gemm_qkv<<<ggrid, 256, GEMM_SMEM>>>(bq, bk, bv);
    }

    attn_mma<<<512, 256, ATTN_SMEM>>>(
        prjhi + 0 * (size_t)NELEM, prjlo + 0 * (size_t)NELEM,
        prjhi + 1 * (size_t)NELEM, prjlo + 1 * (size_t)NELEM,
        prjhi + 2 * (size_t)NELEM, prjlo + 2 * (size_t)NELEM,
        aohi, aolo);

    {
        dim3 ggrid(D_MODEL / 128, MTOT / 128);      // (8, 32)
        gemm_o<<<ggrid, 256, GEMM_SMEM>>>(bo, out);
    }
}

// round 15
// speedup vs baseline: 5.1094x; 1.4015x over previous
#include <cuda_runtime.h>
#include <cuda_fp16.h>
#include <cstdint>

#define D_MODEL 1024
#define SEQ     2048
#define BATCH   2
#define NHEAD   16
#define DHEAD   64
#define MTOT    (BATCH * SEQ)   // 4096
#define NELEM   (MTOT * D_MODEL)

// ---------------- scratch (__device__ globals) ------------------------------
__device__ __half g_xhi [NELEM];
__device__ __half g_xlo [NELEM];
__device__ __half g_Wh  [4][D_MODEL * D_MODEL];   // weights quantized once
__device__ __half g_qhi [NELEM];
__device__ __half g_qlo [NELEM];
__device__ __half g_kh  [NELEM];                  // K single fp16
__device__ __half g_vh  [NELEM];                  // V single fp16
__device__ __half g_aohi[NELEM];
__device__ __half g_aolo[NELEM];

// ---------------------------------------------------------------------------
__device__ __forceinline__ uint32_t smem_u32(const void* p) {
    uint32_t a;
    asm("{ .reg .u64 t; cvta.to.shared.u64 t, %1; cvt.u32.u64 %0, t; }"
        : "=r"(a) : "l"(p));
    return a;
}

#define MMA_F16(acc, a, b) \
    asm volatile("mma.sync.aligned.m16n8k16.row.col.f32.f16.f16.f32 " \
        "{%0,%1,%2,%3}, {%4,%5,%6,%7}, {%8,%9}, {%0,%1,%2,%3};" \
        : "+f"((acc)[0]), "+f"((acc)[1]), "+f"((acc)[2]), "+f"((acc)[3]) \
        : "r"((a)[0]), "r"((a)[1]), "r"((a)[2]), "r"((a)[3]), \
          "r"((b)[0]), "r"((b)[1]))

#define LDMATRIX_X4(r, addr) \
    asm volatile("ldmatrix.sync.aligned.m8n8.x4.shared.b16 {%0,%1,%2,%3}, [%4];" \
        : "=r"((r)[0]), "=r"((r)[1]), "=r"((r)[2]), "=r"((r)[3]) : "r"(addr))

#define LDMATRIX_X4_T(r, addr) \
    asm volatile("ldmatrix.sync.aligned.m8n8.x4.trans.shared.b16 {%0,%1,%2,%3}, [%4];" \
        : "=r"((r)[0]), "=r"((r)[1]), "=r"((r)[2]), "=r"((r)[3]) : "r"(addr))

#define CP_ASYNC16(d, g) \
    asm volatile("cp.async.cg.shared.global [%0], [%1], 16;" :: "r"(d), "l"(g))
#define CP_COMMIT()  asm volatile("cp.async.commit_group;" ::: "memory")
#define CP_WAIT(n)   asm volatile("cp.async.wait_group %0;" :: "n"(n) : "memory")

__device__ __forceinline__ uint32_t pack_f16(float a, float b) {
    __half2 t = __floats2half2_rn(a, b);   // x=a (low), y=b (high)
    return *(uint32_t*)&t;
}

// fast exp2 for x <= 0 (fma/alu pipe only, rel err ~2e-6)
__device__ __forceinline__ float exp2f_fast(float x) {
    x = fmaxf(x, -100.f);
    float r = x + 12582912.f;
    int  ir = __float_as_int(r);
    float n = r - 12582912.f;
    float f = x - n;
    float p = 1.33335581e-3f;
    p = fmaf(p, f, 9.61817249e-3f);
    p = fmaf(p, f, 5.55041086e-2f);
    p = fmaf(p, f, 2.40226507e-1f);
    p = fmaf(p, f, 6.93147182e-1f);
    p = fmaf(p, f, 1.0f);
    return __int_as_float(__float_as_int(p) + ((ir - 0x4B400000) << 23));
}

// ---------------------------------------------------------------------------
// fp32 -> fp16 splits / quant
// ---------------------------------------------------------------------------
__global__ void __launch_bounds__(256) split_x(const float* __restrict__ in, int n4) {
    int i = blockIdx.x * 256 + threadIdx.x;
    if (i >= n4) return;
    float4 v = ((const float4*)in)[i];
    __half hx = __float2half_rn(v.x), hy = __float2half_rn(v.y);
    __half hz = __float2half_rn(v.z), hw = __float2half_rn(v.w);
    union { __half2 h[2]; uint2 u; } H, L;
    H.h[0] = __half2(hx, hy); H.h[1] = __half2(hz, hw);
    L.h[0] = __floats2half2_rn(v.x - __half2float(hx), v.y - __half2float(hy));
    L.h[1] = __floats2half2_rn(v.z - __half2float(hz), v.w - __half2float(hw));
    *(uint2*)(g_xhi + 4 * (size_t)i) = H.u;
    *(uint2*)(g_xlo + 4 * (size_t)i) = L.u;
}

__global__ void __launch_bounds__(256) quant_w4(
    const float* __restrict__ W0, const float* __restrict__ W1,
    const float* __restrict__ W2, const float* __restrict__ W3, int n4) {
    int y = blockIdx.y;
    const float* in = (y == 0) ? W0 : (y == 1) ? W1 : (y == 2) ? W2 : W3;
    int i = blockIdx.x * 256 + threadIdx.x;
    if (i >= n4) return;
    float4 v = ((const float4*)in)[i];
    union { __half2 h[2]; uint2 u; } H;
    H.h[0] = __floats2half2_rn(v.x, v.y);
    H.h[1] = __floats2half2_rn(v.z, v.w);
    *(uint2*)(g_Wh[y] + 4 * (size_t)i) = H.u;
}

// ---------------------------------------------------------------------------
// GEMM mainloop: C = (Ahi + Alo) @ Bh^T, 2-term fp16. 128x128 tile, BK=32,
// 256 thr, warp grid 2x4, 3-stage cp.async pipeline (prefetch distance 2).
// ---------------------------------------------------------------------------
#define TROW   80
#define TILE_B (128 * TROW)      // 10240
#define STAGE_B (3 * TILE_B)     // Ahi, Alo, Bh = 30720
#define GEMM_SMEM (3 * STAGE_B)  // 92160

__device__ __forceinline__ void gemm_mainloop(
    const __half* __restrict__ Ahi, const __half* __restrict__ Alo,
    const __half* __restrict__ Bh,
    uint32_t sb, int tid, float acc[4][4][4])
{
    constexpr int K = D_MODEL;
    const int lane = tid & 31;
    const int wid  = tid >> 5;
    const int m0w = (wid & 1) * 64;
    const int n0w = (wid >> 1) * 32;

    const __half* src[3] = { Ahi, Alo, Bh };

    auto copy_chunk = [&](int c) {
        const uint32_t base = sb + (uint32_t)(c % 3) * STAGE_B;
        const int kc = c * 32;
        #pragma unroll
        for (int t = 0; t < 3; t++) {
            #pragma unroll
            for (int i = 0; i < 2; i++) {
                int v = tid + i * 256;
                int row = v >> 2, seg = v & 3;
                const __half* g = src[t] + (size_t)row * K + kc + seg * 8;
                CP_ASYNC16(base + t * TILE_B + row * TROW + seg * 16, g);
            }
        }
    };

    const int NCH = K / 32;
    copy_chunk(0); CP_COMMIT();
    copy_chunk(1); CP_COMMIT();

    for (int c = 0; c < NCH; c++) {
        if (c + 2 < NCH)      { copy_chunk(c + 2); CP_COMMIT(); CP_WAIT(2); }
        else if (c + 1 < NCH) { CP_WAIT(1); }
        else                  { CP_WAIT(0); }
        __syncthreads();

        const uint32_t stage = sb + (uint32_t)(c % 3) * STAGE_B;

        #pragma unroll
        for (int ks = 0; ks < 2; ks++) {
            uint32_t ahi[4][4], alo[4][4];
            const uint32_t aoff = (uint32_t)(m0w + (lane & 15)) * TROW
                                  + ks * 32 + (lane >> 4) * 16;
            #pragma unroll
            for (int mt = 0; mt < 4; mt++) {
                uint32_t ad = stage + aoff + mt * (16 * TROW);
                LDMATRIX_X4(ahi[mt], ad);
                LDMATRIX_X4(alo[mt], ad + TILE_B);
            }

            const uint32_t brow = (uint32_t)(n0w + ((lane & 16) >> 1) + (lane & 7));
            const uint32_t bcol = (uint32_t)(ks * 32 + (lane & 8) * 2);
            #pragma unroll
            for (int ntp = 0; ntp < 2; ntp++) {
                uint32_t bh[4];
                uint32_t bd = stage + 2 * TILE_B + (brow + ntp * 16) * TROW + bcol;
                LDMATRIX_X4(bh, bd);
                uint32_t bh0[2] = { bh[0], bh[1] }, bh1[2] = { bh[2], bh[3] };
                #pragma unroll
                for (int mt = 0; mt < 4; mt++)
                    MMA_F16(acc[mt][2*ntp],   ahi[mt], bh0);
                #pragma unroll
                for (int mt = 0; mt < 4; mt++)
                    MMA_F16(acc[mt][2*ntp+1], ahi[mt], bh1);
                #pragma unroll
                for (int mt = 0; mt < 4; mt++)
                    MMA_F16(acc[mt][2*ntp],   alo[mt], bh0);
                #pragma unroll
                for (int mt = 0; mt < 4; mt++)
                    MMA_F16(acc[mt][2*ntp+1], alo[mt], bh1);
            }
        }
        __syncthreads();
    }
}

// ---- fused Q/K/V projection: grid (24, 32); z = bx % 3 ----
__global__ void __launch_bounds__(256, 2) gemm_qkv(
    const float* __restrict__ bq, const float* __restrict__ bk,
    const float* __restrict__ bv)
{
    extern __shared__ char smem[];
    const uint32_t sb = smem_u32(smem);
    const int tid = threadIdx.x;
    const int z  = blockIdx.x % 3;
    const int bn = (blockIdx.x / 3) * 128;
    const int bm = blockIdx.y * 128;

    float acc[4][4][4];
    #pragma unroll
    for (int mt = 0; mt < 4; mt++)
        #pragma unroll
        for (int nt = 0; nt < 4; nt++)
            #pragma unroll
            for (int j = 0; j < 4; j++) acc[mt][nt][j] = 0.f;

    gemm_mainloop(g_xhi + (size_t)bm * D_MODEL, g_xlo + (size_t)bm * D_MODEL,
                  g_Wh[z] + (size_t)bn * D_MODEL, sb, tid, acc);

    const float* bias = (z == 0) ? bq : (z == 1) ? bk : bv;
    const int lane = tid & 31, wid = tid >> 5;
    const int m0w = (wid & 1) * 64, n0w = (wid >> 1) * 32;
    const int gid = lane >> 2, tg = lane & 3;

    if (z == 0) {
        // Q: scale into exp2 domain, split hi/lo
        const float scale = 0.125f * 1.44269504f;
        #pragma unroll
        for (int nt = 0; nt < 4; nt++) {
            const int col = bn + n0w + nt * 8 + 2 * tg;
            const float b0 = bias[col], b1 = bias[col + 1];
            #pragma unroll
            for (int mt = 0; mt < 4; mt++) {
                const int r0 = bm + m0w + mt * 16 + gid;
                #pragma unroll
                for (int s = 0; s < 2; s++) {
                    float v0 = (acc[mt][nt][2*s+0] + b0) * scale;
                    float v1 = (acc[mt][nt][2*s+1] + b1) * scale;
                    __half h0 = __float2half_rn(v0);
                    __half h1 = __float2half_rn(v1);
                    size_t off = (size_t)(r0 + 8 * s) * D_MODEL + col;
                    __half2 H(h0, h1);
                    *(uint32_t*)(g_qhi + off) = *(uint32_t*)&H;
                    *(uint32_t*)(g_qlo + off) =
                        pack_f16(v0 - __half2float(h0), v1 - __half2float(h1));
                }
            }
        }
    } else {
        // K / V: single fp16
        __half* C = (z == 1) ? g_kh : g_vh;
        #pragma unroll
        for (int nt = 0; nt < 4; nt++) {
            const int col = bn + n0w + nt * 8 + 2 * tg;
            const float b0 = bias[col], b1 = bias[col + 1];
            #pragma unroll
            for (int mt = 0; mt < 4; mt++) {
                const int r0 = bm + m0w + mt * 16 + gid;
                #pragma unroll
                for (int s = 0; s < 2; s++) {
                    size_t off = (size_t)(r0 + 8 * s) * D_MODEL + col;
                    *(uint32_t*)(C + off) =
                        pack_f16(acc[mt][nt][2*s+0] + b0, acc[mt][nt][2*s+1] + b1);
                }
            }
        }
    }
}

// ---- output projection: grid (8, 32), fp32 epilogue ----
__global__ void __launch_bounds__(256, 2) gemm_o(
    const float* __restrict__ bo, float* __restrict__ out)
{
    extern __shared__ char smem[];
    const uint32_t sb = smem_u32(smem);
    const int tid = threadIdx.x;
    const int bm = blockIdx.y * 128;
    const int bn = blockIdx.x * 128;

    float acc[4][4][4];
    #pragma unroll
    for (int mt = 0; mt < 4; mt++)
        #pragma unroll
        for (int nt = 0; nt < 4; nt++)
            #pragma unroll
            for (int j = 0; j < 4; j++) acc[mt][nt][j] = 0.f;

    gemm_mainloop(g_aohi + (size_t)bm * D_MODEL, g_aolo + (size_t)bm * D_MODEL,
                  g_Wh[3] + (size_t)bn * D_MODEL, sb, tid, acc);

    const int lane = tid & 31, wid = tid >> 5;
    const int m0w = (wid & 1) * 64, n0w = (wid >> 1) * 32;
    const int gid = lane >> 2, tg = lane & 3;

    #pragma unroll
    for (int nt = 0; nt < 4; nt++) {
        const int col = bn + n0w + nt * 8 + 2 * tg;
        const float b0 = bo[col], b1 = bo[col + 1];
        #pragma unroll
        for (int mt = 0; mt < 4; mt++) {
            const int r0 = bm + m0w + mt * 16 + gid;
            float2 v0, v1;
            v0.x = acc[mt][nt][0] + b0; v0.y = acc[mt][nt][1] + b1;
            v1.x = acc[mt][nt][2] + b0; v1.y = acc[mt][nt][3] + b1;
            *(float2*)(out + (size_t)r0 * D_MODEL + col)       = v0;
            *(float2*)(out + (size_t)(r0 + 8) * D_MODEL + col) = v1;
        }
    }
}

// ---------------------------------------------------------------------------
// MMA flash attention, fp16 2-term. Flat grid 512, LPT ordering. 8 warps x 16
// rows. Q split in registers; K/V single fp16, 3-stage cp.async pipeline.
// ---------------------------------------------------------------------------
#define ATROW 144
#define ARR_B (64 * ATROW)       // 9216
#define ASTG  (2 * ARR_B)        // Kh + Vh = 18432
#define A_KH  0
#define A_VH  ARR_B
#define AQ_HI 0
#define AQ_LO (128 * ATROW)      // 18432
#define ATTN_SMEM (3 * ASTG)     // 55296 (Q staging uses first 36864)

__global__ void __launch_bounds__(256, 2) attn_mma(
    __half* __restrict__ Ohi, __half* __restrict__ Olo)
{
    extern __shared__ char smem[];
    const uint32_t sb = smem_u32(smem);
    const int fid = blockIdx.x;
    const int qb  = 15 - (fid >> 5);          // LPT: heavy tasks first
    const int h   = (fid & 31) >> 1;
    const int b   = fid & 1;
    const int tid  = threadIdx.x;
    const int lane = tid & 31;
    const int wid  = tid >> 5;
    const int gid  = lane >> 2;
    const int tg   = lane & 3;
    const int q0   = qb * 128;
    const int r0w  = q0 + wid * 16;
    const size_t rowbase = (size_t)b * SEQ;
    const int colh = h * DHEAD;

    // ---- stage Q (hi+lo), extract fragments, then release the smem ----
    #pragma unroll
    for (int i = 0; i < 8; i++) {
        int v = tid + i * 256;            // 0..2047
        int arr = v >> 10;
        int rem = v & 1023;
        int r = rem >> 3, seg = rem & 7;
        size_t g = (rowbase + q0 + r) * D_MODEL + colh + seg * 8;
        const __half* s = arr ? g_qlo : g_qhi;
        CP_ASYNC16(sb + (arr ? AQ_LO : AQ_HI) + r * ATROW + seg * 16, s + g);
    }
    CP_COMMIT();
    CP_WAIT(0);
    __syncthreads();

    uint32_t qh[4][4], ql[4][4];
    {
        const uint32_t aoff = (uint32_t)(wid * 16 + (lane & 15)) * ATROW
                              + (lane >> 4) * 16;
        #pragma unroll
        for (int ks = 0; ks < 4; ks++) {
            LDMATRIX_X4(qh[ks], sb + AQ_HI + aoff + ks * 32);
            LDMATRIX_X4(ql[ks], sb + AQ_LO + aoff + ks * 32);
        }
    }
    __syncthreads();   // Q consumed; K/V staging may overwrite

    float oacc[8][4];
    #pragma unroll
    for (int nf = 0; nf < 8; nf++)
        #pragma unroll
        for (int e = 0; e < 4; e++) oacc[nf][e] = 0.f;
    float mrow[2] = {-1e30f, -1e30f};
    float lrow[2] = {0.f, 0.f};

    auto stage_tile = [&](int c) {
        const uint32_t base = sb + (uint32_t)(c % 3) * ASTG;
        const int kt = c * 64;
        #pragma unroll
        for (int i = 0; i < 4; i++) {
            int v = tid + i * 256;        // 0..1023
            int arr = v >> 9;             // 0:Kh 1:Vh
            int rem = v & 511;
            int r = rem >> 3, seg = rem & 7;
            size_t g = (rowbase + kt + r) * D_MODEL + colh + seg * 8;
            const __half* s = arr ? g_vh : g_kh;
            CP_ASYNC16(base + arr * ARR_B + r * ATROW + seg * 16, s + g);
        }
    };

    const int NT = (q0 + 128) / 64;       // >= 2
    stage_tile(0); CP_COMMIT();
    stage_tile(1); CP_COMMIT();

    for (int c = 0; c < NT; c++) {
        if (c + 2 < NT)      { stage_tile(c + 2); CP_COMMIT(); CP_WAIT(2); }
        else if (c + 1 < NT) { CP_WAIT(1); }
        else                 { CP_WAIT(0); }
        __syncthreads();

        const int kt0 = c * 64;
        const uint32_t stg = sb + (uint32_t)(c % 3) * ASTG;

        if (kt0 <= r0w + 15) {
            float sacc[8][4];
            #pragma unroll
            for (int nf = 0; nf < 8; nf++)
                #pragma unroll
                for (int e = 0; e < 4; e++) sacc[nf][e] = 0.f;

            // ---- S = (Qh+Ql) Kh^T ----
            const uint32_t krow = ((lane & 16) >> 1) + (lane & 7);
            #pragma unroll
            for (int ks = 0; ks < 4; ks++) {
                const uint32_t kcol = (uint32_t)(ks * 32 + (lane & 8) * 2);
                #pragma unroll
                for (int nfp = 0; nfp < 4; nfp++) {
                    uint32_t bh[4];
                    uint32_t bd = stg + A_KH + (krow + nfp * 16) * ATROW + kcol;
                    LDMATRIX_X4(bh, bd);
                    uint32_t bh0[2] = { bh[0], bh[1] }, bh1[2] = { bh[2], bh[3] };
                    MMA_F16(sacc[2*nfp],   qh[ks], bh0);
                    MMA_F16(sacc[2*nfp+1], qh[ks], bh1);
                    MMA_F16(sacc[2*nfp],   ql[ks], bh0);
                    MMA_F16(sacc[2*nfp+1], ql[ks], bh1);
                }
            }

            if (kt0 + 63 > r0w) {
                #pragma unroll
                for (int nf = 0; nf < 8; nf++)
                    #pragma unroll
                    for (int e = 0; e < 4; e++) {
                        int col = kt0 + nf * 8 + 2 * tg + (e & 1);
                        int row = r0w + gid + ((e >> 1) ? 8 : 0);
                        if (col > row) sacc[nf][e] = -1e30f;
                    }
            }

            float corr[2];
            #pragma unroll
            for (int s = 0; s < 2; s++) {
                float vmax = -1e30f;
                #pragma unroll
                for (int nf = 0; nf < 8; nf++) {
                    vmax = fmaxf(vmax, sacc[nf][2*s]);
                    vmax = fmaxf(vmax, sacc[nf][2*s+1]);
                }
                vmax = fmaxf(vmax, __shfl_xor_sync(0xFFFFFFFF, vmax, 1));
                vmax = fmaxf(vmax, __shfl_xor_sync(0xFFFFFFFF, vmax, 2));
                float mo = mrow[s];
                float mn = fmaxf(mo, vmax);
                float cr = exp2f_fast(mo - mn);
                corr[s] = cr;
                mrow[s] = mn;
                float rs = 0.f;
                #pragma unroll
                for (int nf = 0; nf < 8; nf++) {
                    float p0 = exp2f_fast(sacc[nf][2*s]   - mn);
                    float p1 = exp2f_fast(sacc[nf][2*s+1] - mn);
                    sacc[nf][2*s]   = p0;
                    sacc[nf][2*s+1] = p1;
                    rs += p0 + p1;
                }
                rs += __shfl_xor_sync(0xFFFFFFFF, rs, 1);
                rs += __shfl_xor_sync(0xFFFFFFFF, rs, 2);
                lrow[s] = lrow[s] * cr + rs;
            }
            #pragma unroll
            for (int nf = 0; nf < 8; nf++)
                #pragma unroll
                for (int e = 0; e < 4; e++)
                    oacc[nf][e] *= corr[e >> 1];

            // ---- O += (Phi+Plo) Vh ----
            #pragma unroll
            for (int kf = 0; kf < 4; kf++) {
                uint32_t phi[4], plo[4];
                #pragma unroll
                for (int half_ = 0; half_ < 2; half_++) {
                    const float* c2 = sacc[2 * kf + half_];
                    #pragma unroll
                    for (int s = 0; s < 2; s++) {
                        float v0 = c2[2*s], v1 = c2[2*s+1];
                        __half h0 = __float2half_rn(v0);
                        __half h1 = __float2half_rn(v1);
                        __half2 H(h0, h1);
                        phi[half_ * 2 + s] = *(uint32_t*)&H;
                        plo[half_ * 2 + s] =
                            pack_f16(v0 - __half2float(h0), v1 - __half2float(h1));
                    }
                }
                #pragma unroll
                for (int nf2 = 0; nf2 < 4; nf2++) {
                    uint32_t row = kf * 16 + ((lane >> 3) & 1) * 8 + (lane & 7);
                    uint32_t cb  = nf2 * 32 + (lane >> 4) * 16;
                    uint32_t rh[4];
                    LDMATRIX_X4_T(rh, stg + A_VH + row * ATROW + cb);
                    uint32_t bh0[2] = { rh[0], rh[1] }, bh1[2] = { rh[2], rh[3] };
                    MMA_F16(oacc[2*nf2],   phi, bh0);
                    MMA_F16(oacc[2*nf2+1], phi, bh1);
                    MMA_F16(oacc[2*nf2],   plo, bh0);
                    MMA_F16(oacc[2*nf2+1], plo, bh1);
                }
            }
        }
        __syncthreads();
    }

    // ---- epilogue: normalize, split fp16 hi/lo ----
    float inv[2] = { 1.f / lrow[0], 1.f / lrow[1] };
    #pragma unroll
    for (int s = 0; s < 2; s++) {
        int r = r0w + gid + 8 * s;
        #pragma unroll
        for (int nf = 0; nf < 8; nf++) {
            float v0 = oacc[nf][2*s]   * inv[s];
            float v1 = oacc[nf][2*s+1] * inv[s];
            __half h0 = __float2half_rn(v0);
            __half h1 = __float2half_rn(v1);
            size_t off = (rowbase + r) * D_MODEL + colh + nf * 8 + 2 * tg;
            __half2 H(h0, h1);
            *(uint32_t*)(Ohi + off) = *(uint32_t*)&H;
            *(uint32_t*)(Olo + off) =
                pack_f16(v0 - __half2float(h0), v1 - __half2float(h1));
        }
    }
}

// ---------------------------------------------------------------------------
extern "C" void kernel_launch(void* const* d_in, const int* in_sizes, int n_in,
                              void* d_out, int out_size)
{
    const float* x  = (const float*)d_in[0];
    const float* Wq = (const float*)d_in[1];
    const float* bq = (const float*)d_in[2];
    const float* Wk = (const float*)d_in[3];
    const float* bk = (const float*)d_in[4];
    const float* Wv = (const float*)d_in[5];
    const float* bv = (const float*)d_in[6];
    const float* Wo = (const float*)d_in[7];
    const float* bo = (const float*)d_in[8];
    float* out = (float*)d_out;

    __half *aohi, *aolo;
    cudaGetSymbolAddress((void**)&aohi, g_aohi);
    cudaGetSymbolAddress((void**)&aolo, g_aolo);

    cudaFuncSetAttribute(gemm_qkv,
                         cudaFuncAttributeMaxDynamicSharedMemorySize, GEMM_SMEM);
    cudaFuncSetAttribute(gemm_o,
                         cudaFuncAttributeMaxDynamicSharedMemorySize, GEMM_SMEM);
    cudaFuncSetAttribute(attn_mma,
                         cudaFuncAttributeMaxDynamicSharedMemorySize, ATTN_SMEM);

    const int NX4 = NELEM / 4;
    const int NW4 = D_MODEL * D_MODEL / 4;

    split_x<<<(NX4 + 255) / 256, 256>>>(x, NX4);
    {
        dim3 wgrid((NW4 + 255) / 256, 4);
        quant_w4<<<wgrid, 256>>>(Wq, Wk, Wv, Wo, NW4);
    }

    {
        dim3 ggrid(24, MTOT / 128);                 // (24, 32): z = bx % 3
        gemm_qkv<<<ggrid, 256, GEMM_SMEM>>>(bq, bk, bv);
    }

    attn_mma<<<512, 256, ATTN_SMEM>>>(aohi, aolo);

    {
        dim3 ggrid(D_MODEL / 128, MTOT / 128);      // (8, 32)
        gemm_o<<<ggrid, 256, GEMM_SMEM>>>(bo, out);
    }
}

// round 16
// speedup vs baseline: 8.0357x; 1.5727x over previous
#include <cuda_runtime.h>
#include <cuda_fp16.h>
#include <cstdint>

#define D_MODEL 1024
#define SEQ     2048
#define BATCH   2
#define NHEAD   16
#define DHEAD   64
#define MTOT    (BATCH * SEQ)   // 4096
#define NELEM   (MTOT * D_MODEL)

// ---------------- scratch (__device__ globals) ------------------------------
__device__ __half g_xh [NELEM];
__device__ __half g_Wh [4][D_MODEL * D_MODEL];
__device__ __half g_qh [NELEM];
__device__ __half g_kh [NELEM];
__device__ __half g_vh [NELEM];
__device__ __half g_aoh[NELEM];

// ---------------------------------------------------------------------------
__device__ __forceinline__ uint32_t smem_u32(const void* p) {
    uint32_t a;
    asm("{ .reg .u64 t; cvta.to.shared.u64 t, %1; cvt.u32.u64 %0, t; }"
        : "=r"(a) : "l"(p));
    return a;
}

#define MMA_F16(acc, a, b) \
    asm volatile("mma.sync.aligned.m16n8k16.row.col.f32.f16.f16.f32 " \
        "{%0,%1,%2,%3}, {%4,%5,%6,%7}, {%8,%9}, {%0,%1,%2,%3};" \
        : "+f"((acc)[0]), "+f"((acc)[1]), "+f"((acc)[2]), "+f"((acc)[3]) \
        : "r"((a)[0]), "r"((a)[1]), "r"((a)[2]), "r"((a)[3]), \
          "r"((b)[0]), "r"((b)[1]))

#define LDMATRIX_X4(r, addr) \
    asm volatile("ldmatrix.sync.aligned.m8n8.x4.shared.b16 {%0,%1,%2,%3}, [%4];" \
        : "=r"((r)[0]), "=r"((r)[1]), "=r"((r)[2]), "=r"((r)[3]) : "r"(addr))

#define LDMATRIX_X4_T(r, addr) \
    asm volatile("ldmatrix.sync.aligned.m8n8.x4.trans.shared.b16 {%0,%1,%2,%3}, [%4];" \
        : "=r"((r)[0]), "=r"((r)[1]), "=r"((r)[2]), "=r"((r)[3]) : "r"(addr))

#define CP_ASYNC16(d, g) \
    asm volatile("cp.async.cg.shared.global [%0], [%1], 16;" :: "r"(d), "l"(g))
#define CP_COMMIT()  asm volatile("cp.async.commit_group;" ::: "memory")
#define CP_WAIT(n)   asm volatile("cp.async.wait_group %0;" :: "n"(n) : "memory")

__device__ __forceinline__ uint32_t pack_f16(float a, float b) {
    __half2 t = __floats2half2_rn(a, b);   // x=a (low), y=b (high)
    return *(uint32_t*)&t;
}

// fast exp2 for x <= 0 (fma/alu pipe only, rel err ~2e-6)
__device__ __forceinline__ float exp2f_fast(float x) {
    x = fmaxf(x, -100.f);
    float r = x + 12582912.f;
    int  ir = __float_as_int(r);
    float n = r - 12582912.f;
    float f = x - n;
    float p = 1.33335581e-3f;
    p = fmaf(p, f, 9.61817249e-3f);
    p = fmaf(p, f, 5.55041086e-2f);
    p = fmaf(p, f, 2.40226507e-1f);
    p = fmaf(p, f, 6.93147182e-1f);
    p = fmaf(p, f, 1.0f);
    return __int_as_float(__float_as_int(p) + ((ir - 0x4B400000) << 23));
}

// ---------------------------------------------------------------------------
// fp32 -> fp16 quantization
// ---------------------------------------------------------------------------
__global__ void __launch_bounds__(256) quant_x(const float* __restrict__ in, int n4) {
    int i = blockIdx.x * 256 + threadIdx.x;
    if (i >= n4) return;
    float4 v = ((const float4*)in)[i];
    union { __half2 h[2]; uint2 u; } H;
    H.h[0] = __floats2half2_rn(v.x, v.y);
    H.h[1] = __floats2half2_rn(v.z, v.w);
    *(uint2*)(g_xh + 4 * (size_t)i) = H.u;
}

__global__ void __launch_bounds__(256) quant_w4(
    const float* __restrict__ W0, const float* __restrict__ W1,
    const float* __restrict__ W2, const float* __restrict__ W3, int n4) {
    int y = blockIdx.y;
    const float* in = (y == 0) ? W0 : (y == 1) ? W1 : (y == 2) ? W2 : W3;
    int i = blockIdx.x * 256 + threadIdx.x;
    if (i >= n4) return;
    float4 v = ((const float4*)in)[i];
    union { __half2 h[2]; uint2 u; } H;
    H.h[0] = __floats2half2_rn(v.x, v.y);
    H.h[1] = __floats2half2_rn(v.z, v.w);
    *(uint2*)(g_Wh[y] + 4 * (size_t)i) = H.u;
}

// ---------------------------------------------------------------------------
// GEMM mainloop: C = A @ B^T, single fp16. 128x128 tile, BK=32, 256 thr,
// warp grid 2x4, 4-stage cp.async pipeline (prefetch distance 3).
// ---------------------------------------------------------------------------
#define TROW   80
#define TILE_B (128 * TROW)      // 10240
#define STAGE_B (2 * TILE_B)     // A, B = 20480
#define GEMM_SMEM (4 * STAGE_B)  // 81920

__device__ __forceinline__ void gemm_mainloop(
    const __half* __restrict__ A, const __half* __restrict__ Bh,
    uint32_t sb, int tid, float acc[4][4][4])
{
    constexpr int K = D_MODEL;
    const int lane = tid & 31;
    const int wid  = tid >> 5;
    const int m0w = (wid & 1) * 64;
    const int n0w = (wid >> 1) * 32;

    const __half* src[2] = { A, Bh };

    auto copy_chunk = [&](int c) {
        const uint32_t base = sb + (uint32_t)(c & 3) * STAGE_B;
        const int kc = c * 32;
        #pragma unroll
        for (int t = 0; t < 2; t++) {
            #pragma unroll
            for (int i = 0; i < 2; i++) {
                int v = tid + i * 256;
                int row = v >> 2, seg = v & 3;
                const __half* g = src[t] + (size_t)row * K + kc + seg * 8;
                CP_ASYNC16(base + t * TILE_B + row * TROW + seg * 16, g);
            }
        }
    };

    const int NCH = K / 32;
    copy_chunk(0); CP_COMMIT();
    copy_chunk(1); CP_COMMIT();
    copy_chunk(2); CP_COMMIT();

    for (int c = 0; c < NCH; c++) {
        if (c + 3 < NCH)      { copy_chunk(c + 3); CP_COMMIT(); CP_WAIT(3); }
        else if (c + 2 < NCH) { CP_WAIT(2); }
        else if (c + 1 < NCH) { CP_WAIT(1); }
        else                  { CP_WAIT(0); }
        __syncthreads();

        const uint32_t stage = sb + (uint32_t)(c & 3) * STAGE_B;

        #pragma unroll
        for (int ks = 0; ks < 2; ks++) {
            uint32_t af[4][4];
            const uint32_t aoff = (uint32_t)(m0w + (lane & 15)) * TROW
                                  + ks * 32 + (lane >> 4) * 16;
            #pragma unroll
            for (int mt = 0; mt < 4; mt++)
                LDMATRIX_X4(af[mt], stage + aoff + mt * (16 * TROW));

            const uint32_t brow = (uint32_t)(n0w + ((lane & 16) >> 1) + (lane & 7));
            const uint32_t bcol = (uint32_t)(ks * 32 + (lane & 8) * 2);
            #pragma unroll
            for (int ntp = 0; ntp < 2; ntp++) {
                uint32_t bh[4];
                uint32_t bd = stage + TILE_B + (brow + ntp * 16) * TROW + bcol;
                LDMATRIX_X4(bh, bd);
                uint32_t bh0[2] = { bh[0], bh[1] }, bh1[2] = { bh[2], bh[3] };
                #pragma unroll
                for (int mt = 0; mt < 4; mt++)
                    MMA_F16(acc[mt][2*ntp],   af[mt], bh0);
                #pragma unroll
                for (int mt = 0; mt < 4; mt++)
                    MMA_F16(acc[mt][2*ntp+1], af[mt], bh1);
            }
        }
        __syncthreads();
    }
}

// ---- fused Q/K/V projection: grid (24, 32); z = bx % 3 ----
__global__ void __launch_bounds__(256, 2) gemm_qkv(
    const float* __restrict__ bq, const float* __restrict__ bk,
    const float* __restrict__ bv)
{
    extern __shared__ char smem[];
    const uint32_t sb = smem_u32(smem);
    const int tid = threadIdx.x;
    const int z  = blockIdx.x % 3;
    const int bn = (blockIdx.x / 3) * 128;
    const int bm = blockIdx.y * 128;

    float acc[4][4][4];
    #pragma unroll
    for (int mt = 0; mt < 4; mt++)
        #pragma unroll
        for (int nt = 0; nt < 4; nt++)
            #pragma unroll
            for (int j = 0; j < 4; j++) acc[mt][nt][j] = 0.f;

    gemm_mainloop(g_xh + (size_t)bm * D_MODEL,
                  g_Wh[z] + (size_t)bn * D_MODEL, sb, tid, acc);

    const float* bias = (z == 0) ? bq : (z == 1) ? bk : bv;
    const float scale = (z == 0) ? 0.125f * 1.44269504f : 1.f;
    __half* C = (z == 0) ? g_qh : (z == 1) ? g_kh : g_vh;

    const int lane = tid & 31, wid = tid >> 5;
    const int m0w = (wid & 1) * 64, n0w = (wid >> 1) * 32;
    const int gid = lane >> 2, tg = lane & 3;

    #pragma unroll
    for (int nt = 0; nt < 4; nt++) {
        const int col = bn + n0w + nt * 8 + 2 * tg;
        const float b0 = bias[col], b1 = bias[col + 1];
        #pragma unroll
        for (int mt = 0; mt < 4; mt++) {
            const int r0 = bm + m0w + mt * 16 + gid;
            #pragma unroll
            for (int s = 0; s < 2; s++) {
                size_t off = (size_t)(r0 + 8 * s) * D_MODEL + col;
                *(uint32_t*)(C + off) =
                    pack_f16((acc[mt][nt][2*s+0] + b0) * scale,
                             (acc[mt][nt][2*s+1] + b1) * scale);
            }
        }
    }
}

// ---- output projection: grid (8, 32), fp32 epilogue ----
__global__ void __launch_bounds__(256, 2) gemm_o(
    const float* __restrict__ bo, float* __restrict__ out)
{
    extern __shared__ char smem[];
    const uint32_t sb = smem_u32(smem);
    const int tid = threadIdx.x;
    const int bm = blockIdx.y * 128;
    const int bn = blockIdx.x * 128;

    float acc[4][4][4];
    #pragma unroll
    for (int mt = 0; mt < 4; mt++)
        #pragma unroll
        for (int nt = 0; nt < 4; nt++)
            #pragma unroll
            for (int j = 0; j < 4; j++) acc[mt][nt][j] = 0.f;

    gemm_mainloop(g_aoh + (size_t)bm * D_MODEL,
                  g_Wh[3] + (size_t)bn * D_MODEL, sb, tid, acc);

    const int lane = tid & 31, wid = tid >> 5;
    const int m0w = (wid & 1) * 64, n0w = (wid >> 1) * 32;
    const int gid = lane >> 2, tg = lane & 3;

    #pragma unroll
    for (int nt = 0; nt < 4; nt++) {
        const int col = bn + n0w + nt * 8 + 2 * tg;
        const float b0 = bo[col], b1 = bo[col + 1];
        #pragma unroll
        for (int mt = 0; mt < 4; mt++) {
            const int r0 = bm + m0w + mt * 16 + gid;
            float2 v0, v1;
            v0.x = acc[mt][nt][0] + b0; v0.y = acc[mt][nt][1] + b1;
            v1.x = acc[mt][nt][2] + b0; v1.y = acc[mt][nt][3] + b1;
            *(float2*)(out + (size_t)r0 * D_MODEL + col)       = v0;
            *(float2*)(out + (size_t)(r0 + 8) * D_MODEL + col) = v1;
        }
    }
}

// ---------------------------------------------------------------------------
// MMA flash attention, single fp16. Flat grid 512, LPT ordering. 8 warps x 16
// rows. Q in registers; K/V 3-stage cp.async pipeline; V via ldmatrix.trans.
// ---------------------------------------------------------------------------
#define ATROW 144
#define ARR_B (64 * ATROW)       // 9216
#define ASTG  (2 * ARR_B)        // Kh + Vh = 18432
#define A_KH  0
#define A_VH  ARR_B
#define ATTN_SMEM (3 * ASTG)     // 55296 (Q staging uses first 18432)

__global__ void __launch_bounds__(256, 2) attn_mma()
{
    extern __shared__ char smem[];
    const uint32_t sb = smem_u32(smem);
    const int fid = blockIdx.x;
    const int qb  = 15 - (fid >> 5);          // LPT: heavy tasks first
    const int h   = (fid & 31) >> 1;
    const int b   = fid & 1;
    const int tid  = threadIdx.x;
    const int lane = tid & 31;
    const int wid  = tid >> 5;
    const int gid  = lane >> 2;
    const int tg   = lane & 3;
    const int q0   = qb * 128;
    const int r0w  = q0 + wid * 16;
    const size_t rowbase = (size_t)b * SEQ;
    const int colh = h * DHEAD;

    // ---- stage Q, extract fragments, then release the smem ----
    #pragma unroll
    for (int i = 0; i < 4; i++) {
        int v = tid + i * 256;            // 0..1023
        int r = v >> 3, seg = v & 7;
        size_t g = (rowbase + q0 + r) * D_MODEL + colh + seg * 8;
        CP_ASYNC16(sb + r * ATROW + seg * 16, g_qh + g);
    }
    CP_COMMIT();
    CP_WAIT(0);
    __syncthreads();

    uint32_t qh[4][4];
    {
        const uint32_t aoff = (uint32_t)(wid * 16 + (lane & 15)) * ATROW
                              + (lane >> 4) * 16;
        #pragma unroll
        for (int ks = 0; ks < 4; ks++)
            LDMATRIX_X4(qh[ks], sb + aoff + ks * 32);
    }
    __syncthreads();   // Q consumed; K/V staging may overwrite

    float oacc[8][4];
    #pragma unroll
    for (int nf = 0; nf < 8; nf++)
        #pragma unroll
        for (int e = 0; e < 4; e++) oacc[nf][e] = 0.f;
    float mrow[2] = {-1e30f, -1e30f};
    float lrow[2] = {0.f, 0.f};

    auto stage_tile = [&](int c) {
        const uint32_t base = sb + (uint32_t)(c % 3) * ASTG;
        const int kt = c * 64;
        #pragma unroll
        for (int i = 0; i < 4; i++) {
            int v = tid + i * 256;        // 0..1023
            int arr = v >> 9;             // 0:Kh 1:Vh
            int rem = v & 511;
            int r = rem >> 3, seg = rem & 7;
            size_t g = (rowbase + kt + r) * D_MODEL + colh + seg * 8;
            const __half* s = arr ? g_vh : g_kh;
            CP_ASYNC16(base + arr * ARR_B + r * ATROW + seg * 16, s + g);
        }
    };

    const int NT = (q0 + 128) / 64;       // >= 2
    stage_tile(0); CP_COMMIT();
    stage_tile(1); CP_COMMIT();

    for (int c = 0; c < NT; c++) {
        if (c + 2 < NT)      { stage_tile(c + 2); CP_COMMIT(); CP_WAIT(2); }
        else if (c + 1 < NT) { CP_WAIT(1); }
        else                 { CP_WAIT(0); }
        __syncthreads();

        const int kt0 = c * 64;
        const uint32_t stg = sb + (uint32_t)(c % 3) * ASTG;

        if (kt0 <= r0w + 15) {
            float sacc[8][4];
            #pragma unroll
            for (int nf = 0; nf < 8; nf++)
                #pragma unroll
                for (int e = 0; e < 4; e++) sacc[nf][e] = 0.f;

            // ---- S = Q Kh^T ----
            const uint32_t krow = ((lane & 16) >> 1) + (lane & 7);
            #pragma unroll
            for (int ks = 0; ks < 4; ks++) {
                const uint32_t kcol = (uint32_t)(ks * 32 + (lane & 8) * 2);
                #pragma unroll
                for (int nfp = 0; nfp < 4; nfp++) {
                    uint32_t bh[4];
                    uint32_t bd = stg + A_KH + (krow + nfp * 16) * ATROW + kcol;
                    LDMATRIX_X4(bh, bd);
                    uint32_t bh0[2] = { bh[0], bh[1] }, bh1[2] = { bh[2], bh[3] };
                    MMA_F16(sacc[2*nfp],   qh[ks], bh0);
                    MMA_F16(sacc[2*nfp+1], qh[ks], bh1);
                }
            }

            if (kt0 + 63 > r0w) {
                #pragma unroll
                for (int nf = 0; nf < 8; nf++)
                    #pragma unroll
                    for (int e = 0; e < 4; e++) {
                        int col = kt0 + nf * 8 + 2 * tg + (e & 1);
                        int row = r0w + gid + ((e >> 1) ? 8 : 0);
                        if (col > row) sacc[nf][e] = -1e30f;
                    }
            }

            float corr[2];
            #pragma unroll
            for (int s = 0; s < 2; s++) {
                float vmax = -1e30f;
                #pragma unroll
                for (int nf = 0; nf < 8; nf++) {
                    vmax = fmaxf(vmax, sacc[nf][2*s]);
                    vmax = fmaxf(vmax, sacc[nf][2*s+1]);
                }
                vmax = fmaxf(vmax, __shfl_xor_sync(0xFFFFFFFF, vmax, 1));
                vmax = fmaxf(vmax, __shfl_xor_sync(0xFFFFFFFF, vmax, 2));
                float mo = mrow[s];
                float mn = fmaxf(mo, vmax);
                float cr = exp2f_fast(mo - mn);
                corr[s] = cr;
                mrow[s] = mn;
                float rs = 0.f;
                #pragma unroll
                for (int nf = 0; nf < 8; nf++) {
                    float p0 = exp2f_fast(sacc[nf][2*s]   - mn);
                    float p1 = exp2f_fast(sacc[nf][2*s+1] - mn);
                    sacc[nf][2*s]   = p0;
                    sacc[nf][2*s+1] = p1;
                    rs += p0 + p1;
                }
                rs += __shfl_xor_sync(0xFFFFFFFF, rs, 1);
                rs += __shfl_xor_sync(0xFFFFFFFF, rs, 2);
                lrow[s] = lrow[s] * cr + rs;
            }
            #pragma unroll
            for (int nf = 0; nf < 8; nf++)
                #pragma unroll
                for (int e = 0; e < 4; e++)
                    oacc[nf][e] *= corr[e >> 1];

            // ---- O += P Vh (P quantized to single fp16) ----
            #pragma unroll
            for (int kf = 0; kf < 4; kf++) {
                uint32_t pf[4];
                #pragma unroll
                for (int half_ = 0; half_ < 2; half_++) {
                    const float* c2 = sacc[2 * kf + half_];
                    #pragma unroll
                    for (int s = 0; s < 2; s++)
                        pf[half_ * 2 + s] = pack_f16(c2[2*s], c2[2*s+1]);
                }
                #pragma unroll
                for (int nf2 = 0; nf2 < 4; nf2++) {
                    uint32_t row = kf * 16 + ((lane >> 3) & 1) * 8 + (lane & 7);
                    uint32_t cb  = nf2 * 32 + (lane >> 4) * 16;
                    uint32_t rh[4];
                    LDMATRIX_X4_T(rh, stg + A_VH + row * ATROW + cb);
                    uint32_t bh0[2] = { rh[0], rh[1] }, bh1[2] = { rh[2], rh[3] };
                    MMA_F16(oacc[2*nf2],   pf, bh0);
                    MMA_F16(oacc[2*nf2+1], pf, bh1);
                }
            }
        }
        __syncthreads();
    }

    // ---- epilogue: normalize, quantize to fp16 ----
    float inv[2] = { 1.f / lrow[0], 1.f / lrow[1] };
    #pragma unroll
    for (int s = 0; s < 2; s++) {
        int r = r0w + gid + 8 * s;
        #pragma unroll
        for (int nf = 0; nf < 8; nf++) {
            size_t off = (rowbase + r) * D_MODEL + colh + nf * 8 + 2 * tg;
            *(uint32_t*)(g_aoh + off) =
                pack_f16(oacc[nf][2*s] * inv[s], oacc[nf][2*s+1] * inv[s]);
        }
    }
}

// ---------------------------------------------------------------------------
extern "C" void kernel_launch(void* const* d_in, const int* in_sizes, int n_in,
                              void* d_out, int out_size)
{
    const float* x  = (const float*)d_in[0];
    const float* Wq = (const float*)d_in[1];
    const float* bq = (const float*)d_in[2];
    const float* Wk = (const float*)d_in[3];
    const float* bk = (const float*)d_in[4];
    const float* Wv = (const float*)d_in[5];
    const float* bv = (const float*)d_in[6];
    const float* Wo = (const float*)d_in[7];
    const float* bo = (const float*)d_in[8];
    float* out = (float*)d_out;

    cudaFuncSetAttribute(gemm_qkv,
                         cudaFuncAttributeMaxDynamicSharedMemorySize, GEMM_SMEM);
    cudaFuncSetAttribute(gemm_o,
                         cudaFuncAttributeMaxDynamicSharedMemorySize, GEMM_SMEM);
    cudaFuncSetAttribute(attn_mma,
                         cudaFuncAttributeMaxDynamicSharedMemorySize, ATTN_SMEM);

    const int NX4 = NELEM / 4;
    const int NW4 = D_MODEL * D_MODEL / 4;

    quant_x<<<(NX4 + 255) / 256, 256>>>(x, NX4);
    {
        dim3 wgrid((NW4 + 255) / 256, 4);
        quant_w4<<<wgrid, 256>>>(Wq, Wk, Wv, Wo, NW4);
    }

    {
        dim3 ggrid(24, MTOT / 128);                 // (24, 32): z = bx % 3
        gemm_qkv<<<ggrid, 256, GEMM_SMEM>>>(bq, bk, bv);
    }

    attn_mma<<<512, 256, ATTN_SMEM>>>();

    {
        dim3 ggrid(D_MODEL / 128, MTOT / 128);      // (8, 32)
        gemm_o<<<ggrid, 256, GEMM_SMEM>>>(bo, out);
    }
}

// round 17
// speedup vs baseline: 9.4722x; 1.1788x over previous
#include <cuda_runtime.h>
#include <cuda_fp16.h>
#include <cstdint>

#define D_MODEL 1024
#define SEQ     2048
#define BATCH   2
#define NHEAD   16
#define DHEAD   64
#define MTOT    (BATCH * SEQ)   // 4096
#define NELEM   (MTOT * D_MODEL)

// ---------------- scratch (__device__ globals) ------------------------------
__device__ __half g_xh [NELEM];
__device__ __half g_Wh [4][D_MODEL * D_MODEL];
__device__ __half g_qh [NELEM];
__device__ __half g_kh [NELEM];
__device__ __half g_vh [NELEM];
__device__ __half g_aoh[NELEM];

// ---------------------------------------------------------------------------
__device__ __forceinline__ uint32_t smem_u32(const void* p) {
    uint32_t a;
    asm("{ .reg .u64 t; cvta.to.shared.u64 t, %1; cvt.u32.u64 %0, t; }"
        : "=r"(a) : "l"(p));
    return a;
}

#define MMA_F16(acc, a, b) \
    asm volatile("mma.sync.aligned.m16n8k16.row.col.f32.f16.f16.f32 " \
        "{%0,%1,%2,%3}, {%4,%5,%6,%7}, {%8,%9}, {%0,%1,%2,%3};" \
        : "+f"((acc)[0]), "+f"((acc)[1]), "+f"((acc)[2]), "+f"((acc)[3]) \
        : "r"((a)[0]), "r"((a)[1]), "r"((a)[2]), "r"((a)[3]), \
          "r"((b)[0]), "r"((b)[1]))

#define LDMATRIX_X4(r, addr) \
    asm volatile("ldmatrix.sync.aligned.m8n8.x4.shared.b16 {%0,%1,%2,%3}, [%4];" \
        : "=r"((r)[0]), "=r"((r)[1]), "=r"((r)[2]), "=r"((r)[3]) : "r"(addr))

#define LDMATRIX_X4_T(r, addr) \
    asm volatile("ldmatrix.sync.aligned.m8n8.x4.trans.shared.b16 {%0,%1,%2,%3}, [%4];" \
        : "=r"((r)[0]), "=r"((r)[1]), "=r"((r)[2]), "=r"((r)[3]) : "r"(addr))

#define CP_ASYNC16(d, g) \
    asm volatile("cp.async.cg.shared.global [%0], [%1], 16;" :: "r"(d), "l"(g))
#define CP_COMMIT()  asm volatile("cp.async.commit_group;" ::: "memory")
#define CP_WAIT(n)   asm volatile("cp.async.wait_group %0;" :: "n"(n) : "memory")

__device__ __forceinline__ uint32_t pack_f16(float a, float b) {
    __half2 t = __floats2half2_rn(a, b);
    return *(uint32_t*)&t;
}

// fast exp2 for x <= 0, degree-4 (rel err ~4e-5)
__device__ __forceinline__ float exp2f_fast(float x) {
    x = fmaxf(x, -100.f);
    float r = x + 12582912.f;
    int  ir = __float_as_int(r);
    float n = r - 12582912.f;
    float f = x - n;
    float p = 9.61812910e-3f;
    p = fmaf(p, f, 5.55041086e-2f);
    p = fmaf(p, f, 2.40226507e-1f);
    p = fmaf(p, f, 6.93147182e-1f);
    p = fmaf(p, f, 1.0f);
    return __int_as_float(__float_as_int(p) + ((ir - 0x4B400000) << 23));
}

// ---------------------------------------------------------------------------
// fp32 -> fp16 quantization (merged: y<4 = weights, y==4 = x)
// ---------------------------------------------------------------------------
__global__ void __launch_bounds__(256) quant_all(
    const float* __restrict__ x,
    const float* __restrict__ W0, const float* __restrict__ W1,
    const float* __restrict__ W2, const float* __restrict__ W3)
{
    int y = blockIdx.y;
    const float* in;
    __half* outp;
    int n4;
    if (y == 4) { in = x;  outp = g_xh;    n4 = NELEM / 4; }
    else {
        in = (y == 0) ? W0 : (y == 1) ? W1 : (y == 2) ? W2 : W3;
        outp = g_Wh[y]; n4 = D_MODEL * D_MODEL / 4;
    }
    int i = blockIdx.x * 256 + threadIdx.x;
    if (i >= n4) return;
    float4 v = ((const float4*)in)[i];
    union { __half2 h[2]; uint2 u; } H;
    H.h[0] = __floats2half2_rn(v.x, v.y);
    H.h[1] = __floats2half2_rn(v.z, v.w);
    *(uint2*)(outp + 4 * (size_t)i) = H.u;
}

// ---------------------------------------------------------------------------
// GEMM mainloop: C = A @ B^T, fp16. 128x128 tile, BK=64, 256 thr, warp grid
// 2x4, 3-stage cp.async pipeline, distance 1, SINGLE sync per iteration.
// ---------------------------------------------------------------------------
#define GROW   144                 // 128B data + 16B pad per 64-fp16 row
#define GTILE  (128 * GROW)        // 18432
#define GSTAGE (2 * GTILE)         // A + B = 36864
#define GEMM_SMEM (3 * GSTAGE)     // 110592

__device__ __forceinline__ void gemm_mainloop(
    const __half* __restrict__ A, const __half* __restrict__ Bh,
    uint32_t sb, int tid, float acc[4][4][4])
{
    constexpr int K = D_MODEL;
    const int lane = tid & 31;
    const int wid  = tid >> 5;
    const int m0w = (wid & 1) * 64;
    const int n0w = (wid >> 1) * 32;

    const __half* src[2] = { A, Bh };

    auto copy_chunk = [&](int c) {
        const uint32_t base = sb + (uint32_t)(c % 3) * GSTAGE;
        const int kc = c * 64;
        #pragma unroll
        for (int t = 0; t < 2; t++) {
            #pragma unroll
            for (int i = 0; i < 4; i++) {
                int v = tid + i * 256;          // 0..1023
                int row = v >> 3, seg = v & 7;  // 8 x 16B per 128B row
                const __half* g = src[t] + (size_t)row * K + kc + seg * 8;
                CP_ASYNC16(base + t * GTILE + row * GROW + seg * 16, g);
            }
        }
    };

    const int NCH = K / 64;   // 16
    copy_chunk(0); CP_COMMIT();

    for (int c = 0; c < NCH; c++) {
        if (c + 1 < NCH) { copy_chunk(c + 1); CP_COMMIT(); CP_WAIT(1); }
        else             { CP_WAIT(0); }
        __syncthreads();    // single barrier per iteration (see proof in notes)

        const uint32_t stage = sb + (uint32_t)(c % 3) * GSTAGE;

        #pragma unroll
        for (int ks = 0; ks < 4; ks++) {
            uint32_t af[4][4];
            const uint32_t aoff = (uint32_t)(m0w + (lane & 15)) * GROW
                                  + ks * 32 + (lane >> 4) * 16;
            #pragma unroll
            for (int mt = 0; mt < 4; mt++)
                LDMATRIX_X4(af[mt], stage + aoff + mt * (16 * GROW));

            const uint32_t brow = (uint32_t)(n0w + ((lane & 16) >> 1) + (lane & 7));
            const uint32_t bcol = (uint32_t)(ks * 32 + (lane & 8) * 2);
            #pragma unroll
            for (int ntp = 0; ntp < 2; ntp++) {
                uint32_t bh[4];
                uint32_t bd = stage + GTILE + (brow + ntp * 16) * GROW + bcol;
                LDMATRIX_X4(bh, bd);
                uint32_t bh0[2] = { bh[0], bh[1] }, bh1[2] = { bh[2], bh[3] };
                #pragma unroll
                for (int mt = 0; mt < 4; mt++)
                    MMA_F16(acc[mt][2*ntp],   af[mt], bh0);
                #pragma unroll
                for (int mt = 0; mt < 4; mt++)
                    MMA_F16(acc[mt][2*ntp+1], af[mt], bh1);
            }
        }
    }
}

// ---- fused Q/K/V projection: grid (24, 32); z = bx % 3 ----
__global__ void __launch_bounds__(256, 2) gemm_qkv(
    const float* __restrict__ bq, const float* __restrict__ bk,
    const float* __restrict__ bv)
{
    extern __shared__ char smem[];
    const uint32_t sb = smem_u32(smem);
    const int tid = threadIdx.x;
    const int z  = blockIdx.x % 3;
    const int bn = (blockIdx.x / 3) * 128;
    const int bm = blockIdx.y * 128;

    float acc[4][4][4];
    #pragma unroll
    for (int mt = 0; mt < 4; mt++)
        #pragma unroll
        for (int nt = 0; nt < 4; nt++)
            #pragma unroll
            for (int j = 0; j < 4; j++) acc[mt][nt][j] = 0.f;

    gemm_mainloop(g_xh + (size_t)bm * D_MODEL,
                  g_Wh[z] + (size_t)bn * D_MODEL, sb, tid, acc);

    const float* bias = (z == 0) ? bq : (z == 1) ? bk : bv;
    const float scale = (z == 0) ? 0.125f * 1.44269504f : 1.f;
    __half* C = (z == 0) ? g_qh : (z == 1) ? g_kh : g_vh;

    const int lane = tid & 31, wid = tid >> 5;
    const int m0w = (wid & 1) * 64, n0w = (wid >> 1) * 32;
    const int gid = lane >> 2, tg = lane & 3;

    #pragma unroll
    for (int nt = 0; nt < 4; nt++) {
        const int col = bn + n0w + nt * 8 + 2 * tg;
        const float b0 = bias[col], b1 = bias[col + 1];
        #pragma unroll
        for (int mt = 0; mt < 4; mt++) {
            const int r0 = bm + m0w + mt * 16 + gid;
            #pragma unroll
            for (int s = 0; s < 2; s++) {
                size_t off = (size_t)(r0 + 8 * s) * D_MODEL + col;
                *(uint32_t*)(C + off) =
                    pack_f16((acc[mt][nt][2*s+0] + b0) * scale,
                             (acc[mt][nt][2*s+1] + b1) * scale);
            }
        }
    }
}

// ---- output projection: grid (8, 32), fp32 epilogue ----
__global__ void __launch_bounds__(256, 2) gemm_o(
    const float* __restrict__ bo, float* __restrict__ out)
{
    extern __shared__ char smem[];
    const uint32_t sb = smem_u32(smem);
    const int tid = threadIdx.x;
    const int bm = blockIdx.y * 128;
    const int bn = blockIdx.x * 128;

    float acc[4][4][4];
    #pragma unroll
    for (int mt = 0; mt < 4; mt++)
        #pragma unroll
        for (int nt = 0; nt < 4; nt++)
            #pragma unroll
            for (int j = 0; j < 4; j++) acc[mt][nt][j] = 0.f;

    gemm_mainloop(g_aoh + (size_t)bm * D_MODEL,
                  g_Wh[3] + (size_t)bn * D_MODEL, sb, tid, acc);

    const int lane = tid & 31, wid = tid >> 5;
    const int m0w = (wid & 1) * 64, n0w = (wid >> 1) * 32;
    const int gid = lane >> 2, tg = lane & 3;

    #pragma unroll
    for (int nt = 0; nt < 4; nt++) {
        const int col = bn + n0w + nt * 8 + 2 * tg;
        const float b0 = bo[col], b1 = bo[col + 1];
        #pragma unroll
        for (int mt = 0; mt < 4; mt++) {
            const int r0 = bm + m0w + mt * 16 + gid;
            float2 v0, v1;
            v0.x = acc[mt][nt][0] + b0; v0.y = acc[mt][nt][1] + b1;
            v1.x = acc[mt][nt][2] + b0; v1.y = acc[mt][nt][3] + b1;
            *(float2*)(out + (size_t)r0 * D_MODEL + col)       = v0;
            *(float2*)(out + (size_t)(r0 + 8) * D_MODEL + col) = v1;
        }
    }
}

// ---------------------------------------------------------------------------
// MMA flash attention, fp16. Flat grid 512, LPT. 8 warps x 16 rows. Q in
// registers; K/V 3-stage pipeline, distance 1, single sync per tile.
// ---------------------------------------------------------------------------
#define ATROW 144
#define ARR_B (64 * ATROW)       // 9216
#define ASTG  (2 * ARR_B)        // Kh + Vh = 18432
#define A_KH  0
#define A_VH  ARR_B
#define ATTN_SMEM (3 * ASTG)     // 55296

__global__ void __launch_bounds__(256, 2) attn_mma()
{
    extern __shared__ char smem[];
    const uint32_t sb = smem_u32(smem);
    const int fid = blockIdx.x;
    const int qb  = 15 - (fid >> 5);          // LPT: heavy tasks first
    const int h   = (fid & 31) >> 1;
    const int b   = fid & 1;
    const int tid  = threadIdx.x;
    const int lane = tid & 31;
    const int wid  = tid >> 5;
    const int gid  = lane >> 2;
    const int tg   = lane & 3;
    const int q0   = qb * 128;
    const int r0w  = q0 + wid * 16;
    const size_t rowbase = (size_t)b * SEQ;
    const int colh = h * DHEAD;

    // ---- stage Q, extract fragments, then release the smem ----
    #pragma unroll
    for (int i = 0; i < 4; i++) {
        int v = tid + i * 256;            // 0..1023
        int r = v >> 3, seg = v & 7;
        size_t g = (rowbase + q0 + r) * D_MODEL + colh + seg * 8;
        CP_ASYNC16(sb + r * ATROW + seg * 16, g_qh + g);
    }
    CP_COMMIT();
    CP_WAIT(0);
    __syncthreads();

    uint32_t qh[4][4];
    {
        const uint32_t aoff = (uint32_t)(wid * 16 + (lane & 15)) * ATROW
                              + (lane >> 4) * 16;
        #pragma unroll
        for (int ks = 0; ks < 4; ks++)
            LDMATRIX_X4(qh[ks], sb + aoff + ks * 32);
    }
    __syncthreads();   // Q consumed; K/V staging may overwrite

    float oacc[8][4];
    #pragma unroll
    for (int nf = 0; nf < 8; nf++)
        #pragma unroll
        for (int e = 0; e < 4; e++) oacc[nf][e] = 0.f;
    float mrow[2] = {-1e30f, -1e30f};
    float lrow[2] = {0.f, 0.f};

    auto stage_tile = [&](int c) {
        const uint32_t base = sb + (uint32_t)(c % 3) * ASTG;
        const int kt = c * 64;
        #pragma unroll
        for (int i = 0; i < 4; i++) {
            int v = tid + i * 256;        // 0..1023
            int arr = v >> 9;             // 0:Kh 1:Vh
            int rem = v & 511;
            int r = rem >> 3, seg = rem & 7;
            size_t g = (rowbase + kt + r) * D_MODEL + colh + seg * 8;
            const __half* s = arr ? g_vh : g_kh;
            CP_ASYNC16(base + arr * ARR_B + r * ATROW + seg * 16, s + g);
        }
    };

    const int NT = (q0 + 128) / 64;       // >= 2
    stage_tile(0); CP_COMMIT();

    for (int c = 0; c < NT; c++) {
        if (c + 1 < NT) { stage_tile(c + 1); CP_COMMIT(); CP_WAIT(1); }
        else            { CP_WAIT(0); }
        __syncthreads();    // single barrier per tile

        const int kt0 = c * 64;
        const uint32_t stg = sb + (uint32_t)(c % 3) * ASTG;

        if (kt0 <= r0w + 15) {
            float sacc[8][4];
            #pragma unroll
            for (int nf = 0; nf < 8; nf++)
                #pragma unroll
                for (int e = 0; e < 4; e++) sacc[nf][e] = 0.f;

            // ---- S = Q Kh^T ----
            const uint32_t krow = ((lane & 16) >> 1) + (lane & 7);
            #pragma unroll
            for (int ks = 0; ks < 4; ks++) {
                const uint32_t kcol = (uint32_t)(ks * 32 + (lane & 8) * 2);
                #pragma unroll
                for (int nfp = 0; nfp < 4; nfp++) {
                    uint32_t bh[4];
                    uint32_t bd = stg + A_KH + (krow + nfp * 16) * ATROW + kcol;
                    LDMATRIX_X4(bh, bd);
                    uint32_t bh0[2] = { bh[0], bh[1] }, bh1[2] = { bh[2], bh[3] };
                    MMA_F16(sacc[2*nfp],   qh[ks], bh0);
                    MMA_F16(sacc[2*nfp+1], qh[ks], bh1);
                }
            }

            if (kt0 + 63 > r0w) {
                #pragma unroll
                for (int nf = 0; nf < 8; nf++)
                    #pragma unroll
                    for (int e = 0; e < 4; e++) {
                        int col = kt0 + nf * 8 + 2 * tg + (e & 1);
                        int row = r0w + gid + ((e >> 1) ? 8 : 0);
                        if (col > row) sacc[nf][e] = -1e30f;
                    }
            }

            float corr[2];
            #pragma unroll
            for (int s = 0; s < 2; s++) {
                float vmax = -1e30f;
                #pragma unroll
                for (int nf = 0; nf < 8; nf++) {
                    vmax = fmaxf(vmax, sacc[nf][2*s]);
                    vmax = fmaxf(vmax, sacc[nf][2*s+1]);
                }
                vmax = fmaxf(vmax, __shfl_xor_sync(0xFFFFFFFF, vmax, 1));
                vmax = fmaxf(vmax, __shfl_xor_sync(0xFFFFFFFF, vmax, 2));
                float mo = mrow[s];
                float mn = fmaxf(mo, vmax);
                float cr = exp2f_fast(mo - mn);
                corr[s] = cr;
                mrow[s] = mn;
                float rs = 0.f;
                #pragma unroll
                for (int nf = 0; nf < 8; nf++) {
                    float p0 = exp2f_fast(sacc[nf][2*s]   - mn);
                    float p1 = exp2f_fast(sacc[nf][2*s+1] - mn);
                    sacc[nf][2*s]   = p0;
                    sacc[nf][2*s+1] = p1;
                    rs += p0 + p1;
                }
                rs += __shfl_xor_sync(0xFFFFFFFF, rs, 1);
                rs += __shfl_xor_sync(0xFFFFFFFF, rs, 2);
                lrow[s] = lrow[s] * cr + rs;
            }
            #pragma unroll
            for (int nf = 0; nf < 8; nf++)
                #pragma unroll
                for (int e = 0; e < 4; e++)
                    oacc[nf][e] *= corr[e >> 1];

            // ---- O += P Vh ----
            #pragma unroll
            for (int kf = 0; kf < 4; kf++) {
                uint32_t pf[4];
                #pragma unroll
                for (int half_ = 0; half_ < 2; half_++) {
                    const float* c2 = sacc[2 * kf + half_];
                    #pragma unroll
                    for (int s = 0; s < 2; s++)
                        pf[half_ * 2 + s] = pack_f16(c2[2*s], c2[2*s+1]);
                }
                #pragma unroll
                for (int nf2 = 0; nf2 < 4; nf2++) {
                    uint32_t row = kf * 16 + ((lane >> 3) & 1) * 8 + (lane & 7);
                    uint32_t cb  = nf2 * 32 + (lane >> 4) * 16;
                    uint32_t rh[4];
                    LDMATRIX_X4_T(rh, stg + A_VH + row * ATROW + cb);
                    uint32_t bh0[2] = { rh[0], rh[1] }, bh1[2] = { rh[2], rh[3] };
                    MMA_F16(oacc[2*nf2],   pf, bh0);
                    MMA_F16(oacc[2*nf2+1], pf, bh1);
                }
            }
        }
    }

    // ---- epilogue: normalize, quantize to fp16 ----
    float inv[2] = { 1.f / lrow[0], 1.f / lrow[1] };
    #pragma unroll
    for (int s = 0; s < 2; s++) {
        int r = r0w + gid + 8 * s;
        #pragma unroll
        for (int nf = 0; nf < 8; nf++) {
            size_t off = (rowbase + r) * D_MODEL + colh + nf * 8 + 2 * tg;
            *(uint32_t*)(g_aoh + off) =
                pack_f16(oacc[nf][2*s] * inv[s], oacc[nf][2*s+1] * inv[s]);
        }
    }
}

// ---------------------------------------------------------------------------
extern "C" void kernel_launch(void* const* d_in, const int* in_sizes, int n_in,
                              void* d_out, int out_size)
{
    const float* x  = (const float*)d_in[0];
    const float* Wq = (const float*)d_in[1];
    const float* bq = (const float*)d_in[2];
    const float* Wk = (const float*)d_in[3];
    const float* bk = (const float*)d_in[4];
    const float* Wv = (const float*)d_in[5];
    const float* bv = (const float*)d_in[6];
    const float* Wo = (const float*)d_in[7];
    const float* bo = (const float*)d_in[8];
    float* out = (float*)d_out;

    cudaFuncSetAttribute(gemm_qkv,
                         cudaFuncAttributeMaxDynamicSharedMemorySize, GEMM_SMEM);
    cudaFuncSetAttribute(gemm_o,
                         cudaFuncAttributeMaxDynamicSharedMemorySize, GEMM_SMEM);
    cudaFuncSetAttribute(attn_mma,
                         cudaFuncAttributeMaxDynamicSharedMemorySize, ATTN_SMEM);

    {
        dim3 qgrid((NELEM / 4 + 255) / 256, 5);   // y<4: W, y==4: x
        quant_all<<<qgrid, 256>>>(x, Wq, Wk, Wv, Wo);
    }

    {
        dim3 ggrid(24, MTOT / 128);               // (24, 32): z = bx % 3
        gemm_qkv<<<ggrid, 256, GEMM_SMEM>>>(bq, bk, bv);
    }

    attn_mma<<<512, 256, ATTN_SMEM>>>();

    {
        dim3 ggrid(D_MODEL / 128, MTOT / 128);    // (8, 32)
        gemm_o<<<ggrid, 256, GEMM_SMEM>>>(bo, out);
    }
}